// round 3
// baseline (speedup 1.0000x reference)
#include <cuda_runtime.h>
#include <math.h>
#include <float.h>
#include <stdint.h>

// ---------------------------------------------------------------------------
// MatchLSTM: B=128, P=K=64, E=H=300, V=50000, C=3
//
//  1) pack weights: keep only i,g,o gate rows (f unused, c0=0) -> [900,300]
//  2) G = embed[tokens] @ Wpack^T (fused gather GEMM, TF32 tensor cores)
//  3) s_proj = h_s @ W_s^T ; t_proj = h_t @ W_t^T
//  4) ht_pre = h_t @ Wh'^T ; hsWa = h_s @ Wa'^T  (scan-invariant precomputes)
//  5) scan: 1 persistent block per batch, 64 sequential steps.
// ---------------------------------------------------------------------------

constexpr size_t SZ_GATES = 8192ull * 900;
constexpr size_t SZ_H     = 8192ull * 300;
constexpr size_t OFF_GATES = 0;
constexpr size_t OFF_HS    = OFF_GATES + SZ_GATES;
constexpr size_t OFF_HT    = OFF_HS + SZ_H;
constexpr size_t OFF_SPROJ = OFF_HT + SZ_H;
constexpr size_t OFF_TPROJ = OFF_SPROJ + SZ_H;
constexpr size_t OFF_HTPRE = OFF_TPROJ + SZ_H;
constexpr size_t OFF_HSWA  = OFF_HTPRE + SZ_GATES;
constexpr size_t OFF_WP    = OFF_HSWA + SZ_GATES;
constexpr size_t OFF_WH    = OFF_WP  + 900ull * 300;
constexpr size_t OFF_WA    = OFF_WH  + 900ull * 300;
constexpr size_t OFF_WHM   = OFF_WA  + 900ull * 300;
constexpr size_t OFF_WMT   = OFF_WHM + 900ull * 300;
constexpr size_t OFF_BP    = OFF_WMT + 300ull * 300;
constexpr size_t OFF_BH    = OFF_BP + 900;
constexpr size_t OFF_BM    = OFF_BH + 900;
constexpr size_t BUF_TOTAL = OFF_BM + 900;

__device__ __align__(16) float g_buf[BUF_TOTAL];

__device__ __forceinline__ float sigmoidf_(float x) { return 1.f / (1.f + expf(-x)); }

__device__ __forceinline__ uint32_t f2tf32(float x) {
    uint32_t u;
    asm("cvt.rna.tf32.f32 %0, %1;" : "=r"(u) : "f"(x));
    return u;
}

__device__ __forceinline__ void mma_tf32(float c[4], const uint32_t a[4], const uint32_t b[2]) {
    asm volatile(
        "mma.sync.aligned.m16n8k8.row.col.f32.tf32.tf32.f32 "
        "{%0,%1,%2,%3}, {%4,%5,%6,%7}, {%8,%9}, {%0,%1,%2,%3};"
        : "+f"(c[0]), "+f"(c[1]), "+f"(c[2]), "+f"(c[3])
        : "r"(a[0]), "r"(a[1]), "r"(a[2]), "r"(a[3]), "r"(b[0]), "r"(b[1]));
}

// ---- weight packing: gate rows {i:0..299, g:600..899, o:900..1199} -> 900 rows
__global__ void pack_weights(const float* __restrict__ Wih, const float* __restrict__ bih,
                             const float* __restrict__ bhh, int in_dim, int col_off,
                             float* __restrict__ Wout, float* __restrict__ bout)
{
    int idx = blockIdx.x * blockDim.x + threadIdx.x;
    if (idx < 900 * 300) {
        int j = idx / 300, k2 = idx % 300;
        int src = (j < 300) ? j : j + 300;
        Wout[idx] = Wih[(size_t)src * in_dim + col_off + k2];
    }
    if (idx < 900) {
        int src = (idx < 300) ? idx : idx + 300;
        bout[idx] = bih[src] + bhh[src];
    }
}

__global__ void transpose_wm(const float* __restrict__ Wm, float* __restrict__ WmT)
{
    int idx = blockIdx.x * blockDim.x + threadIdx.x;
    if (idx < 300 * 300) {
        int d = idx / 300, j = idx % 300;
        WmT[idx] = Wm[(size_t)j * 300 + d];
    }
}

// ---- TF32 tensor-core GEMM: C[M,N] = A[M,K] @ B[N,K]^T, optional row gather
// Tiles: BM=128, BN=64, BK=32. 8 warps (4m x 2n), warp tile 32x32 = 2x4 mmas.
__global__ __launch_bounds__(256)
void mma_tn(const float* __restrict__ A, const int* __restrict__ tok,
            const float* __restrict__ B, float* __restrict__ C,
            int M, int N, int K)
{
    constexpr int BM = 128, BN = 64, BK = 32, LDP = BK + 4; // stride 36: conflict-free
    __shared__ uint32_t As[BM][LDP];
    __shared__ uint32_t Bs[BN][LDP];

    const int tid  = threadIdx.x;
    const int warp = tid >> 5, lane = tid & 31;
    const int g = lane >> 2, t = lane & 3;
    const int wm = warp & 3;      // 0..3 -> m offset 32*wm
    const int wn = warp >> 2;     // 0..1 -> n offset 32*wn
    const int mbase = blockIdx.y * BM;
    const int nbase = blockIdx.x * BN;

    float acc[2][4][4];
#pragma unroll
    for (int i = 0; i < 2; i++)
#pragma unroll
        for (int j = 0; j < 4; j++)
#pragma unroll
            for (int e = 0; e < 4; e++) acc[i][j][e] = 0.f;

    const int c4 = (tid & 7) * 4;   // k-chunk within tile
    const int rr = tid >> 3;        // 0..31

    for (int k0 = 0; k0 < K; k0 += BK) {
        const int kk = k0 + c4;
        const bool kv = (kk < K);   // K%4==0 -> whole float4 valid
        // A tile: 128 x 32, 4 rows-passes per thread, uint4 STS
#pragma unroll
        for (int pass = 0; pass < 4; ++pass) {
            const int r  = rr + pass * 32;
            const int gm = mbase + r;
            const int src = tok ? tok[gm] : gm;
            float4 v = make_float4(0.f, 0.f, 0.f, 0.f);
            if (kv) v = *reinterpret_cast<const float4*>(A + (size_t)src * K + kk);
            uint4 w = make_uint4(f2tf32(v.x), f2tf32(v.y), f2tf32(v.z), f2tf32(v.w));
            *reinterpret_cast<uint4*>(&As[r][c4]) = w;
        }
        // B tile: 64 x 32, 2 passes
#pragma unroll
        for (int pass = 0; pass < 2; ++pass) {
            const int r = rr + pass * 32;
            const int n = nbase + r;
            float4 v = make_float4(0.f, 0.f, 0.f, 0.f);
            if (kv && n < N) v = *reinterpret_cast<const float4*>(B + (size_t)n * K + kk);
            uint4 w = make_uint4(f2tf32(v.x), f2tf32(v.y), f2tf32(v.z), f2tf32(v.w));
            *reinterpret_cast<uint4*>(&Bs[r][c4]) = w;
        }
        __syncthreads();

#pragma unroll
        for (int ks = 0; ks < 4; ++ks) {
            const int kof = ks * 8;
            uint32_t afr[2][4];
#pragma unroll
            for (int i = 0; i < 2; ++i) {
                const int row = wm * 32 + i * 16 + g;
                afr[i][0] = As[row][kof + t];
                afr[i][1] = As[row + 8][kof + t];
                afr[i][2] = As[row][kof + t + 4];
                afr[i][3] = As[row + 8][kof + t + 4];
            }
            uint32_t bfr[4][2];
#pragma unroll
            for (int j = 0; j < 4; ++j) {
                const int col = wn * 32 + j * 8 + g;
                bfr[j][0] = Bs[col][kof + t];
                bfr[j][1] = Bs[col][kof + t + 4];
            }
#pragma unroll
            for (int i = 0; i < 2; ++i)
#pragma unroll
                for (int j = 0; j < 4; ++j)
                    mma_tf32(acc[i][j], afr[i], bfr[j]);
        }
        __syncthreads();
    }

    // store: C rows always valid (M multiple of 128); guard columns. N even, n0 even.
#pragma unroll
    for (int i = 0; i < 2; ++i) {
        const int m0 = mbase + wm * 32 + i * 16 + g;
#pragma unroll
        for (int j = 0; j < 4; ++j) {
            const int n0 = nbase + wn * 32 + j * 8 + 2 * t;
            if (n0 < N) {
                *reinterpret_cast<float2*>(C + (size_t)m0 * N + n0) =
                    make_float2(acc[i][j][0], acc[i][j][1]);
                *reinterpret_cast<float2*>(C + (size_t)(m0 + 8) * N + n0) =
                    make_float2(acc[i][j][2], acc[i][j][3]);
            }
        }
    }
}

// ---- lstm0 activation: h = sigmoid(o) * tanh(sigmoid(i) * tanh(g))
__global__ void lstm_act(const float* __restrict__ G, const float* __restrict__ bias,
                         float* __restrict__ h)
{
    int idx = blockIdx.x * blockDim.x + threadIdx.x;
    if (idx >= 8192 * 300) return;
    int m = idx / 300, j = idx % 300;
    const float* g = G + (size_t)m * 900;
    float gi = g[j]       + bias[j];
    float gg = g[j + 300] + bias[j + 300];
    float go = g[j + 600] + bias[j + 600];
    float c  = sigmoidf_(gi) * tanhf(gg);
    h[idx]   = sigmoidf_(go) * tanhf(c);
}

// ---- persistent per-batch scan: 64 sequential match-LSTM steps
constexpr int SCAN_SMEM_FLOATS = 19200 + 300 + 300 + 300 + 300 + 900 + 64 + 300 + 900 + 8;
constexpr int SCAN_SMEM_BYTES  = SCAN_SMEM_FLOATS * 4;

__global__ __launch_bounds__(256)
void scan_kernel(const float* __restrict__ sproj, const float* __restrict__ tproj,
                 const float* __restrict__ htpre, const float* __restrict__ hsWa,
                 const float* __restrict__ WmT,   const float* __restrict__ w_e,
                 const float* __restrict__ biasM, const int* __restrict__ plen_a,
                 const int* __restrict__ hlen_a,  const float* __restrict__ fcw,
                 const float* __restrict__ fcb,   float* __restrict__ out)
{
    extern __shared__ float sm[];
    float* sp    = sm;              // [64][300]
    float* we_s  = sp + 19200;      // 300
    float* hm    = we_s + 300;      // 300
    float* mp    = hm + 300;        // 300
    float* tk    = mp + 300;        // 300
    float* gates = tk + 300;        // 900
    float* alpha = gates + 900;     // 64
    float* hfin  = alpha + 64;      // 300
    float* partA = hfin + 300;      // 900
    float* red   = partA + 900;     // 8

    const int b    = blockIdx.x;
    const int tid  = threadIdx.x;
    const int warp = tid >> 5, lane = tid & 31;

    const float* spg = sproj + (size_t)b * (64 * 300);
    for (int i = tid; i < 64 * 300; i += 256) sp[i] = spg[i];
    for (int i = tid; i < 300; i += 256) { we_s[i] = w_e[i]; hm[i] = 0.f; }
    const int plen = plen_a[b];
    const int hlen = hlen_a[b];
    __syncthreads();

    const float* hwg = hsWa + (size_t)b * (64 * 900);

    for (int k = 0; k < 64; ++k) {
        const float* tkg = tproj + ((size_t)b * 64 + k) * 300;
        for (int i = tid; i < 300; i += 256) tk[i] = tkg[i];

        // Phase A: m_proj = hm @ Wm^T via WmT
        if (tid < 225) {
            const int jq  = tid % 75;
            const int seg = tid / 75;
            const int d0  = seg * 100;
            float4 acc = make_float4(0.f, 0.f, 0.f, 0.f);
#pragma unroll 4
            for (int d = d0; d < d0 + 100; ++d) {
                const float hv = hm[d];
                const float4 w = *reinterpret_cast<const float4*>(WmT + (size_t)d * 300 + jq * 4);
                acc.x += hv * w.x; acc.y += hv * w.y; acc.z += hv * w.z; acc.w += hv * w.w;
            }
            reinterpret_cast<float4*>(partA)[seg * 75 + jq] = acc;
        }
        __syncthreads();
        if (tid < 75) {
            float4 a0 = reinterpret_cast<float4*>(partA)[tid];
            float4 a1 = reinterpret_cast<float4*>(partA)[75 + tid];
            float4 a2 = reinterpret_cast<float4*>(partA)[150 + tid];
            reinterpret_cast<float4*>(mp)[tid] =
                make_float4(a0.x + a1.x + a2.x, a0.y + a1.y + a2.y,
                            a0.z + a1.z + a2.z, a0.w + a1.w + a2.w);
        }
        __syncthreads();

        // Phase B: e[p] = w_e . tanh(s_proj[p] + t_k + m_proj)
        for (int p = warp; p < 64; p += 8) {
            const float* sprow = sp + p * 300;
            float acc = 0.f;
            for (int h = lane; h < 300; h += 32) {
                float x = sprow[h] + tk[h] + mp[h];
                acc += we_s[h] * tanhf(x);
            }
#pragma unroll
            for (int o = 16; o > 0; o >>= 1) acc += __shfl_xor_sync(0xffffffffu, acc, o);
            if (lane == 0) alpha[p] = acc;
        }
        __syncthreads();

        // masked softmax over p
        if (warp == 0) {
            float e0 = (lane < plen) ? alpha[lane] : -FLT_MAX;
            float e1 = (lane + 32 < plen) ? alpha[lane + 32] : -FLT_MAX;
            float mx = fmaxf(e0, e1);
#pragma unroll
            for (int o = 16; o > 0; o >>= 1) mx = fmaxf(mx, __shfl_xor_sync(0xffffffffu, mx, o));
            float x0 = (lane < plen) ? expf(e0 - mx) : 0.f;
            float x1 = (lane + 32 < plen) ? expf(e1 - mx) : 0.f;
            float s = x0 + x1;
#pragma unroll
            for (int o = 16; o > 0; o >>= 1) s += __shfl_xor_sync(0xffffffffu, s, o);
            float inv = 1.f / s;
            alpha[lane]      = x0 * inv;
            alpha[lane + 32] = x1 * inv;
        }
        __syncthreads();

        // Phase C: gates = sum_p alpha[p] * hsWa[b,p,:] + ht_pre[b,k,:] + biasM
        if (tid < 225) {
            float4 acc = make_float4(0.f, 0.f, 0.f, 0.f);
            for (int p = 0; p < 64; ++p) {
                const float ap = alpha[p];
                const float4 w = *reinterpret_cast<const float4*>(hwg + (size_t)p * 900 + tid * 4);
                acc.x += ap * w.x; acc.y += ap * w.y; acc.z += ap * w.z; acc.w += ap * w.w;
            }
            const float4 pre = *reinterpret_cast<const float4*>(htpre + ((size_t)b * 64 + k) * 900 + tid * 4);
            const float4 bs  = *reinterpret_cast<const float4*>(biasM + tid * 4);
            acc.x += pre.x + bs.x; acc.y += pre.y + bs.y;
            acc.z += pre.z + bs.z; acc.w += pre.w + bs.w;
            reinterpret_cast<float4*>(gates)[tid] = acc;
        }
        __syncthreads();

        // Phase D: h_m update
        for (int h = tid; h < 300; h += 256) {
            float gi = gates[h];
            float gg = gates[h + 300];
            float go = gates[h + 600];
            float c  = sigmoidf_(gi) * tanhf(gg);
            float hv = sigmoidf_(go) * tanhf(c);
            hm[h] = hv;
            if (k == hlen - 1) hfin[h] = hv;
        }
        __syncthreads();
    }

    if (warp < 3) {
        float acc = 0.f;
        for (int h = lane; h < 300; h += 32) acc += hfin[h] * fcw[warp * 300 + h];
#pragma unroll
        for (int o = 16; o > 0; o >>= 1) acc += __shfl_xor_sync(0xffffffffu, acc, o);
        if (lane == 0) red[warp] = acc + fcb[warp];
    }
    __syncthreads();
    if (tid == 0) {
        float l0 = red[0], l1 = red[1], l2 = red[2];
        float mx = fmaxf(l0, fmaxf(l1, l2));
        float e0 = expf(l0 - mx), e1 = expf(l1 - mx), e2 = expf(l2 - mx);
        float inv = 1.f / (e0 + e1 + e2);
        out[b * 3 + 0] = e0 * inv;
        out[b * 3 + 1] = e1 * inv;
        out[b * 3 + 2] = e2 * inv;
    }
}

// ---------------------------------------------------------------------------
extern "C" void kernel_launch(void* const* d_in, const int* in_sizes, int n_in,
                              void* d_out, int out_size)
{
    const int*   premise = (const int*)  d_in[0];
    const int*   plen    = (const int*)  d_in[1];
    const int*   hyp     = (const int*)  d_in[2];
    const int*   hlen    = (const int*)  d_in[3];
    const float* embed   = (const float*)d_in[4];
    const float* w_e     = (const float*)d_in[5];
    const float* W_s     = (const float*)d_in[6];
    const float* W_t     = (const float*)d_in[7];
    const float* W_m     = (const float*)d_in[8];
    const float* fc_w    = (const float*)d_in[9];
    const float* fc_b    = (const float*)d_in[10];
    const float* Wih_p   = (const float*)d_in[11];
    const float* bih_p   = (const float*)d_in[13];
    const float* bhh_p   = (const float*)d_in[14];
    const float* Wih_h   = (const float*)d_in[15];
    const float* bih_h   = (const float*)d_in[17];
    const float* bhh_h   = (const float*)d_in[18];
    const float* Wih_m   = (const float*)d_in[19];
    const float* bih_m   = (const float*)d_in[21];
    const float* bhh_m   = (const float*)d_in[22];

    float* buf = nullptr;
    cudaGetSymbolAddress((void**)&buf, g_buf);
    float* gates  = buf + OFF_GATES;
    float* hs     = buf + OFF_HS;
    float* ht     = buf + OFF_HT;
    float* sprojp = buf + OFF_SPROJ;
    float* tprojp = buf + OFF_TPROJ;
    float* htprep = buf + OFF_HTPRE;
    float* hsWap  = buf + OFF_HSWA;
    float* Wp     = buf + OFF_WP;
    float* Wh     = buf + OFF_WH;
    float* Wa     = buf + OFF_WA;
    float* Whm    = buf + OFF_WHM;
    float* WmT    = buf + OFF_WMT;
    float* bp     = buf + OFF_BP;
    float* bh     = buf + OFF_BH;
    float* bm     = buf + OFF_BM;

    pack_weights<<<(900 * 300 + 255) / 256, 256>>>(Wih_p, bih_p, bhh_p, 300, 0,   Wp,  bp);
    pack_weights<<<(900 * 300 + 255) / 256, 256>>>(Wih_h, bih_h, bhh_h, 300, 0,   Wh,  bh);
    pack_weights<<<(900 * 300 + 255) / 256, 256>>>(Wih_m, bih_m, bhh_m, 600, 0,   Wa,  bm);
    pack_weights<<<(900 * 300 + 255) / 256, 256>>>(Wih_m, bih_m, bhh_m, 600, 300, Whm, bm);
    transpose_wm<<<(300 * 300 + 255) / 256, 256>>>(W_m, WmT);

    dim3 blk(256);
    dim3 g900(15, 64);  // ceil(900/64) x 8192/128
    dim3 g300(5, 64);   // ceil(300/64)

    // encoders (fused embedding gather)
    mma_tn<<<g900, blk>>>(embed, premise, Wp, gates, 8192, 900, 300);
    lstm_act<<<9600, 256>>>(gates, bp, hs);
    mma_tn<<<g900, blk>>>(embed, hyp, Wh, gates, 8192, 900, 300);
    lstm_act<<<9600, 256>>>(gates, bh, ht);

    // projections + scan-invariant precomputes
    mma_tn<<<g300, blk>>>(hs, nullptr, W_s, sprojp, 8192, 300, 300);
    mma_tn<<<g300, blk>>>(ht, nullptr, W_t, tprojp, 8192, 300, 300);
    mma_tn<<<g900, blk>>>(ht, nullptr, Whm, htprep, 8192, 900, 300);
    mma_tn<<<g900, blk>>>(hs, nullptr, Wa,  hsWap,  8192, 900, 300);

    // sequential match-LSTM scan, one block per batch
    cudaFuncSetAttribute(scan_kernel, cudaFuncAttributeMaxDynamicSharedMemorySize,
                         SCAN_SMEM_BYTES);
    scan_kernel<<<128, 256, SCAN_SMEM_BYTES>>>(sprojp, tprojp, htprep, hsWap, WmT,
                                               w_e, bm, plen, hlen, fc_w, fc_b,
                                               (float*)d_out);
}

// round 5
// speedup vs baseline: 1.7024x; 1.7024x over previous
#include <cuda_runtime.h>
#include <cuda_bf16.h>
#include <math.h>
#include <float.h>
#include <stdint.h>

// ---------------------------------------------------------------------------
// MatchLSTM: B=128, P=K=64, E=H=300, V=50000, C=3
//  GEMMs: bf16 mma.sync.m16n8k16 + ldmatrix (portable PTX; tcgen05 is
//  unavailable under this harness's compute_103 virtual arch).
//  1) prep (1 launch): pack i,g,o gate rows (f dead) -> [900,300]; WmT; biases
//  2) gates = embed[tokens] @ Wpack^T (gather fused), lstm_act -> h_s, h_t
//  3) s_proj, t_proj, ht_pre, hsWa precomputes
//  4) scan: 1 persistent block per batch, 64 sequential steps.
// ---------------------------------------------------------------------------

constexpr size_t SZ_GATES = 8192ull * 900;
constexpr size_t SZ_H     = 8192ull * 300;
constexpr size_t OFF_GATES = 0;
constexpr size_t OFF_HS    = OFF_GATES + SZ_GATES;
constexpr size_t OFF_HT    = OFF_HS + SZ_H;
constexpr size_t OFF_SPROJ = OFF_HT + SZ_H;
constexpr size_t OFF_TPROJ = OFF_SPROJ + SZ_H;
constexpr size_t OFF_HTPRE = OFF_TPROJ + SZ_H;
constexpr size_t OFF_HSWA  = OFF_HTPRE + SZ_GATES;
constexpr size_t OFF_WP    = OFF_HSWA + SZ_GATES;
constexpr size_t OFF_WH    = OFF_WP  + 900ull * 300;
constexpr size_t OFF_WA    = OFF_WH  + 900ull * 300;
constexpr size_t OFF_WHM   = OFF_WA  + 900ull * 300;
constexpr size_t OFF_WMT   = OFF_WHM + 900ull * 300;
constexpr size_t OFF_BP    = OFF_WMT + 300ull * 300;
constexpr size_t OFF_BH    = OFF_BP + 900;
constexpr size_t OFF_BM    = OFF_BH + 900;
constexpr size_t BUF_TOTAL = OFF_BM + 900;

__device__ __align__(16) float g_buf[BUF_TOTAL];

__device__ __forceinline__ float sigmoidf_(float x) { return 1.f / (1.f + expf(-x)); }

__device__ __forceinline__ uint32_t smem_u32(const void* p) {
    uint32_t a;
    asm("{ .reg .u64 t; cvta.to.shared.u64 t, %1; cvt.u32.u64 %0, t; }" : "=r"(a) : "l"(p));
    return a;
}

__device__ __forceinline__ void ldsm_x4(uint32_t r[4], uint32_t addr) {
    asm volatile("ldmatrix.sync.aligned.m8n8.x4.shared.b16 {%0,%1,%2,%3}, [%4];"
                 : "=r"(r[0]), "=r"(r[1]), "=r"(r[2]), "=r"(r[3]) : "r"(addr));
}

__device__ __forceinline__ void mma_bf16(float c[4], const uint32_t a[4],
                                         uint32_t b0, uint32_t b1) {
    asm volatile(
        "mma.sync.aligned.m16n8k16.row.col.f32.bf16.bf16.f32 "
        "{%0,%1,%2,%3}, {%4,%5,%6,%7}, {%8,%9}, {%0,%1,%2,%3};"
        : "+f"(c[0]), "+f"(c[1]), "+f"(c[2]), "+f"(c[3])
        : "r"(a[0]), "r"(a[1]), "r"(a[2]), "r"(a[3]), "r"(b0), "r"(b1));
}

// ======================= fused prep (1 launch) ==============================
// segments: [0,270000) Wp | [270000,540000) Wh | [540000,810000) Wa |
//           [810000,1080000) Whm | [1080000,1170000) WmT ; idx<900 -> biases
__global__ void prep_all(const float* __restrict__ Wih_p, const float* __restrict__ bih_p,
                         const float* __restrict__ bhh_p,
                         const float* __restrict__ Wih_h, const float* __restrict__ bih_h,
                         const float* __restrict__ bhh_h,
                         const float* __restrict__ Wih_m, const float* __restrict__ bih_m,
                         const float* __restrict__ bhh_m,
                         const float* __restrict__ Wm,
                         float* __restrict__ Wp, float* __restrict__ Wh,
                         float* __restrict__ Wa, float* __restrict__ Whm,
                         float* __restrict__ WmT,
                         float* __restrict__ bp, float* __restrict__ bh,
                         float* __restrict__ bm)
{
    int idx = blockIdx.x * blockDim.x + threadIdx.x;
    if (idx < 270000) {
        int j = idx / 300, k2 = idx % 300;
        int src = (j < 300) ? j : j + 300;
        Wp[idx] = Wih_p[(size_t)src * 300 + k2];
    } else if (idx < 540000) {
        int t = idx - 270000;
        int j = t / 300, k2 = t % 300;
        int src = (j < 300) ? j : j + 300;
        Wh[t] = Wih_h[(size_t)src * 300 + k2];
    } else if (idx < 810000) {
        int t = idx - 540000;
        int j = t / 300, k2 = t % 300;
        int src = (j < 300) ? j : j + 300;
        Wa[t] = Wih_m[(size_t)src * 600 + k2];
    } else if (idx < 1080000) {
        int t = idx - 810000;
        int j = t / 300, k2 = t % 300;
        int src = (j < 300) ? j : j + 300;
        Whm[t] = Wih_m[(size_t)src * 600 + 300 + k2];
    } else if (idx < 1170000) {
        int t = idx - 1080000;
        int d = t / 300, j = t % 300;
        WmT[t] = Wm[(size_t)j * 300 + d];
    }
    if (idx < 900) {
        int src = (idx < 300) ? idx : idx + 300;
        bp[idx] = bih_p[src] + bhh_p[src];
        bh[idx] = bih_h[src] + bhh_h[src];
        bm[idx] = bih_m[src] + bhh_m[src];
    }
}

// ======================= bf16 tensor-core GEMM ==============================
// C[M=8192, N] = A[M,300] @ B[Brows,300]^T, fp32 accum.
// Block 128x128x32, 8 warps (2m x 4n), warp tile 64x32.
constexpr int GLDK = 40;  // bf16 row stride (80B): ldmatrix conflict-free

__global__ __launch_bounds__(256)
void gemm_bf16(const float* __restrict__ A, const int* __restrict__ tok,
               const float* __restrict__ B, int Brows,
               float* __restrict__ C, int N)
{
    __shared__ __nv_bfloat16 As[128 * GLDK];
    __shared__ __nv_bfloat16 Bs[128 * GLDK];

    const int tid = threadIdx.x;
    const int warp = tid >> 5, lane = tid & 31;
    const int wm = warp >> 2;       // 0..1 -> m offset 64*wm
    const int wn = warp & 3;        // 0..3 -> n offset 32*wn
    const int mbase = blockIdx.y * 128;
    const int nbase = blockIdx.x * 128;

    // per-thread fill mapping: f4 = tid + 256*p -> row = f4>>3, c4 = f4&7
    int arow_s[4], asrc[4], ac4[4];
    bool bok[4];
#pragma unroll
    for (int p = 0; p < 4; ++p) {
        const int f4 = tid + 256 * p;
        const int row = f4 >> 3;
        arow_s[p] = row;
        ac4[p]    = f4 & 7;
        const int gm = mbase + row;
        asrc[p] = tok ? tok[gm] : gm;
        bok[p]  = (nbase + row) < Brows;
    }

    float acc[4][4][4];
#pragma unroll
    for (int i = 0; i < 4; i++)
#pragma unroll
        for (int n = 0; n < 4; n++)
#pragma unroll
            for (int e = 0; e < 4; e++) acc[i][n][e] = 0.f;

    const uint32_t aB = smem_u32(As), bB = smem_u32(Bs);
    const int lrow = lane & 15;
    const int lkof = (lane >> 4) << 3;

    float4 va[4], vb[4];
    auto load_chunk = [&](int k0) {
#pragma unroll
        for (int p = 0; p < 4; ++p) {
            const int kk = k0 + ac4[p] * 4;
            if (kk < 300) {
                va[p] = *reinterpret_cast<const float4*>(A + (size_t)asrc[p] * 300 + kk);
                vb[p] = bok[p]
                    ? *reinterpret_cast<const float4*>(B + (size_t)(nbase + arow_s[p]) * 300 + kk)
                    : make_float4(0.f, 0.f, 0.f, 0.f);
            } else {
                va[p] = make_float4(0.f, 0.f, 0.f, 0.f);
                vb[p] = make_float4(0.f, 0.f, 0.f, 0.f);
            }
        }
    };
    auto store_chunk = [&]() {
#pragma unroll
        for (int p = 0; p < 4; ++p) {
            const int off = arow_s[p] * GLDK + ac4[p] * 4;
            __nv_bfloat162 alo = __float22bfloat162_rn(make_float2(va[p].x, va[p].y));
            __nv_bfloat162 ahi = __float22bfloat162_rn(make_float2(va[p].z, va[p].w));
            __nv_bfloat162 blo = __float22bfloat162_rn(make_float2(vb[p].x, vb[p].y));
            __nv_bfloat162 bhi = __float22bfloat162_rn(make_float2(vb[p].z, vb[p].w));
            uint2 ua = make_uint2(*reinterpret_cast<uint32_t*>(&alo),
                                  *reinterpret_cast<uint32_t*>(&ahi));
            uint2 ub = make_uint2(*reinterpret_cast<uint32_t*>(&blo),
                                  *reinterpret_cast<uint32_t*>(&bhi));
            *reinterpret_cast<uint2*>(&As[off]) = ua;
            *reinterpret_cast<uint2*>(&Bs[off]) = ub;
        }
    };

    load_chunk(0);
#pragma unroll 1
    for (int c = 0; c < 10; ++c) {
        store_chunk();
        __syncthreads();
        if (c < 9) load_chunk((c + 1) * 32);   // in flight during compute

#pragma unroll
        for (int j = 0; j < 2; ++j) {
            const int kcol = j * 16 + lkof;
            uint32_t af[4][4], bfr[2][4];
#pragma unroll
            for (int i = 0; i < 4; ++i)
                ldsm_x4(af[i], aB + (uint32_t)(((wm * 64 + i * 16 + lrow) * GLDK + kcol) * 2));
#pragma unroll
            for (int nt = 0; nt < 2; ++nt)
                ldsm_x4(bfr[nt], bB + (uint32_t)(((wn * 32 + nt * 16 + lrow) * GLDK + kcol) * 2));
#pragma unroll
            for (int i = 0; i < 4; ++i)
#pragma unroll
                for (int n = 0; n < 4; ++n) {
                    const int nt = n >> 1, s = n & 1;
                    mma_bf16(acc[i][n], af[i], bfr[nt][s], bfr[nt][s + 2]);
                }
        }
        __syncthreads();
    }

    // epilogue: direct f32 stores (rows always valid; guard cols)
#pragma unroll
    for (int i = 0; i < 4; ++i) {
        const int r = mbase + wm * 64 + i * 16 + (lane >> 2);
#pragma unroll
        for (int n = 0; n < 4; ++n) {
            const int col = nbase + wn * 32 + n * 8 + (lane & 3) * 2;
            if (col < N) {
                *reinterpret_cast<float2*>(C + (size_t)r * N + col) =
                    make_float2(acc[i][n][0], acc[i][n][1]);
                *reinterpret_cast<float2*>(C + (size_t)(r + 8) * N + col) =
                    make_float2(acc[i][n][2], acc[i][n][3]);
            }
        }
    }
}

// ======================= lstm0 activation ===================================
__global__ void lstm_act(const float* __restrict__ G, const float* __restrict__ bias,
                         float* __restrict__ h)
{
    int idx = blockIdx.x * blockDim.x + threadIdx.x;
    if (idx >= 8192 * 300) return;
    int m = idx / 300, j = idx % 300;
    const float* g = G + (size_t)m * 900;
    float gi = g[j]       + bias[j];
    float gg = g[j + 300] + bias[j + 300];
    float go = g[j + 600] + bias[j + 600];
    float c  = sigmoidf_(gi) * tanhf(gg);
    h[idx]   = sigmoidf_(go) * tanhf(c);
}

// ======================= persistent per-batch scan ==========================
constexpr int SCAN_SMEM_FLOATS = 19200 + 300 + 300 + 300 + 300 + 900 + 64 + 300 + 900 + 8;
constexpr int SCAN_SMEM_BYTES  = SCAN_SMEM_FLOATS * 4;

__global__ __launch_bounds__(256)
void scan_kernel(const float* __restrict__ sproj, const float* __restrict__ tproj,
                 const float* __restrict__ htpre, const float* __restrict__ hsWa,
                 const float* __restrict__ WmT,   const float* __restrict__ w_e,
                 const float* __restrict__ biasM, const int* __restrict__ plen_a,
                 const int* __restrict__ hlen_a,  const float* __restrict__ fcw,
                 const float* __restrict__ fcb,   float* __restrict__ out)
{
    extern __shared__ float sm[];
    float* sp    = sm;              // [64][300]
    float* we_s  = sp + 19200;      // 300
    float* hm    = we_s + 300;      // 300
    float* mp    = hm + 300;        // 300
    float* tk    = mp + 300;        // 300
    float* gates = tk + 300;        // 900
    float* alpha = gates + 900;     // 64
    float* hfin  = alpha + 64;      // 300
    float* partA = hfin + 300;      // 900
    float* red   = partA + 900;     // 8

    const int b    = blockIdx.x;
    const int tid  = threadIdx.x;
    const int warp = tid >> 5, lane = tid & 31;

    const float* spg = sproj + (size_t)b * (64 * 300);
    for (int i = tid; i < 64 * 300; i += 256) sp[i] = spg[i];
    for (int i = tid; i < 300; i += 256) { we_s[i] = w_e[i]; hm[i] = 0.f; }
    const int plen = plen_a[b];
    const int hlen = hlen_a[b];
    __syncthreads();

    const float* hwg = hsWa + (size_t)b * (64 * 900);

    for (int k = 0; k < 64; ++k) {
        const float* tkg = tproj + ((size_t)b * 64 + k) * 300;
        for (int i = tid; i < 300; i += 256) tk[i] = tkg[i];

        // Phase A: m_proj = hm @ Wm^T via WmT
        if (tid < 225) {
            const int jq  = tid % 75;
            const int seg = tid / 75;
            const int d0  = seg * 100;
            float4 acc = make_float4(0.f, 0.f, 0.f, 0.f);
#pragma unroll 4
            for (int d = d0; d < d0 + 100; ++d) {
                const float hv = hm[d];
                const float4 w = *reinterpret_cast<const float4*>(WmT + (size_t)d * 300 + jq * 4);
                acc.x += hv * w.x; acc.y += hv * w.y; acc.z += hv * w.z; acc.w += hv * w.w;
            }
            reinterpret_cast<float4*>(partA)[seg * 75 + jq] = acc;
        }
        __syncthreads();
        if (tid < 75) {
            float4 a0 = reinterpret_cast<float4*>(partA)[tid];
            float4 a1 = reinterpret_cast<float4*>(partA)[75 + tid];
            float4 a2 = reinterpret_cast<float4*>(partA)[150 + tid];
            reinterpret_cast<float4*>(mp)[tid] =
                make_float4(a0.x + a1.x + a2.x, a0.y + a1.y + a2.y,
                            a0.z + a1.z + a2.z, a0.w + a1.w + a2.w);
        }
        __syncthreads();

        // Phase B: e[p] = w_e . tanh(s_proj[p] + t_k + m_proj)
        for (int p = warp; p < 64; p += 8) {
            const float* sprow = sp + p * 300;
            float acc = 0.f;
            for (int h = lane; h < 300; h += 32) {
                float x = sprow[h] + tk[h] + mp[h];
                acc += we_s[h] * tanhf(x);
            }
#pragma unroll
            for (int o = 16; o > 0; o >>= 1) acc += __shfl_xor_sync(0xffffffffu, acc, o);
            if (lane == 0) alpha[p] = acc;
        }
        __syncthreads();

        // masked softmax over p
        if (warp == 0) {
            float e0 = (lane < plen) ? alpha[lane] : -FLT_MAX;
            float e1 = (lane + 32 < plen) ? alpha[lane + 32] : -FLT_MAX;
            float mx = fmaxf(e0, e1);
#pragma unroll
            for (int o = 16; o > 0; o >>= 1) mx = fmaxf(mx, __shfl_xor_sync(0xffffffffu, mx, o));
            float x0 = (lane < plen) ? expf(e0 - mx) : 0.f;
            float x1 = (lane + 32 < plen) ? expf(e1 - mx) : 0.f;
            float s = x0 + x1;
#pragma unroll
            for (int o = 16; o > 0; o >>= 1) s += __shfl_xor_sync(0xffffffffu, s, o);
            float inv = 1.f / s;
            alpha[lane]      = x0 * inv;
            alpha[lane + 32] = x1 * inv;
        }
        __syncthreads();

        // Phase C: gates = sum_p alpha[p] * hsWa[b,p,:] + ht_pre[b,k,:] + biasM
        if (tid < 225) {
            float4 acc = make_float4(0.f, 0.f, 0.f, 0.f);
            for (int p = 0; p < 64; ++p) {
                const float ap = alpha[p];
                const float4 w = *reinterpret_cast<const float4*>(hwg + (size_t)p * 900 + tid * 4);
                acc.x += ap * w.x; acc.y += ap * w.y; acc.z += ap * w.z; acc.w += ap * w.w;
            }
            const float4 pre = *reinterpret_cast<const float4*>(htpre + ((size_t)b * 64 + k) * 900 + tid * 4);
            const float4 bs  = *reinterpret_cast<const float4*>(biasM + tid * 4);
            acc.x += pre.x + bs.x; acc.y += pre.y + bs.y;
            acc.z += pre.z + bs.z; acc.w += pre.w + bs.w;
            reinterpret_cast<float4*>(gates)[tid] = acc;
        }
        __syncthreads();

        // Phase D: h_m update
        for (int h = tid; h < 300; h += 256) {
            float gi = gates[h];
            float gg = gates[h + 300];
            float go = gates[h + 600];
            float c  = sigmoidf_(gi) * tanhf(gg);
            float hv = sigmoidf_(go) * tanhf(c);
            hm[h] = hv;
            if (k == hlen - 1) hfin[h] = hv;
        }
        __syncthreads();
    }

    if (warp < 3) {
        float acc = 0.f;
        for (int h = lane; h < 300; h += 32) acc += hfin[h] * fcw[warp * 300 + h];
#pragma unroll
        for (int o = 16; o > 0; o >>= 1) acc += __shfl_xor_sync(0xffffffffu, acc, o);
        if (lane == 0) red[warp] = acc + fcb[warp];
    }
    __syncthreads();
    if (tid == 0) {
        float l0 = red[0], l1 = red[1], l2 = red[2];
        float mx = fmaxf(l0, fmaxf(l1, l2));
        float e0 = expf(l0 - mx), e1 = expf(l1 - mx), e2 = expf(l2 - mx);
        float inv = 1.f / (e0 + e1 + e2);
        out[b * 3 + 0] = e0 * inv;
        out[b * 3 + 1] = e1 * inv;
        out[b * 3 + 2] = e2 * inv;
    }
}

// ---------------------------------------------------------------------------
extern "C" void kernel_launch(void* const* d_in, const int* in_sizes, int n_in,
                              void* d_out, int out_size)
{
    const int*   premise = (const int*)  d_in[0];
    const int*   plen    = (const int*)  d_in[1];
    const int*   hyp     = (const int*)  d_in[2];
    const int*   hlen    = (const int*)  d_in[3];
    const float* embed   = (const float*)d_in[4];
    const float* w_e     = (const float*)d_in[5];
    const float* W_s     = (const float*)d_in[6];
    const float* W_t     = (const float*)d_in[7];
    const float* W_m     = (const float*)d_in[8];
    const float* fc_w    = (const float*)d_in[9];
    const float* fc_b    = (const float*)d_in[10];
    const float* Wih_p   = (const float*)d_in[11];
    const float* bih_p   = (const float*)d_in[13];
    const float* bhh_p   = (const float*)d_in[14];
    const float* Wih_h   = (const float*)d_in[15];
    const float* bih_h   = (const float*)d_in[17];
    const float* bhh_h   = (const float*)d_in[18];
    const float* Wih_m   = (const float*)d_in[19];
    const float* bih_m   = (const float*)d_in[21];
    const float* bhh_m   = (const float*)d_in[22];

    float* buf = nullptr;
    cudaGetSymbolAddress((void**)&buf, g_buf);
    float* gates  = buf + OFF_GATES;
    float* hs     = buf + OFF_HS;
    float* ht     = buf + OFF_HT;
    float* sprojp = buf + OFF_SPROJ;
    float* tprojp = buf + OFF_TPROJ;
    float* htprep = buf + OFF_HTPRE;
    float* hsWap  = buf + OFF_HSWA;
    float* Wp     = buf + OFF_WP;
    float* Wh     = buf + OFF_WH;
    float* Wa     = buf + OFF_WA;
    float* Whm    = buf + OFF_WHM;
    float* WmT    = buf + OFF_WMT;
    float* bp     = buf + OFF_BP;
    float* bh     = buf + OFF_BH;
    float* bm     = buf + OFF_BM;

    // 1 launch: all weight packing + WmT + biases
    prep_all<<<(1170000 + 255) / 256, 256>>>(Wih_p, bih_p, bhh_p,
                                             Wih_h, bih_h, bhh_h,
                                             Wih_m, bih_m, bhh_m, W_m,
                                             Wp, Wh, Wa, Whm, WmT, bp, bh, bm);

    dim3 g900(8, 64);   // ceil(900/128) x 8192/128
    dim3 g300(3, 64);   // ceil(300/128)

    // encoders (fused embedding gather)
    gemm_bf16<<<g900, 256>>>(embed, premise, Wp, 900, gates, 900);
    lstm_act<<<9600, 256>>>(gates, bp, hs);
    gemm_bf16<<<g900, 256>>>(embed, hyp, Wh, 900, gates, 900);
    lstm_act<<<9600, 256>>>(gates, bh, ht);

    // hsWa first (launch #6 -> ncu capture slot), then rest
    gemm_bf16<<<g900, 256>>>(hs, nullptr, Wa,  900, hsWap,  900);
    gemm_bf16<<<g900, 256>>>(ht, nullptr, Whm, 900, htprep, 900);
    gemm_bf16<<<g300, 256>>>(hs, nullptr, W_s, 300, sprojp, 300);
    gemm_bf16<<<g300, 256>>>(ht, nullptr, W_t, 300, tprojp, 300);

    // sequential match-LSTM scan, one block per batch
    cudaFuncSetAttribute(scan_kernel, cudaFuncAttributeMaxDynamicSharedMemorySize,
                         SCAN_SMEM_BYTES);
    scan_kernel<<<128, 256, SCAN_SMEM_BYTES>>>(sprojp, tprojp, htprep, hsWap, WmT,
                                               w_e, bm, plen, hlen, fc_w, fc_b,
                                               (float*)d_out);
}

// round 6
// speedup vs baseline: 1.9018x; 1.1171x over previous
#include <cuda_runtime.h>
#include <cuda_bf16.h>
#include <math.h>
#include <float.h>
#include <stdint.h>

// ---------------------------------------------------------------------------
// MatchLSTM: B=128, P=K=64, E=H=300, V=50000, C=3
//  GEMMs: bf16 mma.sync.m16n8k16 + ldmatrix (portable PTX).
//  Scan: WmT resident in SMEM (bf16); hsWa/htpre/tproj streamed as bf16.
// ---------------------------------------------------------------------------

constexpr size_t OFF_GATES = 0;                        // 8192*900 f32
constexpr size_t OFF_HS    = OFF_GATES + 7372800;      // 8192*300 bf16
constexpr size_t OFF_HT    = OFF_HS    + 1228800;      // 8192*300 bf16
constexpr size_t OFF_SPROJ = OFF_HT    + 1228800;      // 8192*300 f32
constexpr size_t OFF_TPROJ = OFF_SPROJ + 2457600;      // 8192*300 bf16
constexpr size_t OFF_HTPRE = OFF_TPROJ + 1228800;      // 8192*900 bf16
constexpr size_t OFF_HSWA  = OFF_HTPRE + 3686400;      // 8192*900 bf16
constexpr size_t OFF_WPB   = OFF_HSWA  + 3686400;      // 900*300 bf16
constexpr size_t OFF_WHB   = OFF_WPB   + 135000;
constexpr size_t OFF_WAB   = OFF_WHB   + 135000;
constexpr size_t OFF_WHMB  = OFF_WAB   + 135000;
constexpr size_t OFF_WSB   = OFF_WHMB  + 135000;       // 300*300 bf16
constexpr size_t OFF_WTB   = OFF_WSB   + 45000;
constexpr size_t OFF_WMTB  = OFF_WTB   + 45000;        // 300*300 bf16
constexpr size_t OFF_BP    = OFF_WMTB  + 45000;        // 900 f32
constexpr size_t OFF_BH    = OFF_BP + 900;
constexpr size_t OFF_BM    = OFF_BH + 900;
constexpr size_t BUF_TOTAL = OFF_BM + 900;

__device__ __align__(16) float g_buf[BUF_TOTAL];

__device__ __forceinline__ float sigmoidf_(float x) { return 1.f / (1.f + expf(-x)); }

__device__ __forceinline__ uint32_t smem_u32(const void* p) {
    uint32_t a;
    asm("{ .reg .u64 t; cvta.to.shared.u64 t, %1; cvt.u32.u64 %0, t; }" : "=r"(a) : "l"(p));
    return a;
}
__device__ __forceinline__ void ldsm_x4(uint32_t r[4], uint32_t addr) {
    asm volatile("ldmatrix.sync.aligned.m8n8.x4.shared.b16 {%0,%1,%2,%3}, [%4];"
                 : "=r"(r[0]), "=r"(r[1]), "=r"(r[2]), "=r"(r[3]) : "r"(addr));
}
__device__ __forceinline__ void mma_bf16(float c[4], const uint32_t a[4],
                                         uint32_t b0, uint32_t b1) {
    asm volatile(
        "mma.sync.aligned.m16n8k16.row.col.f32.bf16.bf16.f32 "
        "{%0,%1,%2,%3}, {%4,%5,%6,%7}, {%8,%9}, {%0,%1,%2,%3};"
        : "+f"(c[0]), "+f"(c[1]), "+f"(c[2]), "+f"(c[3])
        : "r"(a[0]), "r"(a[1]), "r"(a[2]), "r"(a[3]), "r"(b0), "r"(b1));
}
__device__ __forceinline__ float2 bf2f2(uint32_t u) {
    __nv_bfloat162 h = *reinterpret_cast<__nv_bfloat162*>(&u);
    return __bfloat1622float2(h);
}

// ======================= fused prep (1 launch) ==============================
__global__ void prep_all(const float* __restrict__ Wih_p, const float* __restrict__ bih_p,
                         const float* __restrict__ bhh_p,
                         const float* __restrict__ Wih_h, const float* __restrict__ bih_h,
                         const float* __restrict__ bhh_h,
                         const float* __restrict__ Wih_m, const float* __restrict__ bih_m,
                         const float* __restrict__ bhh_m,
                         const float* __restrict__ Wm,
                         const float* __restrict__ Ws, const float* __restrict__ Wt,
                         __nv_bfloat16* __restrict__ Wp, __nv_bfloat16* __restrict__ Wh,
                         __nv_bfloat16* __restrict__ Wa, __nv_bfloat16* __restrict__ Whm,
                         __nv_bfloat16* __restrict__ Wsb, __nv_bfloat16* __restrict__ Wtb,
                         __nv_bfloat16* __restrict__ WmT,
                         float* __restrict__ bp, float* __restrict__ bh,
                         float* __restrict__ bm)
{
    int idx = blockIdx.x * blockDim.x + threadIdx.x;
    if (idx < 270000) {
        int j = idx / 300, k2 = idx % 300;
        int src = (j < 300) ? j : j + 300;
        Wp[idx] = __float2bfloat16(Wih_p[(size_t)src * 300 + k2]);
    } else if (idx < 540000) {
        int t = idx - 270000; int j = t / 300, k2 = t % 300;
        int src = (j < 300) ? j : j + 300;
        Wh[t] = __float2bfloat16(Wih_h[(size_t)src * 300 + k2]);
    } else if (idx < 810000) {
        int t = idx - 540000; int j = t / 300, k2 = t % 300;
        int src = (j < 300) ? j : j + 300;
        Wa[t] = __float2bfloat16(Wih_m[(size_t)src * 600 + k2]);
    } else if (idx < 1080000) {
        int t = idx - 810000; int j = t / 300, k2 = t % 300;
        int src = (j < 300) ? j : j + 300;
        Whm[t] = __float2bfloat16(Wih_m[(size_t)src * 600 + 300 + k2]);
    } else if (idx < 1170000) {
        int t = idx - 1080000;
        Wsb[t] = __float2bfloat16(Ws[t]);
    } else if (idx < 1260000) {
        int t = idx - 1170000;
        Wtb[t] = __float2bfloat16(Wt[t]);
    } else if (idx < 1350000) {
        int t = idx - 1260000; int d = t / 300, j = t % 300;
        WmT[t] = __float2bfloat16(Wm[(size_t)j * 300 + d]);
    }
    if (idx < 900) {
        int src = (idx < 300) ? idx : idx + 300;
        bp[idx] = bih_p[src] + bhh_p[src];
        bh[idx] = bih_h[src] + bhh_h[src];
        bm[idx] = bih_m[src] + bhh_m[src];
    }
}

// ======================= bf16 tensor-core GEMM ==============================
// C[M=8192, N] = A[M,300] @ B[Brows,300]^T, fp32 accum.
// Block 128x128x32, 8 warps (2m x 4n), warp tile 64x32.
// AT in {float (gather A), __nv_bfloat16}; CT in {float, __nv_bfloat16}.
constexpr int GLDK = 40;

template <typename AT, typename CT>
__global__ __launch_bounds__(256)
void gemm_bb(const AT* __restrict__ A, const int* __restrict__ tok,
             const __nv_bfloat16* __restrict__ B, int Brows,
             CT* __restrict__ C, int N)
{
    constexpr bool AF32 = (sizeof(AT) == 4);
    __shared__ __nv_bfloat16 As[128 * GLDK];
    __shared__ __nv_bfloat16 Bs[128 * GLDK];

    const int tid = threadIdx.x;
    const int warp = tid >> 5, lane = tid & 31;
    const int wm = warp >> 2, wn = warp & 3;
    const int mbase = blockIdx.y * 128;
    const int nbase = blockIdx.x * 128;

    int arow_s[4], asrc[4], ac4[4];
    bool bok[4];
#pragma unroll
    for (int p = 0; p < 4; ++p) {
        const int f4 = tid + 256 * p;
        const int row = f4 >> 3;
        arow_s[p] = row;
        ac4[p]    = f4 & 7;
        const int gm = mbase + row;
        asrc[p] = tok ? tok[gm] : gm;
        bok[p]  = (nbase + row) < Brows;
    }

    float acc[4][4][4];
#pragma unroll
    for (int i = 0; i < 4; i++)
#pragma unroll
        for (int n = 0; n < 4; n++)
#pragma unroll
            for (int e = 0; e < 4; e++) acc[i][n][e] = 0.f;

    const uint32_t aB = smem_u32(As), bB = smem_u32(Bs);
    const int lrow = lane & 15;
    const int lkof = (lane >> 4) << 3;

    float4 vaf[4];
    uint2  vab[4], vbb[4];

    auto load_chunk = [&](int k0) {
#pragma unroll
        for (int p = 0; p < 4; ++p) {
            const int kk = k0 + ac4[p] * 4;
            const bool kv = (kk < 300);
            if (AF32) {
                vaf[p] = kv ? *reinterpret_cast<const float4*>((const float*)A + (size_t)asrc[p] * 300 + kk)
                            : make_float4(0.f, 0.f, 0.f, 0.f);
            } else {
                vab[p] = kv ? *reinterpret_cast<const uint2*>((const __nv_bfloat16*)A + (size_t)asrc[p] * 300 + kk)
                            : make_uint2(0u, 0u);
            }
            vbb[p] = (kv && bok[p])
                ? *reinterpret_cast<const uint2*>(B + (size_t)(nbase + arow_s[p]) * 300 + kk)
                : make_uint2(0u, 0u);
        }
    };
    auto store_chunk = [&]() {
#pragma unroll
        for (int p = 0; p < 4; ++p) {
            const int off = arow_s[p] * GLDK + ac4[p] * 4;
            if (AF32) {
                __nv_bfloat162 alo = __float22bfloat162_rn(make_float2(vaf[p].x, vaf[p].y));
                __nv_bfloat162 ahi = __float22bfloat162_rn(make_float2(vaf[p].z, vaf[p].w));
                *reinterpret_cast<uint2*>(&As[off]) =
                    make_uint2(*reinterpret_cast<uint32_t*>(&alo), *reinterpret_cast<uint32_t*>(&ahi));
            } else {
                *reinterpret_cast<uint2*>(&As[off]) = vab[p];
            }
            *reinterpret_cast<uint2*>(&Bs[off]) = vbb[p];
        }
    };

    load_chunk(0);
#pragma unroll 1
    for (int c = 0; c < 10; ++c) {
        store_chunk();
        __syncthreads();
        if (c < 9) load_chunk((c + 1) * 32);

#pragma unroll
        for (int j = 0; j < 2; ++j) {
            const int kcol = j * 16 + lkof;
            uint32_t af[4][4], bfr[2][4];
#pragma unroll
            for (int i = 0; i < 4; ++i)
                ldsm_x4(af[i], aB + (uint32_t)(((wm * 64 + i * 16 + lrow) * GLDK + kcol) * 2));
#pragma unroll
            for (int nt = 0; nt < 2; ++nt)
                ldsm_x4(bfr[nt], bB + (uint32_t)(((wn * 32 + nt * 16 + lrow) * GLDK + kcol) * 2));
#pragma unroll
            for (int i = 0; i < 4; ++i)
#pragma unroll
                for (int n = 0; n < 4; ++n) {
                    const int nt = n >> 1, s = n & 1;
                    mma_bf16(acc[i][n], af[i], bfr[nt][s], bfr[nt][s + 2]);
                }
        }
        __syncthreads();
    }

#pragma unroll
    for (int i = 0; i < 4; ++i) {
        const int r = mbase + wm * 64 + i * 16 + (lane >> 2);
#pragma unroll
        for (int n = 0; n < 4; ++n) {
            const int col = nbase + wn * 32 + n * 8 + (lane & 3) * 2;
            if (col < N) {
                if (sizeof(CT) == 4) {
                    *reinterpret_cast<float2*>((float*)C + (size_t)r * N + col) =
                        make_float2(acc[i][n][0], acc[i][n][1]);
                    *reinterpret_cast<float2*>((float*)C + (size_t)(r + 8) * N + col) =
                        make_float2(acc[i][n][2], acc[i][n][3]);
                } else {
                    __nv_bfloat162 lo = __float22bfloat162_rn(make_float2(acc[i][n][0], acc[i][n][1]));
                    __nv_bfloat162 hi = __float22bfloat162_rn(make_float2(acc[i][n][2], acc[i][n][3]));
                    *reinterpret_cast<uint32_t*>((__nv_bfloat16*)C + (size_t)r * N + col) =
                        *reinterpret_cast<uint32_t*>(&lo);
                    *reinterpret_cast<uint32_t*>((__nv_bfloat16*)C + (size_t)(r + 8) * N + col) =
                        *reinterpret_cast<uint32_t*>(&hi);
                }
            }
        }
    }
}

// ======================= lstm0 activation (f32 in, bf16 out) ================
__global__ void lstm_act(const float* __restrict__ G, const float* __restrict__ bias,
                         __nv_bfloat16* __restrict__ h)
{
    int idx = blockIdx.x * blockDim.x + threadIdx.x;
    if (idx >= 8192 * 300) return;
    int m = idx / 300, j = idx % 300;
    const float* g = G + (size_t)m * 900;
    float gi = g[j]       + bias[j];
    float gg = g[j + 300] + bias[j + 300];
    float go = g[j + 600] + bias[j + 600];
    float c  = sigmoidf_(gi) * tanhf(gg);
    h[idx]   = __float2bfloat16(sigmoidf_(go) * tanhf(c));
}

// ======================= persistent per-batch scan ==========================
// SMEM: WmT bf16 180000 | sp bf16 38400 | we 1200 | hm 1200 | mp 1200 |
//       tk 1200 | gates 3600 (=partA) | alpha 256 | hfin 1200 | red 32
constexpr int SCAN_SMEM_BYTES = 180000 + 38400 + 1200 + 1200 + 1200 + 1200
                              + 3600 + 256 + 1200 + 32;   // 228288

__global__ __launch_bounds__(256)
void scan_kernel(const float* __restrict__ sproj, const __nv_bfloat16* __restrict__ tproj,
                 const __nv_bfloat16* __restrict__ htpre, const __nv_bfloat16* __restrict__ hsWa,
                 const __nv_bfloat16* __restrict__ WmTg,  const float* __restrict__ w_e,
                 const float* __restrict__ biasM, const int* __restrict__ plen_a,
                 const int* __restrict__ hlen_a,  const float* __restrict__ fcw,
                 const float* __restrict__ fcb,   float* __restrict__ out)
{
    extern __shared__ char smraw[];
    __nv_bfloat16* wmt  = reinterpret_cast<__nv_bfloat16*>(smraw);            // 90000
    __nv_bfloat16* sp   = reinterpret_cast<__nv_bfloat16*>(smraw + 180000);   // 19200
    float* we_s  = reinterpret_cast<float*>(smraw + 218400);  // 300
    float* hm    = we_s + 300;
    float* mp    = hm + 300;
    float* tk    = mp + 300;
    float* gates = tk + 300;        // 900 (doubles as partA)
    float* alpha = gates + 900;     // 64
    float* hfin  = alpha + 64;      // 300
    float* red   = hfin + 300;      // 8

    const int b    = blockIdx.x;
    const int tid  = threadIdx.x;
    const int warp = tid >> 5, lane = tid & 31;

    // one-time loads
    for (int i = tid; i < 11250; i += 256)
        reinterpret_cast<uint4*>(wmt)[i] = reinterpret_cast<const uint4*>(WmTg)[i];
    const float* spg = sproj + (size_t)b * (64 * 300);
    for (int i = tid; i < 19200; i += 256) sp[i] = __float2bfloat16(spg[i]);
    for (int i = tid; i < 300; i += 256) { we_s[i] = w_e[i]; hm[i] = 0.f; }
    const int plen = plen_a[b];
    const int hlen = hlen_a[b];
    __syncthreads();

    const __nv_bfloat16* hwg = hsWa + (size_t)b * (64 * 900);

    for (int k = 0; k < 64; ++k) {
        // t_k (bf16 -> f32 smem)
        const __nv_bfloat16* tkg = tproj + ((size_t)b * 64 + k) * 300;
        if (tid < 150) {
            float2 v = bf2f2(reinterpret_cast<const uint32_t*>(tkg)[tid]);
            tk[2 * tid] = v.x; tk[2 * tid + 1] = v.y;
        }

        // Phase A: m_proj = hm @ Wm^T, WmT resident in SMEM (bf16)
        if (tid < 225) {
            const int jq  = tid % 75;
            const int seg = tid / 75;
            const int d0  = seg * 100;
            float4 acc = make_float4(0.f, 0.f, 0.f, 0.f);
#pragma unroll 4
            for (int d = d0; d < d0 + 100; ++d) {
                const float hv = hm[d];
                const uint2 w = *reinterpret_cast<const uint2*>(wmt + d * 300 + jq * 4);
                float2 w0 = bf2f2(w.x), w1 = bf2f2(w.y);
                acc.x += hv * w0.x; acc.y += hv * w0.y;
                acc.z += hv * w1.x; acc.w += hv * w1.y;
            }
            reinterpret_cast<float4*>(gates)[seg * 75 + jq] = acc;  // partials
        }
        __syncthreads();
        if (tid < 75) {
            float4 a0 = reinterpret_cast<float4*>(gates)[tid];
            float4 a1 = reinterpret_cast<float4*>(gates)[75 + tid];
            float4 a2 = reinterpret_cast<float4*>(gates)[150 + tid];
            reinterpret_cast<float4*>(mp)[tid] =
                make_float4(a0.x + a1.x + a2.x, a0.y + a1.y + a2.y,
                            a0.z + a1.z + a2.z, a0.w + a1.w + a2.w);
        }
        __syncthreads();

        // Phase B: e[p] = w_e . tanh(s_proj[p] + t_k + m_proj), p < plen only
        for (int p = warp; p < plen; p += 8) {
            const uint32_t* sprow = reinterpret_cast<const uint32_t*>(sp + p * 300);
            float acc = 0.f;
            for (int hp = lane; hp < 150; hp += 32) {
                float2 s = bf2f2(sprow[hp]);
                const int h = 2 * hp;
                acc += we_s[h]     * tanhf(s.x + tk[h]     + mp[h]);
                acc += we_s[h + 1] * tanhf(s.y + tk[h + 1] + mp[h + 1]);
            }
#pragma unroll
            for (int o = 16; o > 0; o >>= 1) acc += __shfl_xor_sync(0xffffffffu, acc, o);
            if (lane == 0) alpha[p] = acc;
        }
        __syncthreads();

        // masked softmax over p
        if (warp == 0) {
            float e0 = (lane < plen) ? alpha[lane] : -FLT_MAX;
            float e1 = (lane + 32 < plen) ? alpha[lane + 32] : -FLT_MAX;
            float mx = fmaxf(e0, e1);
#pragma unroll
            for (int o = 16; o > 0; o >>= 1) mx = fmaxf(mx, __shfl_xor_sync(0xffffffffu, mx, o));
            float x0 = (lane < plen) ? expf(e0 - mx) : 0.f;
            float x1 = (lane + 32 < plen) ? expf(e1 - mx) : 0.f;
            float s = x0 + x1;
#pragma unroll
            for (int o = 16; o > 0; o >>= 1) s += __shfl_xor_sync(0xffffffffu, s, o);
            float inv = 1.f / s;
            alpha[lane]      = x0 * inv;
            alpha[lane + 32] = x1 * inv;
        }
        __syncthreads();

        // Phase C: gates = sum_{p<plen} alpha[p]*hsWa[b,p,:] + ht_pre[b,k,:] + biasM
        if (tid < 225) {
            float4 acc = make_float4(0.f, 0.f, 0.f, 0.f);
            for (int p = 0; p < plen; ++p) {
                const float ap = alpha[p];
                const uint2 w = __ldcs(reinterpret_cast<const uint2*>(hwg + (size_t)p * 900 + tid * 4));
                float2 w0 = bf2f2(w.x), w1 = bf2f2(w.y);
                acc.x += ap * w0.x; acc.y += ap * w0.y;
                acc.z += ap * w1.x; acc.w += ap * w1.y;
            }
            const uint2 pr = __ldcs(reinterpret_cast<const uint2*>(
                htpre + ((size_t)b * 64 + k) * 900 + tid * 4));
            float2 p0 = bf2f2(pr.x), p1 = bf2f2(pr.y);
            const float4 bs = *reinterpret_cast<const float4*>(biasM + tid * 4);
            acc.x += p0.x + bs.x; acc.y += p0.y + bs.y;
            acc.z += p1.x + bs.z; acc.w += p1.y + bs.w;
            reinterpret_cast<float4*>(gates)[tid] = acc;
        }
        __syncthreads();

        // Phase D: h_m update
        for (int h = tid; h < 300; h += 256) {
            float gi = gates[h];
            float gg = gates[h + 300];
            float go = gates[h + 600];
            float c  = sigmoidf_(gi) * tanhf(gg);
            float hv = sigmoidf_(go) * tanhf(c);
            hm[h] = hv;
            if (k == hlen - 1) hfin[h] = hv;
        }
        __syncthreads();
    }

    if (warp < 3) {
        float acc = 0.f;
        for (int h = lane; h < 300; h += 32) acc += hfin[h] * fcw[warp * 300 + h];
#pragma unroll
        for (int o = 16; o > 0; o >>= 1) acc += __shfl_xor_sync(0xffffffffu, acc, o);
        if (lane == 0) red[warp] = acc + fcb[warp];
    }
    __syncthreads();
    if (tid == 0) {
        float l0 = red[0], l1 = red[1], l2 = red[2];
        float mx = fmaxf(l0, fmaxf(l1, l2));
        float e0 = expf(l0 - mx), e1 = expf(l1 - mx), e2 = expf(l2 - mx);
        float inv = 1.f / (e0 + e1 + e2);
        out[b * 3 + 0] = e0 * inv;
        out[b * 3 + 1] = e1 * inv;
        out[b * 3 + 2] = e2 * inv;
    }
}

// ---------------------------------------------------------------------------
extern "C" void kernel_launch(void* const* d_in, const int* in_sizes, int n_in,
                              void* d_out, int out_size)
{
    const int*   premise = (const int*)  d_in[0];
    const int*   plen    = (const int*)  d_in[1];
    const int*   hyp     = (const int*)  d_in[2];
    const int*   hlen    = (const int*)  d_in[3];
    const float* embed   = (const float*)d_in[4];
    const float* w_e     = (const float*)d_in[5];
    const float* W_s     = (const float*)d_in[6];
    const float* W_t     = (const float*)d_in[7];
    const float* W_m     = (const float*)d_in[8];
    const float* fc_w    = (const float*)d_in[9];
    const float* fc_b    = (const float*)d_in[10];
    const float* Wih_p   = (const float*)d_in[11];
    const float* bih_p   = (const float*)d_in[13];
    const float* bhh_p   = (const float*)d_in[14];
    const float* Wih_h   = (const float*)d_in[15];
    const float* bih_h   = (const float*)d_in[17];
    const float* bhh_h   = (const float*)d_in[18];
    const float* Wih_m   = (const float*)d_in[19];
    const float* bih_m   = (const float*)d_in[21];
    const float* bhh_m   = (const float*)d_in[22];

    float* buf = nullptr;
    cudaGetSymbolAddress((void**)&buf, g_buf);
    float*          gates  = buf + OFF_GATES;
    __nv_bfloat16*  hs     = (__nv_bfloat16*)(buf + OFF_HS);
    __nv_bfloat16*  ht     = (__nv_bfloat16*)(buf + OFF_HT);
    float*          sprojp = buf + OFF_SPROJ;
    __nv_bfloat16*  tprojp = (__nv_bfloat16*)(buf + OFF_TPROJ);
    __nv_bfloat16*  htprep = (__nv_bfloat16*)(buf + OFF_HTPRE);
    __nv_bfloat16*  hsWap  = (__nv_bfloat16*)(buf + OFF_HSWA);
    __nv_bfloat16*  Wp     = (__nv_bfloat16*)(buf + OFF_WPB);
    __nv_bfloat16*  Wh     = (__nv_bfloat16*)(buf + OFF_WHB);
    __nv_bfloat16*  Wa     = (__nv_bfloat16*)(buf + OFF_WAB);
    __nv_bfloat16*  Whm    = (__nv_bfloat16*)(buf + OFF_WHMB);
    __nv_bfloat16*  Wsb    = (__nv_bfloat16*)(buf + OFF_WSB);
    __nv_bfloat16*  Wtb    = (__nv_bfloat16*)(buf + OFF_WTB);
    __nv_bfloat16*  WmT    = (__nv_bfloat16*)(buf + OFF_WMTB);
    float* bp = buf + OFF_BP;
    float* bh = buf + OFF_BH;
    float* bm = buf + OFF_BM;

    prep_all<<<(1350000 + 255) / 256, 256>>>(Wih_p, bih_p, bhh_p,
                                             Wih_h, bih_h, bhh_h,
                                             Wih_m, bih_m, bhh_m,
                                             W_m, W_s, W_t,
                                             Wp, Wh, Wa, Whm, Wsb, Wtb, WmT,
                                             bp, bh, bm);

    dim3 g900(8, 64), g300(3, 64);

    // encoders (fused embedding gather, f32 A)
    gemm_bb<float, float><<<g900, 256>>>(embed, premise, Wp, 900, gates, 900);
    lstm_act<<<9600, 256>>>(gates, bp, hs);
    gemm_bb<float, float><<<g900, 256>>>(embed, hyp, Wh, 900, gates, 900);
    lstm_act<<<9600, 256>>>(gates, bh, ht);

    // precomputes (bf16 A; hsWa first so ncu's capture slot sees it)
    gemm_bb<__nv_bfloat16, __nv_bfloat16><<<g900, 256>>>(hs, nullptr, Wa,  900, hsWap,  900);
    gemm_bb<__nv_bfloat16, __nv_bfloat16><<<g900, 256>>>(ht, nullptr, Whm, 900, htprep, 900);
    gemm_bb<__nv_bfloat16, float        ><<<g300, 256>>>(hs, nullptr, Wsb, 300, sprojp, 300);
    gemm_bb<__nv_bfloat16, __nv_bfloat16><<<g300, 256>>>(ht, nullptr, Wtb, 300, tprojp, 300);

    cudaFuncSetAttribute(scan_kernel, cudaFuncAttributeMaxDynamicSharedMemorySize,
                         SCAN_SMEM_BYTES);
    scan_kernel<<<128, 256, SCAN_SMEM_BYTES>>>(sprojp, tprojp, htprep, hsWap, WmT,
                                               w_e, bm, plen, hlen, fc_w, fc_b,
                                               (float*)d_out);
}

// round 7
// speedup vs baseline: 2.1389x; 1.1247x over previous
#include <cuda_runtime.h>
#include <cuda_bf16.h>
#include <math.h>
#include <float.h>
#include <stdint.h>

// ---------------------------------------------------------------------------
// MatchLSTM: B=128, P=K=64, E=H=300, V=50000, C=3
//  GEMMs: bf16 mma.sync.m16n8k16 + ldmatrix (portable PTX).
//  Scan: 512 thr/block, WmT in SMEM, bf16x2 packed attention with MUFU tanh.
// ---------------------------------------------------------------------------

constexpr size_t OFF_GATES = 0;                        // 8192*900 f32
constexpr size_t OFF_HS    = OFF_GATES + 7372800;      // 8192*300 bf16
constexpr size_t OFF_HT    = OFF_HS    + 1228800;
constexpr size_t OFF_SPROJ = OFF_HT    + 1228800;      // 8192*300 f32
constexpr size_t OFF_TPROJ = OFF_SPROJ + 2457600;      // 8192*300 bf16
constexpr size_t OFF_HTPRE = OFF_TPROJ + 1228800;      // 8192*900 bf16
constexpr size_t OFF_HSWA  = OFF_HTPRE + 3686400;      // 8192*900 bf16
constexpr size_t OFF_WPB   = OFF_HSWA  + 3686400;      // 900*300 bf16
constexpr size_t OFF_WHB   = OFF_WPB   + 135000;
constexpr size_t OFF_WAB   = OFF_WHB   + 135000;
constexpr size_t OFF_WHMB  = OFF_WAB   + 135000;
constexpr size_t OFF_WSB   = OFF_WHMB  + 135000;       // 300*300 bf16
constexpr size_t OFF_WTB   = OFF_WSB   + 45000;
constexpr size_t OFF_WMTB  = OFF_WTB   + 45000;        // 300*300 bf16
constexpr size_t OFF_BP    = OFF_WMTB  + 45000;        // 900 f32
constexpr size_t OFF_BH    = OFF_BP + 900;
constexpr size_t OFF_BM    = OFF_BH + 900;
constexpr size_t BUF_TOTAL = OFF_BM + 900;

__device__ __align__(16) float g_buf[BUF_TOTAL];

__device__ __forceinline__ float sigmoidf_(float x) { return 1.f / (1.f + expf(-x)); }

__device__ __forceinline__ uint32_t smem_u32(const void* p) {
    uint32_t a;
    asm("{ .reg .u64 t; cvta.to.shared.u64 t, %1; cvt.u32.u64 %0, t; }" : "=r"(a) : "l"(p));
    return a;
}
__device__ __forceinline__ void ldsm_x4(uint32_t r[4], uint32_t addr) {
    asm volatile("ldmatrix.sync.aligned.m8n8.x4.shared.b16 {%0,%1,%2,%3}, [%4];"
                 : "=r"(r[0]), "=r"(r[1]), "=r"(r[2]), "=r"(r[3]) : "r"(addr));
}
__device__ __forceinline__ void mma_bf16(float c[4], const uint32_t a[4],
                                         uint32_t b0, uint32_t b1) {
    asm volatile(
        "mma.sync.aligned.m16n8k16.row.col.f32.bf16.bf16.f32 "
        "{%0,%1,%2,%3}, {%4,%5,%6,%7}, {%8,%9}, {%0,%1,%2,%3};"
        : "+f"(c[0]), "+f"(c[1]), "+f"(c[2]), "+f"(c[3])
        : "r"(a[0]), "r"(a[1]), "r"(a[2]), "r"(a[3]), "r"(b0), "r"(b1));
}
__device__ __forceinline__ float2 bf2f2(uint32_t u) {
    __nv_bfloat162 h = *reinterpret_cast<__nv_bfloat162*>(&u);
    return __bfloat1622float2(h);
}
__device__ __forceinline__ uint32_t tanh_bf16x2(uint32_t x) {
    uint32_t d;
    asm("tanh.approx.bf16x2 %0, %1;" : "=r"(d) : "r"(x));
    return d;
}

// ======================= fused prep (1 launch) ==============================
__global__ void prep_all(const float* __restrict__ Wih_p, const float* __restrict__ bih_p,
                         const float* __restrict__ bhh_p,
                         const float* __restrict__ Wih_h, const float* __restrict__ bih_h,
                         const float* __restrict__ bhh_h,
                         const float* __restrict__ Wih_m, const float* __restrict__ bih_m,
                         const float* __restrict__ bhh_m,
                         const float* __restrict__ Wm,
                         const float* __restrict__ Ws, const float* __restrict__ Wt,
                         __nv_bfloat16* __restrict__ Wp, __nv_bfloat16* __restrict__ Wh,
                         __nv_bfloat16* __restrict__ Wa, __nv_bfloat16* __restrict__ Whm,
                         __nv_bfloat16* __restrict__ Wsb, __nv_bfloat16* __restrict__ Wtb,
                         __nv_bfloat16* __restrict__ WmT,
                         float* __restrict__ bp, float* __restrict__ bh,
                         float* __restrict__ bm)
{
    int idx = blockIdx.x * blockDim.x + threadIdx.x;
    if (idx < 270000) {
        int j = idx / 300, k2 = idx % 300;
        int src = (j < 300) ? j : j + 300;
        Wp[idx] = __float2bfloat16(Wih_p[(size_t)src * 300 + k2]);
    } else if (idx < 540000) {
        int t = idx - 270000; int j = t / 300, k2 = t % 300;
        int src = (j < 300) ? j : j + 300;
        Wh[t] = __float2bfloat16(Wih_h[(size_t)src * 300 + k2]);
    } else if (idx < 810000) {
        int t = idx - 540000; int j = t / 300, k2 = t % 300;
        int src = (j < 300) ? j : j + 300;
        Wa[t] = __float2bfloat16(Wih_m[(size_t)src * 600 + k2]);
    } else if (idx < 1080000) {
        int t = idx - 810000; int j = t / 300, k2 = t % 300;
        int src = (j < 300) ? j : j + 300;
        Whm[t] = __float2bfloat16(Wih_m[(size_t)src * 600 + 300 + k2]);
    } else if (idx < 1170000) {
        int t = idx - 1080000;
        Wsb[t] = __float2bfloat16(Ws[t]);
    } else if (idx < 1260000) {
        int t = idx - 1170000;
        Wtb[t] = __float2bfloat16(Wt[t]);
    } else if (idx < 1350000) {
        int t = idx - 1260000; int d = t / 300, j = t % 300;
        WmT[t] = __float2bfloat16(Wm[(size_t)j * 300 + d]);
    }
    if (idx < 900) {
        int src = (idx < 300) ? idx : idx + 300;
        bp[idx] = bih_p[src] + bhh_p[src];
        bh[idx] = bih_h[src] + bhh_h[src];
        bm[idx] = bih_m[src] + bhh_m[src];
    }
}

// ======================= bf16 tensor-core GEMM ==============================
constexpr int GLDK = 40;

template <typename AT, typename CT>
__global__ __launch_bounds__(256)
void gemm_bb(const AT* __restrict__ A, const int* __restrict__ tok,
             const __nv_bfloat16* __restrict__ B, int Brows,
             CT* __restrict__ C, int N)
{
    constexpr bool AF32 = (sizeof(AT) == 4);
    __shared__ __nv_bfloat16 As[128 * GLDK];
    __shared__ __nv_bfloat16 Bs[128 * GLDK];

    const int tid = threadIdx.x;
    const int warp = tid >> 5, lane = tid & 31;
    const int wm = warp >> 2, wn = warp & 3;
    const int mbase = blockIdx.y * 128;
    const int nbase = blockIdx.x * 128;

    int arow_s[4], asrc[4], ac4[4];
    bool bok[4];
#pragma unroll
    for (int p = 0; p < 4; ++p) {
        const int f4 = tid + 256 * p;
        const int row = f4 >> 3;
        arow_s[p] = row;
        ac4[p]    = f4 & 7;
        const int gm = mbase + row;
        asrc[p] = tok ? tok[gm] : gm;
        bok[p]  = (nbase + row) < Brows;
    }

    float acc[4][4][4];
#pragma unroll
    for (int i = 0; i < 4; i++)
#pragma unroll
        for (int n = 0; n < 4; n++)
#pragma unroll
            for (int e = 0; e < 4; e++) acc[i][n][e] = 0.f;

    const uint32_t aB = smem_u32(As), bB = smem_u32(Bs);
    const int lrow = lane & 15;
    const int lkof = (lane >> 4) << 3;

    float4 vaf[4];
    uint2  vab[4], vbb[4];

    auto load_chunk = [&](int k0) {
#pragma unroll
        for (int p = 0; p < 4; ++p) {
            const int kk = k0 + ac4[p] * 4;
            const bool kv = (kk < 300);
            if (AF32) {
                vaf[p] = kv ? *reinterpret_cast<const float4*>((const float*)A + (size_t)asrc[p] * 300 + kk)
                            : make_float4(0.f, 0.f, 0.f, 0.f);
            } else {
                vab[p] = kv ? *reinterpret_cast<const uint2*>((const __nv_bfloat16*)A + (size_t)asrc[p] * 300 + kk)
                            : make_uint2(0u, 0u);
            }
            vbb[p] = (kv && bok[p])
                ? *reinterpret_cast<const uint2*>(B + (size_t)(nbase + arow_s[p]) * 300 + kk)
                : make_uint2(0u, 0u);
        }
    };
    auto store_chunk = [&]() {
#pragma unroll
        for (int p = 0; p < 4; ++p) {
            const int off = arow_s[p] * GLDK + ac4[p] * 4;
            if (AF32) {
                __nv_bfloat162 alo = __float22bfloat162_rn(make_float2(vaf[p].x, vaf[p].y));
                __nv_bfloat162 ahi = __float22bfloat162_rn(make_float2(vaf[p].z, vaf[p].w));
                *reinterpret_cast<uint2*>(&As[off]) =
                    make_uint2(*reinterpret_cast<uint32_t*>(&alo), *reinterpret_cast<uint32_t*>(&ahi));
            } else {
                *reinterpret_cast<uint2*>(&As[off]) = vab[p];
            }
            *reinterpret_cast<uint2*>(&Bs[off]) = vbb[p];
        }
    };

    load_chunk(0);
#pragma unroll 1
    for (int c = 0; c < 10; ++c) {
        store_chunk();
        __syncthreads();
        if (c < 9) load_chunk((c + 1) * 32);

#pragma unroll
        for (int j = 0; j < 2; ++j) {
            const int kcol = j * 16 + lkof;
            uint32_t af[4][4], bfr[2][4];
#pragma unroll
            for (int i = 0; i < 4; ++i)
                ldsm_x4(af[i], aB + (uint32_t)(((wm * 64 + i * 16 + lrow) * GLDK + kcol) * 2));
#pragma unroll
            for (int nt = 0; nt < 2; ++nt)
                ldsm_x4(bfr[nt], bB + (uint32_t)(((wn * 32 + nt * 16 + lrow) * GLDK + kcol) * 2));
#pragma unroll
            for (int i = 0; i < 4; ++i)
#pragma unroll
                for (int n = 0; n < 4; ++n) {
                    const int nt = n >> 1, s = n & 1;
                    mma_bf16(acc[i][n], af[i], bfr[nt][s], bfr[nt][s + 2]);
                }
        }
        __syncthreads();
    }

#pragma unroll
    for (int i = 0; i < 4; ++i) {
        const int r = mbase + wm * 64 + i * 16 + (lane >> 2);
#pragma unroll
        for (int n = 0; n < 4; ++n) {
            const int col = nbase + wn * 32 + n * 8 + (lane & 3) * 2;
            if (col < N) {
                if (sizeof(CT) == 4) {
                    *reinterpret_cast<float2*>((float*)C + (size_t)r * N + col) =
                        make_float2(acc[i][n][0], acc[i][n][1]);
                    *reinterpret_cast<float2*>((float*)C + (size_t)(r + 8) * N + col) =
                        make_float2(acc[i][n][2], acc[i][n][3]);
                } else {
                    __nv_bfloat162 lo = __float22bfloat162_rn(make_float2(acc[i][n][0], acc[i][n][1]));
                    __nv_bfloat162 hi = __float22bfloat162_rn(make_float2(acc[i][n][2], acc[i][n][3]));
                    *reinterpret_cast<uint32_t*>((__nv_bfloat16*)C + (size_t)r * N + col) =
                        *reinterpret_cast<uint32_t*>(&lo);
                    *reinterpret_cast<uint32_t*>((__nv_bfloat16*)C + (size_t)(r + 8) * N + col) =
                        *reinterpret_cast<uint32_t*>(&hi);
                }
            }
        }
    }
}

// ======================= lstm0 activation (f32 in, bf16 out) ================
__global__ void lstm_act(const float* __restrict__ G, const float* __restrict__ bias,
                         __nv_bfloat16* __restrict__ h)
{
    int idx = blockIdx.x * blockDim.x + threadIdx.x;
    if (idx >= 8192 * 300) return;
    int m = idx / 300, j = idx % 300;
    const float* g = G + (size_t)m * 900;
    float gi = g[j]       + bias[j];
    float gg = g[j + 300] + bias[j + 300];
    float go = g[j + 600] + bias[j + 600];
    float c  = sigmoidf_(gi) * tanhf(gg);
    h[idx]   = __float2bfloat16(sigmoidf_(go) * tanhf(c));
}

// ======================= persistent per-batch scan (512 thr) ================
// SMEM layout (bytes):
constexpr int SM_WMT = 0;        // 90000 bf16 = 180000
constexpr int SM_SP  = 180000;   // 19200 bf16 = 38400
constexpr int SM_SCR = 218400;   // 1800 f32 = 7200 (A partials; C/D gates)
constexpr int SM_WE  = 225600;   // 300 f32
constexpr int SM_HM  = 226800;   // 300 f32
constexpr int SM_AL  = 228000;   // 64 f32
constexpr int SM_HF  = 228256;   // 300 f32
constexpr int SM_TM  = 229456;   // 300 bf16 = 600
constexpr int SM_RED = 230056;   // 8 f32
constexpr int SCAN_SMEM_BYTES = 230088;

__global__ __launch_bounds__(512)
void scan_kernel(const float* __restrict__ sproj, const __nv_bfloat16* __restrict__ tproj,
                 const __nv_bfloat16* __restrict__ htpre, const __nv_bfloat16* __restrict__ hsWa,
                 const __nv_bfloat16* __restrict__ WmTg,  const float* __restrict__ w_e,
                 const float* __restrict__ biasM, const int* __restrict__ plen_a,
                 const int* __restrict__ hlen_a,  const float* __restrict__ fcw,
                 const float* __restrict__ fcb,   float* __restrict__ out)
{
    extern __shared__ char smraw[];
    __nv_bfloat16* wmt   = reinterpret_cast<__nv_bfloat16*>(smraw + SM_WMT);
    __nv_bfloat16* sp    = reinterpret_cast<__nv_bfloat16*>(smraw + SM_SP);
    float*         scr   = reinterpret_cast<float*>(smraw + SM_SCR);   // partials / gates
    float*         we_s  = reinterpret_cast<float*>(smraw + SM_WE);
    float*         hm    = reinterpret_cast<float*>(smraw + SM_HM);
    float*         alpha = reinterpret_cast<float*>(smraw + SM_AL);
    float*         hfin  = reinterpret_cast<float*>(smraw + SM_HF);
    __nv_bfloat16* tm    = reinterpret_cast<__nv_bfloat16*>(smraw + SM_TM);
    float*         red   = reinterpret_cast<float*>(smraw + SM_RED);

    const int b    = blockIdx.x;
    const int tid  = threadIdx.x;
    const int warp = tid >> 5, lane = tid & 31;

    // one-time loads
    for (int i = tid; i < 11250; i += 512)
        reinterpret_cast<uint4*>(wmt)[i] = reinterpret_cast<const uint4*>(WmTg)[i];
    const float* spg = sproj + (size_t)b * (64 * 300);
    for (int i = tid; i < 9600; i += 512) {
        float2 v = *reinterpret_cast<const float2*>(spg + 2 * i);
        __nv_bfloat162 h2 = __float22bfloat162_rn(v);
        reinterpret_cast<uint32_t*>(sp)[i] = *reinterpret_cast<uint32_t*>(&h2);
    }
    for (int i = tid; i < 300; i += 512) { we_s[i] = w_e[i]; hm[i] = 0.f; }
    const int plen = plen_a[b];
    const int hlen = hlen_a[b];
    __syncthreads();

    const __nv_bfloat16* hwg = hsWa + (size_t)b * (64 * 900);

    for (int k = 0; k < 64; ++k) {
        // Phase A: m_proj partials = hm @ Wm^T (6 segs x 75 col-quads)
        if (tid < 450) {
            const int seg = tid / 75;
            const int jq  = tid % 75;
            const int d0  = seg * 50;
            float4 acc = make_float4(0.f, 0.f, 0.f, 0.f);
#pragma unroll 2
            for (int d = d0; d < d0 + 50; ++d) {
                const float hv = hm[d];
                const uint2 w = *reinterpret_cast<const uint2*>(wmt + d * 300 + jq * 4);
                float2 w0 = bf2f2(w.x), w1 = bf2f2(w.y);
                acc.x += hv * w0.x; acc.y += hv * w0.y;
                acc.z += hv * w1.x; acc.w += hv * w1.y;
            }
            reinterpret_cast<float4*>(scr)[seg * 75 + jq] = acc;
        }
        __syncthreads();

        // reduce partials -> mp; tm = bf16(tk + mp)  (no cross-thread dep)
        if (tid < 75) {
            float4 m = make_float4(0.f, 0.f, 0.f, 0.f);
#pragma unroll
            for (int s = 0; s < 6; ++s) {
                float4 a = reinterpret_cast<float4*>(scr)[s * 75 + tid];
                m.x += a.x; m.y += a.y; m.z += a.z; m.w += a.w;
            }
            const uint32_t* tkg = reinterpret_cast<const uint32_t*>(
                tproj + ((size_t)b * 64 + k) * 300) + 2 * tid;
            float2 t0 = bf2f2(tkg[0]), t1 = bf2f2(tkg[1]);
            __nv_bfloat162 p0 = __float22bfloat162_rn(make_float2(m.x + t0.x, m.y + t0.y));
            __nv_bfloat162 p1 = __float22bfloat162_rn(make_float2(m.z + t1.x, m.w + t1.y));
            *reinterpret_cast<uint2*>(tm + 4 * tid) =
                make_uint2(*reinterpret_cast<uint32_t*>(&p0), *reinterpret_cast<uint32_t*>(&p1));
        }
        __syncthreads();

        // Phase B: e[p] = w_e . tanh(sp[p] + tm)  (packed bf16x2, MUFU tanh)
        const uint32_t* tmu = reinterpret_cast<const uint32_t*>(tm);
        for (int p = warp; p < plen; p += 16) {
            const uint32_t* srow = reinterpret_cast<const uint32_t*>(sp + p * 300);
            float acc = 0.f;
            for (int hp = lane; hp < 150; hp += 32) {
                uint32_t s2 = srow[hp], t2 = tmu[hp];
                __nv_bfloat162 x2 = __hadd2(*reinterpret_cast<__nv_bfloat162*>(&s2),
                                            *reinterpret_cast<__nv_bfloat162*>(&t2));
                uint32_t th = tanh_bf16x2(*reinterpret_cast<uint32_t*>(&x2));
                float2 tf = bf2f2(th);
                float2 w2 = *reinterpret_cast<const float2*>(we_s + 2 * hp);
                acc = fmaf(w2.x, tf.x, acc);
                acc = fmaf(w2.y, tf.y, acc);
            }
#pragma unroll
            for (int o = 16; o > 0; o >>= 1) acc += __shfl_xor_sync(0xffffffffu, acc, o);
            if (lane == 0) alpha[p] = acc;
        }
        __syncthreads();

        // masked softmax over p (warp 0)
        if (warp == 0) {
            float e0 = (lane < plen) ? alpha[lane] : -FLT_MAX;
            float e1 = (lane + 32 < plen) ? alpha[lane + 32] : -FLT_MAX;
            float mx = fmaxf(e0, e1);
#pragma unroll
            for (int o = 16; o > 0; o >>= 1) mx = fmaxf(mx, __shfl_xor_sync(0xffffffffu, mx, o));
            float x0 = (lane < plen) ? __expf(e0 - mx) : 0.f;
            float x1 = (lane + 32 < plen) ? __expf(e1 - mx) : 0.f;
            float s = x0 + x1;
#pragma unroll
            for (int o = 16; o > 0; o >>= 1) s += __shfl_xor_sync(0xffffffffu, s, o);
            float inv = 1.f / s;
            alpha[lane]      = x0 * inv;
            alpha[lane + 32] = x1 * inv;
        }
        __syncthreads();

        // Phase C: gates = sum_{p<plen} alpha[p]*hsWa[b,p,:] + htpre[b,k,:] + biasM
        if (tid < 450) {
            float2 acc = make_float2(0.f, 0.f);
            const uint32_t* hw = reinterpret_cast<const uint32_t*>(hwg) + tid;
            int p = 0;
            for (; p + 2 <= plen; p += 2) {
                const float a0 = alpha[p], a1 = alpha[p + 1];
                const uint32_t w0 = __ldcs(hw + (size_t)p * 450);
                const uint32_t w1 = __ldcs(hw + (size_t)(p + 1) * 450);
                float2 f0 = bf2f2(w0), f1 = bf2f2(w1);
                acc.x += a0 * f0.x + a1 * f1.x;
                acc.y += a0 * f0.y + a1 * f1.y;
            }
            if (p < plen) {
                const float a0 = alpha[p];
                float2 f0 = bf2f2(__ldcs(hw + (size_t)p * 450));
                acc.x += a0 * f0.x; acc.y += a0 * f0.y;
            }
            const uint32_t pr = __ldcs(reinterpret_cast<const uint32_t*>(
                htpre + ((size_t)b * 64 + k) * 900) + tid);
            float2 pf = bf2f2(pr);
            const float2 bs = *reinterpret_cast<const float2*>(biasM + 2 * tid);
            acc.x += pf.x + bs.x;
            acc.y += pf.y + bs.y;
            scr[2 * tid]     = acc.x;
            scr[2 * tid + 1] = acc.y;
        }
        __syncthreads();

        // Phase D: h_m update (accurate f32 — feeds final logits)
        if (tid < 300) {
            const int h = tid;
            float gi = scr[h];
            float gg = scr[h + 300];
            float go = scr[h + 600];
            float c  = sigmoidf_(gi) * tanhf(gg);
            float hv = sigmoidf_(go) * tanhf(c);
            hm[h] = hv;
            if (k == hlen - 1) hfin[h] = hv;
        }
        __syncthreads();
    }

    if (warp < 3) {
        float acc = 0.f;
        for (int h = lane; h < 300; h += 32) acc += hfin[h] * fcw[warp * 300 + h];
#pragma unroll
        for (int o = 16; o > 0; o >>= 1) acc += __shfl_xor_sync(0xffffffffu, acc, o);
        if (lane == 0) red[warp] = acc + fcb[warp];
    }
    __syncthreads();
    if (tid == 0) {
        float l0 = red[0], l1 = red[1], l2 = red[2];
        float mx = fmaxf(l0, fmaxf(l1, l2));
        float e0 = expf(l0 - mx), e1 = expf(l1 - mx), e2 = expf(l2 - mx);
        float inv = 1.f / (e0 + e1 + e2);
        out[b * 3 + 0] = e0 * inv;
        out[b * 3 + 1] = e1 * inv;
        out[b * 3 + 2] = e2 * inv;
    }
}

// ---------------------------------------------------------------------------
extern "C" void kernel_launch(void* const* d_in, const int* in_sizes, int n_in,
                              void* d_out, int out_size)
{
    const int*   premise = (const int*)  d_in[0];
    const int*   plen    = (const int*)  d_in[1];
    const int*   hyp     = (const int*)  d_in[2];
    const int*   hlen    = (const int*)  d_in[3];
    const float* embed   = (const float*)d_in[4];
    const float* w_e     = (const float*)d_in[5];
    const float* W_s     = (const float*)d_in[6];
    const float* W_t     = (const float*)d_in[7];
    const float* W_m     = (const float*)d_in[8];
    const float* fc_w    = (const float*)d_in[9];
    const float* fc_b    = (const float*)d_in[10];
    const float* Wih_p   = (const float*)d_in[11];
    const float* bih_p   = (const float*)d_in[13];
    const float* bhh_p   = (const float*)d_in[14];
    const float* Wih_h   = (const float*)d_in[15];
    const float* bih_h   = (const float*)d_in[17];
    const float* bhh_h   = (const float*)d_in[18];
    const float* Wih_m   = (const float*)d_in[19];
    const float* bih_m   = (const float*)d_in[21];
    const float* bhh_m   = (const float*)d_in[22];

    float* buf = nullptr;
    cudaGetSymbolAddress((void**)&buf, g_buf);
    float*          gates  = buf + OFF_GATES;
    __nv_bfloat16*  hs     = (__nv_bfloat16*)(buf + OFF_HS);
    __nv_bfloat16*  ht     = (__nv_bfloat16*)(buf + OFF_HT);
    float*          sprojp = buf + OFF_SPROJ;
    __nv_bfloat16*  tprojp = (__nv_bfloat16*)(buf + OFF_TPROJ);
    __nv_bfloat16*  htprep = (__nv_bfloat16*)(buf + OFF_HTPRE);
    __nv_bfloat16*  hsWap  = (__nv_bfloat16*)(buf + OFF_HSWA);
    __nv_bfloat16*  Wp     = (__nv_bfloat16*)(buf + OFF_WPB);
    __nv_bfloat16*  Wh     = (__nv_bfloat16*)(buf + OFF_WHB);
    __nv_bfloat16*  Wa     = (__nv_bfloat16*)(buf + OFF_WAB);
    __nv_bfloat16*  Whm    = (__nv_bfloat16*)(buf + OFF_WHMB);
    __nv_bfloat16*  Wsb    = (__nv_bfloat16*)(buf + OFF_WSB);
    __nv_bfloat16*  Wtb    = (__nv_bfloat16*)(buf + OFF_WTB);
    __nv_bfloat16*  WmT    = (__nv_bfloat16*)(buf + OFF_WMTB);
    float* bp = buf + OFF_BP;
    float* bh = buf + OFF_BH;
    float* bm = buf + OFF_BM;

    prep_all<<<(1350000 + 255) / 256, 256>>>(Wih_p, bih_p, bhh_p,
                                             Wih_h, bih_h, bhh_h,
                                             Wih_m, bih_m, bhh_m,
                                             W_m, W_s, W_t,
                                             Wp, Wh, Wa, Whm, Wsb, Wtb, WmT,
                                             bp, bh, bm);

    dim3 g900(8, 64), g300(3, 64);

    gemm_bb<float, float><<<g900, 256>>>(embed, premise, Wp, 900, gates, 900);
    lstm_act<<<9600, 256>>>(gates, bp, hs);
    gemm_bb<float, float><<<g900, 256>>>(embed, hyp, Wh, 900, gates, 900);
    lstm_act<<<9600, 256>>>(gates, bh, ht);

    gemm_bb<__nv_bfloat16, __nv_bfloat16><<<g900, 256>>>(hs, nullptr, Wa,  900, hsWap,  900);
    gemm_bb<__nv_bfloat16, __nv_bfloat16><<<g900, 256>>>(ht, nullptr, Whm, 900, htprep, 900);
    gemm_bb<__nv_bfloat16, float        ><<<g300, 256>>>(hs, nullptr, Wsb, 300, sprojp, 300);
    gemm_bb<__nv_bfloat16, __nv_bfloat16><<<g300, 256>>>(ht, nullptr, Wtb, 300, tprojp, 300);

    cudaFuncSetAttribute(scan_kernel, cudaFuncAttributeMaxDynamicSharedMemorySize,
                         SCAN_SMEM_BYTES);
    scan_kernel<<<128, 512, SCAN_SMEM_BYTES>>>(sprojp, tprojp, htprep, hsWap, WmT,
                                               w_e, bm, plen, hlen, fc_w, fc_b,
                                               (float*)d_out);
}

// round 8
// speedup vs baseline: 2.7264x; 1.2747x over previous
#include <cuda_runtime.h>
#include <cuda_bf16.h>
#include <math.h>
#include <float.h>
#include <stdint.h>

// ---------------------------------------------------------------------------
// MatchLSTM: B=128, P=K=64, E=H=300, V=50000, C=3
//  GEMMs: bf16 mma.sync.m16n8k16 + ldmatrix (portable PTX).
//  Scan: 512 thr/block, WmT in SMEM, bf16x2 MUFU-tanh attention,
//        k-loop cut at hlen (output only needs h_m[hlen-1]).
// ---------------------------------------------------------------------------

constexpr size_t OFF_GATES = 0;                        // 8192*900 f32
constexpr size_t OFF_HS    = OFF_GATES + 7372800;      // 8192*300 bf16
constexpr size_t OFF_HT    = OFF_HS    + 1228800;
constexpr size_t OFF_SPROJ = OFF_HT    + 1228800;      // 8192*300 f32
constexpr size_t OFF_TPROJ = OFF_SPROJ + 2457600;      // 8192*300 bf16
constexpr size_t OFF_HTPRE = OFF_TPROJ + 1228800;      // 8192*900 bf16
constexpr size_t OFF_HSWA  = OFF_HTPRE + 3686400;      // 8192*900 bf16
constexpr size_t OFF_WPB   = OFF_HSWA  + 3686400;      // 900*300 bf16
constexpr size_t OFF_WHB   = OFF_WPB   + 135000;
constexpr size_t OFF_WAB   = OFF_WHB   + 135000;
constexpr size_t OFF_WHMB  = OFF_WAB   + 135000;
constexpr size_t OFF_WSB   = OFF_WHMB  + 135000;       // 300*300 bf16
constexpr size_t OFF_WTB   = OFF_WSB   + 45000;
constexpr size_t OFF_WMTB  = OFF_WTB   + 45000;        // 300*300 bf16
constexpr size_t OFF_BP    = OFF_WMTB  + 45000;        // 900 f32
constexpr size_t OFF_BH    = OFF_BP + 900;
constexpr size_t OFF_BM    = OFF_BH + 900;
constexpr size_t BUF_TOTAL = OFF_BM + 900;

__device__ __align__(16) float g_buf[BUF_TOTAL];

// fast, accurate-enough (~1e-6) activation helpers (MUFU EX2 based)
__device__ __forceinline__ float fast_sigmoid(float x) {
    return __fdividef(1.f, 1.f + __expf(-x));
}
__device__ __forceinline__ float fast_tanh(float x) {
    float e = __expf(2.f * x);
    return 1.f - __fdividef(2.f, e + 1.f);
}

__device__ __forceinline__ uint32_t smem_u32(const void* p) {
    uint32_t a;
    asm("{ .reg .u64 t; cvta.to.shared.u64 t, %1; cvt.u32.u64 %0, t; }" : "=r"(a) : "l"(p));
    return a;
}
__device__ __forceinline__ void ldsm_x4(uint32_t r[4], uint32_t addr) {
    asm volatile("ldmatrix.sync.aligned.m8n8.x4.shared.b16 {%0,%1,%2,%3}, [%4];"
                 : "=r"(r[0]), "=r"(r[1]), "=r"(r[2]), "=r"(r[3]) : "r"(addr));
}
__device__ __forceinline__ void mma_bf16(float c[4], const uint32_t a[4],
                                         uint32_t b0, uint32_t b1) {
    asm volatile(
        "mma.sync.aligned.m16n8k16.row.col.f32.bf16.bf16.f32 "
        "{%0,%1,%2,%3}, {%4,%5,%6,%7}, {%8,%9}, {%0,%1,%2,%3};"
        : "+f"(c[0]), "+f"(c[1]), "+f"(c[2]), "+f"(c[3])
        : "r"(a[0]), "r"(a[1]), "r"(a[2]), "r"(a[3]), "r"(b0), "r"(b1));
}
__device__ __forceinline__ float2 bf2f2(uint32_t u) {
    __nv_bfloat162 h = *reinterpret_cast<__nv_bfloat162*>(&u);
    return __bfloat1622float2(h);
}
__device__ __forceinline__ uint32_t tanh_bf16x2(uint32_t x) {
    uint32_t d;
    asm("tanh.approx.bf16x2 %0, %1;" : "=r"(d) : "r"(x));
    return d;
}

// ======================= fused prep (1 launch) ==============================
__global__ void prep_all(const float* __restrict__ Wih_p, const float* __restrict__ bih_p,
                         const float* __restrict__ bhh_p,
                         const float* __restrict__ Wih_h, const float* __restrict__ bih_h,
                         const float* __restrict__ bhh_h,
                         const float* __restrict__ Wih_m, const float* __restrict__ bih_m,
                         const float* __restrict__ bhh_m,
                         const float* __restrict__ Wm,
                         const float* __restrict__ Ws, const float* __restrict__ Wt,
                         __nv_bfloat16* __restrict__ Wp, __nv_bfloat16* __restrict__ Wh,
                         __nv_bfloat16* __restrict__ Wa, __nv_bfloat16* __restrict__ Whm,
                         __nv_bfloat16* __restrict__ Wsb, __nv_bfloat16* __restrict__ Wtb,
                         __nv_bfloat16* __restrict__ WmT,
                         float* __restrict__ bp, float* __restrict__ bh,
                         float* __restrict__ bm)
{
    int idx = blockIdx.x * blockDim.x + threadIdx.x;
    if (idx < 270000) {
        int j = idx / 300, k2 = idx % 300;
        int src = (j < 300) ? j : j + 300;
        Wp[idx] = __float2bfloat16(Wih_p[(size_t)src * 300 + k2]);
    } else if (idx < 540000) {
        int t = idx - 270000; int j = t / 300, k2 = t % 300;
        int src = (j < 300) ? j : j + 300;
        Wh[t] = __float2bfloat16(Wih_h[(size_t)src * 300 + k2]);
    } else if (idx < 810000) {
        int t = idx - 540000; int j = t / 300, k2 = t % 300;
        int src = (j < 300) ? j : j + 300;
        Wa[t] = __float2bfloat16(Wih_m[(size_t)src * 600 + k2]);
    } else if (idx < 1080000) {
        int t = idx - 810000; int j = t / 300, k2 = t % 300;
        int src = (j < 300) ? j : j + 300;
        Whm[t] = __float2bfloat16(Wih_m[(size_t)src * 600 + 300 + k2]);
    } else if (idx < 1170000) {
        int t = idx - 1080000;
        Wsb[t] = __float2bfloat16(Ws[t]);
    } else if (idx < 1260000) {
        int t = idx - 1170000;
        Wtb[t] = __float2bfloat16(Wt[t]);
    } else if (idx < 1350000) {
        int t = idx - 1260000; int d = t / 300, j = t % 300;
        WmT[t] = __float2bfloat16(Wm[(size_t)j * 300 + d]);
    }
    if (idx < 900) {
        int src = (idx < 300) ? idx : idx + 300;
        bp[idx] = bih_p[src] + bhh_p[src];
        bh[idx] = bih_h[src] + bhh_h[src];
        bm[idx] = bih_m[src] + bhh_m[src];
    }
}

// ======================= bf16 tensor-core GEMM ==============================
constexpr int GLDK = 40;

template <typename AT, typename CT>
__global__ __launch_bounds__(256)
void gemm_bb(const AT* __restrict__ A, const int* __restrict__ tok,
             const __nv_bfloat16* __restrict__ B, int Brows,
             CT* __restrict__ C, int N)
{
    constexpr bool AF32 = (sizeof(AT) == 4);
    __shared__ __nv_bfloat16 As[128 * GLDK];
    __shared__ __nv_bfloat16 Bs[128 * GLDK];

    const int tid = threadIdx.x;
    const int warp = tid >> 5, lane = tid & 31;
    const int wm = warp >> 2, wn = warp & 3;
    const int mbase = blockIdx.y * 128;
    const int nbase = blockIdx.x * 128;

    int arow_s[4], asrc[4], ac4[4];
    bool bok[4];
#pragma unroll
    for (int p = 0; p < 4; ++p) {
        const int f4 = tid + 256 * p;
        const int row = f4 >> 3;
        arow_s[p] = row;
        ac4[p]    = f4 & 7;
        const int gm = mbase + row;
        asrc[p] = tok ? tok[gm] : gm;
        bok[p]  = (nbase + row) < Brows;
    }

    float acc[4][4][4];
#pragma unroll
    for (int i = 0; i < 4; i++)
#pragma unroll
        for (int n = 0; n < 4; n++)
#pragma unroll
            for (int e = 0; e < 4; e++) acc[i][n][e] = 0.f;

    const uint32_t aB = smem_u32(As), bB = smem_u32(Bs);
    const int lrow = lane & 15;
    const int lkof = (lane >> 4) << 3;

    float4 vaf[4];
    uint2  vab[4], vbb[4];

    auto load_chunk = [&](int k0) {
#pragma unroll
        for (int p = 0; p < 4; ++p) {
            const int kk = k0 + ac4[p] * 4;
            const bool kv = (kk < 300);
            if (AF32) {
                vaf[p] = kv ? *reinterpret_cast<const float4*>((const float*)A + (size_t)asrc[p] * 300 + kk)
                            : make_float4(0.f, 0.f, 0.f, 0.f);
            } else {
                vab[p] = kv ? *reinterpret_cast<const uint2*>((const __nv_bfloat16*)A + (size_t)asrc[p] * 300 + kk)
                            : make_uint2(0u, 0u);
            }
            vbb[p] = (kv && bok[p])
                ? *reinterpret_cast<const uint2*>(B + (size_t)(nbase + arow_s[p]) * 300 + kk)
                : make_uint2(0u, 0u);
        }
    };
    auto store_chunk = [&]() {
#pragma unroll
        for (int p = 0; p < 4; ++p) {
            const int off = arow_s[p] * GLDK + ac4[p] * 4;
            if (AF32) {
                __nv_bfloat162 alo = __float22bfloat162_rn(make_float2(vaf[p].x, vaf[p].y));
                __nv_bfloat162 ahi = __float22bfloat162_rn(make_float2(vaf[p].z, vaf[p].w));
                *reinterpret_cast<uint2*>(&As[off]) =
                    make_uint2(*reinterpret_cast<uint32_t*>(&alo), *reinterpret_cast<uint32_t*>(&ahi));
            } else {
                *reinterpret_cast<uint2*>(&As[off]) = vab[p];
            }
            *reinterpret_cast<uint2*>(&Bs[off]) = vbb[p];
        }
    };

    load_chunk(0);
#pragma unroll 1
    for (int c = 0; c < 10; ++c) {
        store_chunk();
        __syncthreads();
        if (c < 9) load_chunk((c + 1) * 32);

#pragma unroll
        for (int j = 0; j < 2; ++j) {
            const int kcol = j * 16 + lkof;
            uint32_t af[4][4], bfr[2][4];
#pragma unroll
            for (int i = 0; i < 4; ++i)
                ldsm_x4(af[i], aB + (uint32_t)(((wm * 64 + i * 16 + lrow) * GLDK + kcol) * 2));
#pragma unroll
            for (int nt = 0; nt < 2; ++nt)
                ldsm_x4(bfr[nt], bB + (uint32_t)(((wn * 32 + nt * 16 + lrow) * GLDK + kcol) * 2));
#pragma unroll
            for (int i = 0; i < 4; ++i)
#pragma unroll
                for (int n = 0; n < 4; ++n) {
                    const int nt = n >> 1, s = n & 1;
                    mma_bf16(acc[i][n], af[i], bfr[nt][s], bfr[nt][s + 2]);
                }
        }
        __syncthreads();
    }

#pragma unroll
    for (int i = 0; i < 4; ++i) {
        const int r = mbase + wm * 64 + i * 16 + (lane >> 2);
#pragma unroll
        for (int n = 0; n < 4; ++n) {
            const int col = nbase + wn * 32 + n * 8 + (lane & 3) * 2;
            if (col < N) {
                if (sizeof(CT) == 4) {
                    *reinterpret_cast<float2*>((float*)C + (size_t)r * N + col) =
                        make_float2(acc[i][n][0], acc[i][n][1]);
                    *reinterpret_cast<float2*>((float*)C + (size_t)(r + 8) * N + col) =
                        make_float2(acc[i][n][2], acc[i][n][3]);
                } else {
                    __nv_bfloat162 lo = __float22bfloat162_rn(make_float2(acc[i][n][0], acc[i][n][1]));
                    __nv_bfloat162 hi = __float22bfloat162_rn(make_float2(acc[i][n][2], acc[i][n][3]));
                    *reinterpret_cast<uint32_t*>((__nv_bfloat16*)C + (size_t)r * N + col) =
                        *reinterpret_cast<uint32_t*>(&lo);
                    *reinterpret_cast<uint32_t*>((__nv_bfloat16*)C + (size_t)(r + 8) * N + col) =
                        *reinterpret_cast<uint32_t*>(&hi);
                }
            }
        }
    }
}

// ======================= lstm0 activation (f32 in, bf16 out) ================
__global__ void lstm_act(const float* __restrict__ G, const float* __restrict__ bias,
                         __nv_bfloat16* __restrict__ h)
{
    int idx = blockIdx.x * blockDim.x + threadIdx.x;
    if (idx >= 8192 * 300) return;
    int m = idx / 300, j = idx % 300;
    const float* g = G + (size_t)m * 900;
    float gi = g[j]       + bias[j];
    float gg = g[j + 300] + bias[j + 300];
    float go = g[j + 600] + bias[j + 600];
    float c  = fast_sigmoid(gi) * fast_tanh(gg);
    h[idx]   = __float2bfloat16(fast_sigmoid(go) * fast_tanh(c));
}

// ======================= persistent per-batch scan (512 thr) ================
constexpr int SM_WMT = 0;        // 90000 bf16 = 180000
constexpr int SM_SP  = 180000;   // 19200 bf16 = 38400
constexpr int SM_SCR = 218400;   // 1800 f32 = 7200 (A partials; C gates)
constexpr int SM_WE  = 225600;   // 300 f32
constexpr int SM_HM  = 226800;   // 300 f32
constexpr int SM_AL  = 228000;   // 64 f32
constexpr int SM_HF  = 228256;   // 300 f32
constexpr int SM_TM  = 229456;   // 300 bf16 = 600
constexpr int SM_RED = 230056;   // 8 f32
constexpr int SCAN_SMEM_BYTES = 230088;

__global__ __launch_bounds__(512)
void scan_kernel(const float* __restrict__ sproj, const __nv_bfloat16* __restrict__ tproj,
                 const __nv_bfloat16* __restrict__ htpre, const __nv_bfloat16* __restrict__ hsWa,
                 const __nv_bfloat16* __restrict__ WmTg,  const float* __restrict__ w_e,
                 const float* __restrict__ biasM, const int* __restrict__ plen_a,
                 const int* __restrict__ hlen_a,  const float* __restrict__ fcw,
                 const float* __restrict__ fcb,   float* __restrict__ out)
{
    extern __shared__ char smraw[];
    __nv_bfloat16* wmt   = reinterpret_cast<__nv_bfloat16*>(smraw + SM_WMT);
    __nv_bfloat16* sp    = reinterpret_cast<__nv_bfloat16*>(smraw + SM_SP);
    float*         scr   = reinterpret_cast<float*>(smraw + SM_SCR);
    float*         we_s  = reinterpret_cast<float*>(smraw + SM_WE);
    float*         hm    = reinterpret_cast<float*>(smraw + SM_HM);
    float*         alpha = reinterpret_cast<float*>(smraw + SM_AL);
    float*         hfin  = reinterpret_cast<float*>(smraw + SM_HF);
    __nv_bfloat16* tm    = reinterpret_cast<__nv_bfloat16*>(smraw + SM_TM);
    float*         red   = reinterpret_cast<float*>(smraw + SM_RED);

    const int b    = blockIdx.x;
    const int tid  = threadIdx.x;
    const int warp = tid >> 5, lane = tid & 31;

    for (int i = tid; i < 11250; i += 512)
        reinterpret_cast<uint4*>(wmt)[i] = reinterpret_cast<const uint4*>(WmTg)[i];
    const float* spg = sproj + (size_t)b * (64 * 300);
    for (int i = tid; i < 9600; i += 512) {
        float2 v = *reinterpret_cast<const float2*>(spg + 2 * i);
        __nv_bfloat162 h2 = __float22bfloat162_rn(v);
        reinterpret_cast<uint32_t*>(sp)[i] = *reinterpret_cast<uint32_t*>(&h2);
    }
    for (int i = tid; i < 300; i += 512) { we_s[i] = w_e[i]; hm[i] = 0.f; }
    const int plen = plen_a[b];
    const int hlen = hlen_a[b];     // output only needs h_m at step hlen-1
    __syncthreads();

    const __nv_bfloat16* hwg = hsWa + (size_t)b * (64 * 900);

    for (int k = 0; k < hlen; ++k) {
        // Phase A: m_proj partials = hm @ Wm^T (6 segs x 75 col-quads)
        if (tid < 450) {
            const int seg = tid / 75;
            const int jq  = tid % 75;
            const int d0  = seg * 50;
            float4 acc = make_float4(0.f, 0.f, 0.f, 0.f);
#pragma unroll 2
            for (int d = d0; d < d0 + 50; ++d) {
                const float hv = hm[d];
                const uint2 w = *reinterpret_cast<const uint2*>(wmt + d * 300 + jq * 4);
                float2 w0 = bf2f2(w.x), w1 = bf2f2(w.y);
                acc.x += hv * w0.x; acc.y += hv * w0.y;
                acc.z += hv * w1.x; acc.w += hv * w1.y;
            }
            reinterpret_cast<float4*>(scr)[seg * 75 + jq] = acc;
        }
        __syncthreads();

        // reduce partials -> mp; tm = bf16(tk + mp)
        if (tid < 75) {
            float4 m = make_float4(0.f, 0.f, 0.f, 0.f);
#pragma unroll
            for (int s = 0; s < 6; ++s) {
                float4 a = reinterpret_cast<float4*>(scr)[s * 75 + tid];
                m.x += a.x; m.y += a.y; m.z += a.z; m.w += a.w;
            }
            const uint32_t* tkg = reinterpret_cast<const uint32_t*>(
                tproj + ((size_t)b * 64 + k) * 300) + 2 * tid;
            float2 t0 = bf2f2(tkg[0]), t1 = bf2f2(tkg[1]);
            __nv_bfloat162 p0 = __float22bfloat162_rn(make_float2(m.x + t0.x, m.y + t0.y));
            __nv_bfloat162 p1 = __float22bfloat162_rn(make_float2(m.z + t1.x, m.w + t1.y));
            *reinterpret_cast<uint2*>(tm + 4 * tid) =
                make_uint2(*reinterpret_cast<uint32_t*>(&p0), *reinterpret_cast<uint32_t*>(&p1));
        }
        __syncthreads();

        // Phase B: e[p] = w_e . tanh(sp[p] + tm)  (packed bf16x2, MUFU tanh)
        const uint32_t* tmu = reinterpret_cast<const uint32_t*>(tm);
        for (int p = warp; p < plen; p += 16) {
            const uint32_t* srow = reinterpret_cast<const uint32_t*>(sp + p * 300);
            float acc = 0.f;
            for (int hp = lane; hp < 150; hp += 32) {
                uint32_t s2 = srow[hp], t2 = tmu[hp];
                __nv_bfloat162 x2 = __hadd2(*reinterpret_cast<__nv_bfloat162*>(&s2),
                                            *reinterpret_cast<__nv_bfloat162*>(&t2));
                uint32_t th = tanh_bf16x2(*reinterpret_cast<uint32_t*>(&x2));
                float2 tf = bf2f2(th);
                float2 w2 = *reinterpret_cast<const float2*>(we_s + 2 * hp);
                acc = fmaf(w2.x, tf.x, acc);
                acc = fmaf(w2.y, tf.y, acc);
            }
#pragma unroll
            for (int o = 16; o > 0; o >>= 1) acc += __shfl_xor_sync(0xffffffffu, acc, o);
            if (lane == 0) alpha[p] = acc;
        }
        __syncthreads();

        // masked softmax over p (warp 0); writes exact zeros for p >= plen
        if (warp == 0) {
            float e0 = (lane < plen) ? alpha[lane] : -FLT_MAX;
            float e1 = (lane + 32 < plen) ? alpha[lane + 32] : -FLT_MAX;
            float mx = fmaxf(e0, e1);
#pragma unroll
            for (int o = 16; o > 0; o >>= 1) mx = fmaxf(mx, __shfl_xor_sync(0xffffffffu, mx, o));
            float x0 = (lane < plen) ? __expf(e0 - mx) : 0.f;
            float x1 = (lane + 32 < plen) ? __expf(e1 - mx) : 0.f;
            float s = x0 + x1;
#pragma unroll
            for (int o = 16; o > 0; o >>= 1) s += __shfl_xor_sync(0xffffffffu, s, o);
            float inv = 1.f / s;
            alpha[lane]      = x0 * inv;
            alpha[lane + 32] = x1 * inv;
        }
        __syncthreads();

        // Phase C: gates = sum_p alpha[p]*hsWa[b,p,:] + htpre[b,k,:] + biasM
        // alpha is exactly 0 for p >= plen, so loop to plen rounded up to 4.
        if (tid < 450) {
            const int plen4 = (plen + 3) & ~3;
            float2 acc = make_float2(0.f, 0.f);
            const uint32_t* hw = reinterpret_cast<const uint32_t*>(hwg) + tid;
            for (int p = 0; p < plen4; p += 4) {
                const float a0 = alpha[p],     a1 = alpha[p + 1];
                const float a2 = alpha[p + 2], a3 = alpha[p + 3];
                const uint32_t w0 = __ldcs(hw + (size_t)p * 450);
                const uint32_t w1 = __ldcs(hw + (size_t)(p + 1) * 450);
                const uint32_t w2 = __ldcs(hw + (size_t)(p + 2) * 450);
                const uint32_t w3 = __ldcs(hw + (size_t)(p + 3) * 450);
                float2 f0 = bf2f2(w0), f1 = bf2f2(w1), f2 = bf2f2(w2), f3 = bf2f2(w3);
                acc.x += a0 * f0.x + a1 * f1.x + a2 * f2.x + a3 * f3.x;
                acc.y += a0 * f0.y + a1 * f1.y + a2 * f2.y + a3 * f3.y;
            }
            const uint32_t pr = __ldcs(reinterpret_cast<const uint32_t*>(
                htpre + ((size_t)b * 64 + k) * 900) + tid);
            float2 pf = bf2f2(pr);
            const float2 bs = *reinterpret_cast<const float2*>(biasM + 2 * tid);
            acc.x += pf.x + bs.x;
            acc.y += pf.y + bs.y;
            scr[2 * tid]     = acc.x;
            scr[2 * tid + 1] = acc.y;
        }
        __syncthreads();

        // Phase D: h_m update (fast-math f32, ~1e-6 accurate)
        if (tid < 300) {
            const int h = tid;
            float gi = scr[h];
            float gg = scr[h + 300];
            float go = scr[h + 600];
            float c  = fast_sigmoid(gi) * fast_tanh(gg);
            float hv = fast_sigmoid(go) * fast_tanh(c);
            hm[h] = hv;
            if (k == hlen - 1) hfin[h] = hv;
        }
        __syncthreads();
    }

    if (warp < 3) {
        float acc = 0.f;
        for (int h = lane; h < 300; h += 32) acc += hfin[h] * fcw[warp * 300 + h];
#pragma unroll
        for (int o = 16; o > 0; o >>= 1) acc += __shfl_xor_sync(0xffffffffu, acc, o);
        if (lane == 0) red[warp] = acc + fcb[warp];
    }
    __syncthreads();
    if (tid == 0) {
        float l0 = red[0], l1 = red[1], l2 = red[2];
        float mx = fmaxf(l0, fmaxf(l1, l2));
        float e0 = expf(l0 - mx), e1 = expf(l1 - mx), e2 = expf(l2 - mx);
        float inv = 1.f / (e0 + e1 + e2);
        out[b * 3 + 0] = e0 * inv;
        out[b * 3 + 1] = e1 * inv;
        out[b * 3 + 2] = e2 * inv;
    }
}

// ---------------------------------------------------------------------------
extern "C" void kernel_launch(void* const* d_in, const int* in_sizes, int n_in,
                              void* d_out, int out_size)
{
    const int*   premise = (const int*)  d_in[0];
    const int*   plen    = (const int*)  d_in[1];
    const int*   hyp     = (const int*)  d_in[2];
    const int*   hlen    = (const int*)  d_in[3];
    const float* embed   = (const float*)d_in[4];
    const float* w_e     = (const float*)d_in[5];
    const float* W_s     = (const float*)d_in[6];
    const float* W_t     = (const float*)d_in[7];
    const float* W_m     = (const float*)d_in[8];
    const float* fc_w    = (const float*)d_in[9];
    const float* fc_b    = (const float*)d_in[10];
    const float* Wih_p   = (const float*)d_in[11];
    const float* bih_p   = (const float*)d_in[13];
    const float* bhh_p   = (const float*)d_in[14];
    const float* Wih_h   = (const float*)d_in[15];
    const float* bih_h   = (const float*)d_in[17];
    const float* bhh_h   = (const float*)d_in[18];
    const float* Wih_m   = (const float*)d_in[19];
    const float* bih_m   = (const float*)d_in[21];
    const float* bhh_m   = (const float*)d_in[22];

    float* buf = nullptr;
    cudaGetSymbolAddress((void**)&buf, g_buf);
    float*          gates  = buf + OFF_GATES;
    __nv_bfloat16*  hs     = (__nv_bfloat16*)(buf + OFF_HS);
    __nv_bfloat16*  ht     = (__nv_bfloat16*)(buf + OFF_HT);
    float*          sprojp = buf + OFF_SPROJ;
    __nv_bfloat16*  tprojp = (__nv_bfloat16*)(buf + OFF_TPROJ);
    __nv_bfloat16*  htprep = (__nv_bfloat16*)(buf + OFF_HTPRE);
    __nv_bfloat16*  hsWap  = (__nv_bfloat16*)(buf + OFF_HSWA);
    __nv_bfloat16*  Wp     = (__nv_bfloat16*)(buf + OFF_WPB);
    __nv_bfloat16*  Wh     = (__nv_bfloat16*)(buf + OFF_WHB);
    __nv_bfloat16*  Wa     = (__nv_bfloat16*)(buf + OFF_WAB);
    __nv_bfloat16*  Whm    = (__nv_bfloat16*)(buf + OFF_WHMB);
    __nv_bfloat16*  Wsb    = (__nv_bfloat16*)(buf + OFF_WSB);
    __nv_bfloat16*  Wtb    = (__nv_bfloat16*)(buf + OFF_WTB);
    __nv_bfloat16*  WmT    = (__nv_bfloat16*)(buf + OFF_WMTB);
    float* bp = buf + OFF_BP;
    float* bh = buf + OFF_BH;
    float* bm = buf + OFF_BM;

    prep_all<<<(1350000 + 255) / 256, 256>>>(Wih_p, bih_p, bhh_p,
                                             Wih_h, bih_h, bhh_h,
                                             Wih_m, bih_m, bhh_m,
                                             W_m, W_s, W_t,
                                             Wp, Wh, Wa, Whm, Wsb, Wtb, WmT,
                                             bp, bh, bm);

    dim3 g900(8, 64), g300(3, 64);

    gemm_bb<float, float><<<g900, 256>>>(embed, premise, Wp, 900, gates, 900);
    lstm_act<<<9600, 256>>>(gates, bp, hs);
    gemm_bb<float, float><<<g900, 256>>>(embed, hyp, Wh, 900, gates, 900);
    lstm_act<<<9600, 256>>>(gates, bh, ht);

    gemm_bb<__nv_bfloat16, __nv_bfloat16><<<g900, 256>>>(hs, nullptr, Wa,  900, hsWap,  900);
    gemm_bb<__nv_bfloat16, __nv_bfloat16><<<g900, 256>>>(ht, nullptr, Whm, 900, htprep, 900);
    gemm_bb<__nv_bfloat16, float        ><<<g300, 256>>>(hs, nullptr, Wsb, 300, sprojp, 300);
    gemm_bb<__nv_bfloat16, __nv_bfloat16><<<g300, 256>>>(ht, nullptr, Wtb, 300, tprojp, 300);

    cudaFuncSetAttribute(scan_kernel, cudaFuncAttributeMaxDynamicSharedMemorySize,
                         SCAN_SMEM_BYTES);
    scan_kernel<<<128, 512, SCAN_SMEM_BYTES>>>(sprojp, tprojp, htprep, hsWap, WmT,
                                               w_e, bm, plen, hlen, fc_w, fc_b,
                                               (float*)d_out);
}

// round 9
// speedup vs baseline: 3.4861x; 1.2786x over previous
#include <cuda_runtime.h>
#include <cuda_bf16.h>
#include <math.h>
#include <float.h>
#include <stdint.h>

// ---------------------------------------------------------------------------
// MatchLSTM: B=128, P=K=64, E=H=300, V=50000, C=3
//  GEMMs: bf16 mma.sync.m16n8k16 + ldmatrix, double-buffered SMEM, fused bias.
//  Scan: 512 thr/block, WmT in SMEM, hsWa register-prefetch across phases.
// ---------------------------------------------------------------------------

// offsets in f32 units
constexpr size_t OFF_GATES1 = 0;                        // 8192*900 f32
constexpr size_t OFF_GATES2 = OFF_GATES1 + 7372800;     // 8192*900 f32
constexpr size_t OFF_HS     = OFF_GATES2 + 7372800;     // 8192*300 bf16
constexpr size_t OFF_HT     = OFF_HS     + 1228800;
constexpr size_t OFF_SPROJ  = OFF_HT     + 1228800;     // 8192*300 bf16
constexpr size_t OFF_TPROJ  = OFF_SPROJ  + 1228800;     // 8192*300 bf16
constexpr size_t OFF_HTPRE  = OFF_TPROJ  + 1228800;     // 8192*900 bf16 (+biasM)
constexpr size_t OFF_HSWA   = OFF_HTPRE  + 3686400;     // 8192*900 bf16
constexpr size_t OFF_WPB    = OFF_HSWA   + 3686400;     // 900*300 bf16
constexpr size_t OFF_WHB    = OFF_WPB    + 135000;
constexpr size_t OFF_WAB    = OFF_WHB    + 135000;
constexpr size_t OFF_WHMB   = OFF_WAB    + 135000;
constexpr size_t OFF_WSB    = OFF_WHMB   + 135000;      // 300*300 bf16
constexpr size_t OFF_WTB    = OFF_WSB    + 45000;
constexpr size_t OFF_WMTB   = OFF_WTB    + 45000;       // 300*300 bf16
constexpr size_t OFF_BP     = OFF_WMTB   + 45000;       // 900 f32
constexpr size_t OFF_BH     = OFF_BP + 900;
constexpr size_t OFF_BM     = OFF_BH + 900;
constexpr size_t BUF_TOTAL  = OFF_BM + 900;

__device__ __align__(16) float g_buf[BUF_TOTAL];

__device__ __forceinline__ float fast_sigmoid(float x) {
    return __fdividef(1.f, 1.f + __expf(-x));
}
__device__ __forceinline__ float fast_tanh(float x) {
    float e = __expf(2.f * x);
    return 1.f - __fdividef(2.f, e + 1.f);
}
__device__ __forceinline__ float tanh_apx(float x) {
    float y; asm("tanh.approx.f32 %0, %1;" : "=f"(y) : "f"(x)); return y;
}
__device__ __forceinline__ float sig_apx(float x) {
    return fmaf(0.5f, tanh_apx(0.5f * x), 0.5f);
}

__device__ __forceinline__ uint32_t smem_u32(const void* p) {
    uint32_t a;
    asm("{ .reg .u64 t; cvta.to.shared.u64 t, %1; cvt.u32.u64 %0, t; }" : "=r"(a) : "l"(p));
    return a;
}
__device__ __forceinline__ void ldsm_x4(uint32_t r[4], uint32_t addr) {
    asm volatile("ldmatrix.sync.aligned.m8n8.x4.shared.b16 {%0,%1,%2,%3}, [%4];"
                 : "=r"(r[0]), "=r"(r[1]), "=r"(r[2]), "=r"(r[3]) : "r"(addr));
}
__device__ __forceinline__ void mma_bf16(float c[4], const uint32_t a[4],
                                         uint32_t b0, uint32_t b1) {
    asm volatile(
        "mma.sync.aligned.m16n8k16.row.col.f32.bf16.bf16.f32 "
        "{%0,%1,%2,%3}, {%4,%5,%6,%7}, {%8,%9}, {%0,%1,%2,%3};"
        : "+f"(c[0]), "+f"(c[1]), "+f"(c[2]), "+f"(c[3])
        : "r"(a[0]), "r"(a[1]), "r"(a[2]), "r"(a[3]), "r"(b0), "r"(b1));
}
__device__ __forceinline__ float2 bf2f2(uint32_t u) {
    __nv_bfloat162 h = *reinterpret_cast<__nv_bfloat162*>(&u);
    return __bfloat1622float2(h);
}
__device__ __forceinline__ uint32_t tanh_bf16x2(uint32_t x) {
    uint32_t d;
    asm("tanh.approx.bf16x2 %0, %1;" : "=r"(d) : "r"(x));
    return d;
}

// ======================= fused prep (1 launch) ==============================
__global__ void prep_all(const float* __restrict__ Wih_p, const float* __restrict__ bih_p,
                         const float* __restrict__ bhh_p,
                         const float* __restrict__ Wih_h, const float* __restrict__ bih_h,
                         const float* __restrict__ bhh_h,
                         const float* __restrict__ Wih_m, const float* __restrict__ bih_m,
                         const float* __restrict__ bhh_m,
                         const float* __restrict__ Wm,
                         const float* __restrict__ Ws, const float* __restrict__ Wt,
                         __nv_bfloat16* __restrict__ Wp, __nv_bfloat16* __restrict__ Wh,
                         __nv_bfloat16* __restrict__ Wa, __nv_bfloat16* __restrict__ Whm,
                         __nv_bfloat16* __restrict__ Wsb, __nv_bfloat16* __restrict__ Wtb,
                         __nv_bfloat16* __restrict__ WmT,
                         float* __restrict__ bp, float* __restrict__ bh,
                         float* __restrict__ bm)
{
    int idx = blockIdx.x * blockDim.x + threadIdx.x;
    if (idx < 270000) {
        int j = idx / 300, k2 = idx % 300;
        int src = (j < 300) ? j : j + 300;
        Wp[idx] = __float2bfloat16(Wih_p[(size_t)src * 300 + k2]);
    } else if (idx < 540000) {
        int t = idx - 270000; int j = t / 300, k2 = t % 300;
        int src = (j < 300) ? j : j + 300;
        Wh[t] = __float2bfloat16(Wih_h[(size_t)src * 300 + k2]);
    } else if (idx < 810000) {
        int t = idx - 540000; int j = t / 300, k2 = t % 300;
        int src = (j < 300) ? j : j + 300;
        Wa[t] = __float2bfloat16(Wih_m[(size_t)src * 600 + k2]);
    } else if (idx < 1080000) {
        int t = idx - 810000; int j = t / 300, k2 = t % 300;
        int src = (j < 300) ? j : j + 300;
        Whm[t] = __float2bfloat16(Wih_m[(size_t)src * 600 + 300 + k2]);
    } else if (idx < 1170000) {
        int t = idx - 1080000;
        Wsb[t] = __float2bfloat16(Ws[t]);
    } else if (idx < 1260000) {
        int t = idx - 1170000;
        Wtb[t] = __float2bfloat16(Wt[t]);
    } else if (idx < 1350000) {
        int t = idx - 1260000; int d = t / 300, j = t % 300;
        WmT[t] = __float2bfloat16(Wm[(size_t)j * 300 + d]);
    }
    if (idx < 900) {
        int src = (idx < 300) ? idx : idx + 300;
        bp[idx] = bih_p[src] + bhh_p[src];
        bh[idx] = bih_h[src] + bhh_h[src];
        bm[idx] = bih_m[src] + bhh_m[src];
    }
}

// ======================= bf16 tensor-core GEMM core =========================
// C[128 tile, N] = A @ B^T + bias, double-buffered SMEM (1 sync / K-chunk).
constexpr int GLDK = 40;
constexpr int GBUF = 128 * GLDK;   // 5120 bf16 per buffer

template <typename AT, typename CT>
__device__ __forceinline__ void gemm_core(
    const AT* __restrict__ A, const int* __restrict__ tok,
    const __nv_bfloat16* __restrict__ B, int Brows,
    CT* __restrict__ C, int N, const float* __restrict__ bias,
    __nv_bfloat16* __restrict__ sm, int mbase, int nbase)
{
    constexpr bool AF32 = (sizeof(AT) == 4);
    const int tid = threadIdx.x;
    const int warp = tid >> 5, lane = tid & 31;
    const int wm = warp >> 2, wn = warp & 3;

    const uint32_t aB[2] = { smem_u32(sm),            smem_u32(sm + GBUF) };
    const uint32_t bB[2] = { smem_u32(sm + 2 * GBUF), smem_u32(sm + 3 * GBUF) };

    int arow_s[4], asrc[4], ac4[4];
    bool bok[4];
#pragma unroll
    for (int p = 0; p < 4; ++p) {
        const int f4 = tid + 256 * p;
        const int row = f4 >> 3;
        arow_s[p] = row;
        ac4[p]    = f4 & 7;
        const int gm = mbase + row;
        asrc[p] = tok ? tok[gm] : gm;
        bok[p]  = (nbase + row) < Brows;
    }

    float acc[4][4][4];
#pragma unroll
    for (int i = 0; i < 4; i++)
#pragma unroll
        for (int n = 0; n < 4; n++)
#pragma unroll
            for (int e = 0; e < 4; e++) acc[i][n][e] = 0.f;

    const int lrow = lane & 15;
    const int lkof = (lane >> 4) << 3;

    float4 vaf[4];
    uint2  vab[4], vbb[4];

    auto load_chunk = [&](int k0) {
#pragma unroll
        for (int p = 0; p < 4; ++p) {
            const int kk = k0 + ac4[p] * 4;
            const bool kv = (kk < 300);
            if (AF32) {
                vaf[p] = kv ? *reinterpret_cast<const float4*>((const float*)A + (size_t)asrc[p] * 300 + kk)
                            : make_float4(0.f, 0.f, 0.f, 0.f);
            } else {
                vab[p] = kv ? *reinterpret_cast<const uint2*>((const __nv_bfloat16*)A + (size_t)asrc[p] * 300 + kk)
                            : make_uint2(0u, 0u);
            }
            vbb[p] = (kv && bok[p])
                ? *reinterpret_cast<const uint2*>(B + (size_t)(nbase + arow_s[p]) * 300 + kk)
                : make_uint2(0u, 0u);
        }
    };
    auto store_chunk = [&](int buf) {
        __nv_bfloat16* Asb = sm + buf * GBUF;
        __nv_bfloat16* Bsb = sm + (2 + buf) * GBUF;
#pragma unroll
        for (int p = 0; p < 4; ++p) {
            const int off = arow_s[p] * GLDK + ac4[p] * 4;
            if (AF32) {
                __nv_bfloat162 alo = __float22bfloat162_rn(make_float2(vaf[p].x, vaf[p].y));
                __nv_bfloat162 ahi = __float22bfloat162_rn(make_float2(vaf[p].z, vaf[p].w));
                *reinterpret_cast<uint2*>(&Asb[off]) =
                    make_uint2(*reinterpret_cast<uint32_t*>(&alo), *reinterpret_cast<uint32_t*>(&ahi));
            } else {
                *reinterpret_cast<uint2*>(&Asb[off]) = vab[p];
            }
            *reinterpret_cast<uint2*>(&Bsb[off]) = vbb[p];
        }
    };

    load_chunk(0);
    store_chunk(0);
    __syncthreads();

#pragma unroll 1
    for (int c = 0; c < 10; ++c) {
        if (c < 9) load_chunk((c + 1) * 32);
        const uint32_t a0 = aB[c & 1], b0 = bB[c & 1];
#pragma unroll
        for (int j = 0; j < 2; ++j) {
            const int kcol = j * 16 + lkof;
            uint32_t af[4][4], bfr[2][4];
#pragma unroll
            for (int i = 0; i < 4; ++i)
                ldsm_x4(af[i], a0 + (uint32_t)(((wm * 64 + i * 16 + lrow) * GLDK + kcol) * 2));
#pragma unroll
            for (int nt = 0; nt < 2; ++nt)
                ldsm_x4(bfr[nt], b0 + (uint32_t)(((wn * 32 + nt * 16 + lrow) * GLDK + kcol) * 2));
#pragma unroll
            for (int i = 0; i < 4; ++i)
#pragma unroll
                for (int n = 0; n < 4; ++n) {
                    const int nt = n >> 1, s = n & 1;
                    mma_bf16(acc[i][n], af[i], bfr[nt][s], bfr[nt][s + 2]);
                }
        }
        if (c < 9) { store_chunk((c + 1) & 1); __syncthreads(); }
    }

#pragma unroll
    for (int i = 0; i < 4; ++i) {
        const int r = mbase + wm * 64 + i * 16 + (lane >> 2);
#pragma unroll
        for (int n = 0; n < 4; ++n) {
            const int col = nbase + wn * 32 + n * 8 + (lane & 3) * 2;
            if (col < N) {
                float2 bv = make_float2(0.f, 0.f);
                if (bias) bv = *reinterpret_cast<const float2*>(bias + col);
                float v0 = acc[i][n][0] + bv.x, v1 = acc[i][n][1] + bv.y;
                float v2 = acc[i][n][2] + bv.x, v3 = acc[i][n][3] + bv.y;
                if (sizeof(CT) == 4) {
                    *reinterpret_cast<float2*>((float*)C + (size_t)r * N + col) = make_float2(v0, v1);
                    *reinterpret_cast<float2*>((float*)C + (size_t)(r + 8) * N + col) = make_float2(v2, v3);
                } else {
                    __nv_bfloat162 lo = __float22bfloat162_rn(make_float2(v0, v1));
                    __nv_bfloat162 hi = __float22bfloat162_rn(make_float2(v2, v3));
                    *reinterpret_cast<uint32_t*>((__nv_bfloat16*)C + (size_t)r * N + col) =
                        *reinterpret_cast<uint32_t*>(&lo);
                    *reinterpret_cast<uint32_t*>((__nv_bfloat16*)C + (size_t)(r + 8) * N + col) =
                        *reinterpret_cast<uint32_t*>(&hi);
                }
            }
        }
    }
}

// encoders: z=0 premise, z=1 hypothesis (f32 gather A, f32 C, fused bias)
__global__ __launch_bounds__(256)
void gemm_enc(const float* __restrict__ embed,
              const int* __restrict__ tokA, const int* __restrict__ tokB,
              const __nv_bfloat16* __restrict__ WA, const __nv_bfloat16* __restrict__ WB,
              const float* __restrict__ bA, const float* __restrict__ bB2,
              float* __restrict__ CA, float* __restrict__ CB)
{
    __shared__ __nv_bfloat16 sm[4 * GBUF];
    const int z = blockIdx.z;
    gemm_core<float, float>(embed, z ? tokB : tokA, z ? WB : WA, 900,
                            z ? CB : CA, 900, z ? bB2 : bA, sm,
                            blockIdx.y * 128, blockIdx.x * 128);
}

// 4 precomputes in one launch (bf16 A, bf16 C)
struct Pre4 {
    const __nv_bfloat16* A[4];
    const __nv_bfloat16* B[4];
    __nv_bfloat16*       C[4];
    const float*         bias[4];
    int                  N[4];
};
__global__ __launch_bounds__(256)
void gemm_pre(Pre4 a)
{
    __shared__ __nv_bfloat16 sm[4 * GBUF];
    const int z = blockIdx.z;
    const int N = a.N[z];
    const int nbase = blockIdx.x * 128;
    if (nbase >= N) return;
    gemm_core<__nv_bfloat16, __nv_bfloat16>(a.A[z], nullptr, a.B[z], N,
                                            a.C[z], N, a.bias[z], sm,
                                            blockIdx.y * 128, nbase);
}

// ======================= lstm0 activation (bias pre-fused) ==================
__global__ void lstm_act2(const float* __restrict__ G1, const float* __restrict__ G2,
                          __nv_bfloat16* __restrict__ h1, __nv_bfloat16* __restrict__ h2)
{
    int idx = blockIdx.x * blockDim.x + threadIdx.x;
    if (idx >= 8192 * 150) return;
    const float* G = blockIdx.y ? G2 : G1;
    __nv_bfloat16* h = blockIdx.y ? h2 : h1;
    int m = idx / 150, j2 = (idx % 150) * 2;
    const float* g = G + (size_t)m * 900;
    float2 gi = *reinterpret_cast<const float2*>(g + j2);
    float2 gg = *reinterpret_cast<const float2*>(g + j2 + 300);
    float2 go = *reinterpret_cast<const float2*>(g + j2 + 600);
    float c0 = sig_apx(gi.x) * tanh_apx(gg.x);
    float c1 = sig_apx(gi.y) * tanh_apx(gg.y);
    float v0 = sig_apx(go.x) * tanh_apx(c0);
    float v1 = sig_apx(go.y) * tanh_apx(c1);
    __nv_bfloat162 o2 = __float22bfloat162_rn(make_float2(v0, v1));
    *reinterpret_cast<uint32_t*>(h + (size_t)m * 300 + j2) = *reinterpret_cast<uint32_t*>(&o2);
}

// ======================= persistent per-batch scan (512 thr) ================
constexpr int SM_WMT = 0;        // 90000 bf16 = 180000
constexpr int SM_SP  = 180000;   // 19200 bf16 = 38400
constexpr int SM_SCR = 218400;   // 1800 f32 = 7200 (A partials; C gates)
constexpr int SM_WE  = 225600;   // 300 f32
constexpr int SM_HM  = 226800;   // 300 f32
constexpr int SM_AL  = 228000;   // 64 f32
constexpr int SM_HF  = 228256;   // 300 f32
constexpr int SM_TM  = 229456;   // 300 bf16 = 600
constexpr int SM_RED = 230056;   // 8 f32
constexpr int SCAN_SMEM_BYTES = 230088;

__global__ __launch_bounds__(512)
void scan_kernel(const __nv_bfloat16* __restrict__ sproj, const __nv_bfloat16* __restrict__ tproj,
                 const __nv_bfloat16* __restrict__ htpre, const __nv_bfloat16* __restrict__ hsWa,
                 const __nv_bfloat16* __restrict__ WmTg,  const float* __restrict__ w_e,
                 const int* __restrict__ plen_a,  const int* __restrict__ hlen_a,
                 const float* __restrict__ fcw,   const float* __restrict__ fcb,
                 float* __restrict__ out)
{
    extern __shared__ char smraw[];
    __nv_bfloat16* wmt   = reinterpret_cast<__nv_bfloat16*>(smraw + SM_WMT);
    __nv_bfloat16* sp    = reinterpret_cast<__nv_bfloat16*>(smraw + SM_SP);
    float*         scr   = reinterpret_cast<float*>(smraw + SM_SCR);
    float*         we_s  = reinterpret_cast<float*>(smraw + SM_WE);
    float*         hm    = reinterpret_cast<float*>(smraw + SM_HM);
    float*         alpha = reinterpret_cast<float*>(smraw + SM_AL);
    float*         hfin  = reinterpret_cast<float*>(smraw + SM_HF);
    __nv_bfloat16* tm    = reinterpret_cast<__nv_bfloat16*>(smraw + SM_TM);
    float*         red   = reinterpret_cast<float*>(smraw + SM_RED);

    const int b    = blockIdx.x;
    const int tid  = threadIdx.x;
    const int warp = tid >> 5, lane = tid & 31;

    for (int i = tid; i < 11250; i += 512)
        reinterpret_cast<uint4*>(wmt)[i] = reinterpret_cast<const uint4*>(WmTg)[i];
    const uint4* spg = reinterpret_cast<const uint4*>(sproj + (size_t)b * 19200);
    for (int i = tid; i < 2400; i += 512)
        reinterpret_cast<uint4*>(sp)[i] = spg[i];
    for (int i = tid; i < 300; i += 512) { we_s[i] = w_e[i]; hm[i] = 0.f; }
    const int plen = plen_a[b];
    const int hlen = hlen_a[b];
    __syncthreads();

    const __nv_bfloat16* hwg = hsWa + (size_t)b * (64 * 900);

    for (int k = 0; k < hlen; ++k) {
        // prefetch phase-C operands into registers; L2 latency hides under A/B
        uint32_t pre[64];
        uint32_t prh = 0;
        if (tid < 450) {
            const uint32_t* hwp = reinterpret_cast<const uint32_t*>(hwg) + tid;
#pragma unroll
            for (int p = 0; p < 64; ++p)
                pre[p] = __ldcs(hwp + (size_t)p * 450);
            prh = __ldcs(reinterpret_cast<const uint32_t*>(
                      htpre + ((size_t)b * 64 + k) * 900) + tid);
        }

        // Phase A: m_proj partials = hm @ Wm^T (6 segs x 75 col-quads)
        if (k > 0 && tid < 450) {
            const int seg = tid / 75;
            const int jq  = tid % 75;
            const int d0  = seg * 50;
            float4 acc = make_float4(0.f, 0.f, 0.f, 0.f);
#pragma unroll 2
            for (int d = d0; d < d0 + 50; ++d) {
                const float hv = hm[d];
                const uint2 w = *reinterpret_cast<const uint2*>(wmt + d * 300 + jq * 4);
                float2 w0 = bf2f2(w.x), w1 = bf2f2(w.y);
                acc.x += hv * w0.x; acc.y += hv * w0.y;
                acc.z += hv * w1.x; acc.w += hv * w1.y;
            }
            reinterpret_cast<float4*>(scr)[seg * 75 + jq] = acc;
        }
        __syncthreads();

        // reduce partials -> mp; tm = bf16(tk + mp)
        if (tid < 75) {
            float4 m = make_float4(0.f, 0.f, 0.f, 0.f);
            if (k > 0) {
#pragma unroll
                for (int s = 0; s < 6; ++s) {
                    float4 a = reinterpret_cast<float4*>(scr)[s * 75 + tid];
                    m.x += a.x; m.y += a.y; m.z += a.z; m.w += a.w;
                }
            }
            const uint32_t* tkg = reinterpret_cast<const uint32_t*>(
                tproj + ((size_t)b * 64 + k) * 300) + 2 * tid;
            float2 t0 = bf2f2(tkg[0]), t1 = bf2f2(tkg[1]);
            __nv_bfloat162 p0 = __float22bfloat162_rn(make_float2(m.x + t0.x, m.y + t0.y));
            __nv_bfloat162 p1 = __float22bfloat162_rn(make_float2(m.z + t1.x, m.w + t1.y));
            *reinterpret_cast<uint2*>(tm + 4 * tid) =
                make_uint2(*reinterpret_cast<uint32_t*>(&p0), *reinterpret_cast<uint32_t*>(&p1));
        }
        __syncthreads();

        // Phase B: e[p] = w_e . tanh(sp[p] + tm)  (packed bf16x2, MUFU tanh)
        const uint32_t* tmu = reinterpret_cast<const uint32_t*>(tm);
        for (int p = warp; p < plen; p += 16) {
            const uint32_t* srow = reinterpret_cast<const uint32_t*>(sp + p * 300);
            float acc = 0.f;
            for (int hp = lane; hp < 150; hp += 32) {
                uint32_t s2 = srow[hp], t2 = tmu[hp];
                __nv_bfloat162 x2 = __hadd2(*reinterpret_cast<__nv_bfloat162*>(&s2),
                                            *reinterpret_cast<__nv_bfloat162*>(&t2));
                uint32_t th = tanh_bf16x2(*reinterpret_cast<uint32_t*>(&x2));
                float2 tf = bf2f2(th);
                float2 w2 = *reinterpret_cast<const float2*>(we_s + 2 * hp);
                acc = fmaf(w2.x, tf.x, acc);
                acc = fmaf(w2.y, tf.y, acc);
            }
#pragma unroll
            for (int o = 16; o > 0; o >>= 1) acc += __shfl_xor_sync(0xffffffffu, acc, o);
            if (lane == 0) alpha[p] = acc;
        }
        __syncthreads();

        // masked softmax over p (warp 0); writes exact zeros for p >= plen
        if (warp == 0) {
            float e0 = (lane < plen) ? alpha[lane] : -FLT_MAX;
            float e1 = (lane + 32 < plen) ? alpha[lane + 32] : -FLT_MAX;
            float mx = fmaxf(e0, e1);
#pragma unroll
            for (int o = 16; o > 0; o >>= 1) mx = fmaxf(mx, __shfl_xor_sync(0xffffffffu, mx, o));
            float x0 = (lane < plen) ? __expf(e0 - mx) : 0.f;
            float x1 = (lane + 32 < plen) ? __expf(e1 - mx) : 0.f;
            float s = x0 + x1;
#pragma unroll
            for (int o = 16; o > 0; o >>= 1) s += __shfl_xor_sync(0xffffffffu, s, o);
            float inv = 1.f / s;
            alpha[lane]      = x0 * inv;
            alpha[lane + 32] = x1 * inv;
        }
        __syncthreads();

        // Phase C: gates = sum_p alpha[p]*pre[p] + htpre(+biasM)  — regs only
        if (tid < 450) {
            float2 acc = bf2f2(prh);
#pragma unroll
            for (int p = 0; p < 64; ++p) {
                const float a = alpha[p];
                float2 w = bf2f2(pre[p]);
                acc.x = fmaf(a, w.x, acc.x);
                acc.y = fmaf(a, w.y, acc.y);
            }
            scr[2 * tid]     = acc.x;
            scr[2 * tid + 1] = acc.y;
        }
        __syncthreads();

        // Phase D: h_m update (accurate fast-math f32 — feeds final logits)
        if (tid < 300) {
            const int h = tid;
            float gi = scr[h];
            float gg = scr[h + 300];
            float go = scr[h + 600];
            float c  = fast_sigmoid(gi) * fast_tanh(gg);
            float hv = fast_sigmoid(go) * fast_tanh(c);
            hm[h] = hv;
            if (k == hlen - 1) hfin[h] = hv;
        }
        __syncthreads();
    }

    if (warp < 3) {
        float acc = 0.f;
        for (int h = lane; h < 300; h += 32) acc += hfin[h] * fcw[warp * 300 + h];
#pragma unroll
        for (int o = 16; o > 0; o >>= 1) acc += __shfl_xor_sync(0xffffffffu, acc, o);
        if (lane == 0) red[warp] = acc + fcb[warp];
    }
    __syncthreads();
    if (tid == 0) {
        float l0 = red[0], l1 = red[1], l2 = red[2];
        float mx = fmaxf(l0, fmaxf(l1, l2));
        float e0 = expf(l0 - mx), e1 = expf(l1 - mx), e2 = expf(l2 - mx);
        float inv = 1.f / (e0 + e1 + e2);
        out[b * 3 + 0] = e0 * inv;
        out[b * 3 + 1] = e1 * inv;
        out[b * 3 + 2] = e2 * inv;
    }
}

// ---------------------------------------------------------------------------
extern "C" void kernel_launch(void* const* d_in, const int* in_sizes, int n_in,
                              void* d_out, int out_size)
{
    const int*   premise = (const int*)  d_in[0];
    const int*   plen    = (const int*)  d_in[1];
    const int*   hyp     = (const int*)  d_in[2];
    const int*   hlen    = (const int*)  d_in[3];
    const float* embed   = (const float*)d_in[4];
    const float* w_e     = (const float*)d_in[5];
    const float* W_s     = (const float*)d_in[6];
    const float* W_t     = (const float*)d_in[7];
    const float* W_m     = (const float*)d_in[8];
    const float* fc_w    = (const float*)d_in[9];
    const float* fc_b    = (const float*)d_in[10];
    const float* Wih_p   = (const float*)d_in[11];
    const float* bih_p   = (const float*)d_in[13];
    const float* bhh_p   = (const float*)d_in[14];
    const float* Wih_h   = (const float*)d_in[15];
    const float* bih_h   = (const float*)d_in[17];
    const float* bhh_h   = (const float*)d_in[18];
    const float* Wih_m   = (const float*)d_in[19];
    const float* bih_m   = (const float*)d_in[21];
    const float* bhh_m   = (const float*)d_in[22];

    float* buf = nullptr;
    cudaGetSymbolAddress((void**)&buf, g_buf);
    float*          gates1 = buf + OFF_GATES1;
    float*          gates2 = buf + OFF_GATES2;
    __nv_bfloat16*  hs     = (__nv_bfloat16*)(buf + OFF_HS);
    __nv_bfloat16*  ht     = (__nv_bfloat16*)(buf + OFF_HT);
    __nv_bfloat16*  sprojp = (__nv_bfloat16*)(buf + OFF_SPROJ);
    __nv_bfloat16*  tprojp = (__nv_bfloat16*)(buf + OFF_TPROJ);
    __nv_bfloat16*  htprep = (__nv_bfloat16*)(buf + OFF_HTPRE);
    __nv_bfloat16*  hsWap  = (__nv_bfloat16*)(buf + OFF_HSWA);
    __nv_bfloat16*  Wp     = (__nv_bfloat16*)(buf + OFF_WPB);
    __nv_bfloat16*  Wh     = (__nv_bfloat16*)(buf + OFF_WHB);
    __nv_bfloat16*  Wa     = (__nv_bfloat16*)(buf + OFF_WAB);
    __nv_bfloat16*  Whm    = (__nv_bfloat16*)(buf + OFF_WHMB);
    __nv_bfloat16*  Wsb    = (__nv_bfloat16*)(buf + OFF_WSB);
    __nv_bfloat16*  Wtb    = (__nv_bfloat16*)(buf + OFF_WTB);
    __nv_bfloat16*  WmT    = (__nv_bfloat16*)(buf + OFF_WMTB);
    float* bp = buf + OFF_BP;
    float* bh = buf + OFF_BH;
    float* bm = buf + OFF_BM;

    prep_all<<<(1350000 + 255) / 256, 256>>>(Wih_p, bih_p, bhh_p,
                                             Wih_h, bih_h, bhh_h,
                                             Wih_m, bih_m, bhh_m,
                                             W_m, W_s, W_t,
                                             Wp, Wh, Wa, Whm, Wsb, Wtb, WmT,
                                             bp, bh, bm);

    // encoders: one launch, bias fused
    gemm_enc<<<dim3(8, 64, 2), 256>>>(embed, premise, hyp, Wp, Wh, bp, bh,
                                      gates1, gates2);
    lstm_act2<<<dim3((8192 * 150 + 255) / 256, 2), 256>>>(gates1, gates2, hs, ht);

    // 4 precomputes: one launch (htpre gets biasM fused)
    Pre4 pa;
    pa.A[0] = hs;  pa.B[0] = Wa;  pa.C[0] = hsWap;  pa.bias[0] = nullptr; pa.N[0] = 900;
    pa.A[1] = ht;  pa.B[1] = Whm; pa.C[1] = htprep; pa.bias[1] = bm;      pa.N[1] = 900;
    pa.A[2] = hs;  pa.B[2] = Wsb; pa.C[2] = sprojp; pa.bias[2] = nullptr; pa.N[2] = 300;
    pa.A[3] = ht;  pa.B[3] = Wtb; pa.C[3] = tprojp; pa.bias[3] = nullptr; pa.N[3] = 300;
    gemm_pre<<<dim3(8, 64, 4), 256>>>(pa);

    cudaFuncSetAttribute(scan_kernel, cudaFuncAttributeMaxDynamicSharedMemorySize,
                         SCAN_SMEM_BYTES);
    scan_kernel<<<128, 512, SCAN_SMEM_BYTES>>>(sprojp, tprojp, htprep, hsWap, WmT,
                                               w_e, plen, hlen, fc_w, fc_b,
                                               (float*)d_out);
}

// round 10
// speedup vs baseline: 3.8086x; 1.0925x over previous
#include <cuda_runtime.h>
#include <cuda_bf16.h>
#include <math.h>
#include <float.h>
#include <stdint.h>

// ---------------------------------------------------------------------------
// MatchLSTM: B=128, P=K=64, E=H=300, V=50000, C=3
//  GEMMs: bf16 mma.sync.m16n8k16 + ldmatrix, double-buffered SMEM, fused bias.
//  Scan: 512 thr/block; WmT in SMEM; hsWa held in REGISTERS across all steps
//        (k-invariant); only htpre row k streamed per step.
// ---------------------------------------------------------------------------

// offsets in f32 units
constexpr size_t OFF_GATES1 = 0;                        // 8192*900 f32
constexpr size_t OFF_GATES2 = OFF_GATES1 + 7372800;     // 8192*900 f32
constexpr size_t OFF_HS     = OFF_GATES2 + 7372800;     // 8192*300 bf16
constexpr size_t OFF_HT     = OFF_HS     + 1228800;
constexpr size_t OFF_SPROJ  = OFF_HT     + 1228800;     // 8192*300 bf16
constexpr size_t OFF_TPROJ  = OFF_SPROJ  + 1228800;     // 8192*300 bf16
constexpr size_t OFF_HTPRE  = OFF_TPROJ  + 1228800;     // 8192*900 bf16 (+biasM)
constexpr size_t OFF_HSWA   = OFF_HTPRE  + 3686400;     // 8192*900 bf16
constexpr size_t OFF_WPB    = OFF_HSWA   + 3686400;     // 900*300 bf16
constexpr size_t OFF_WHB    = OFF_WPB    + 135000;
constexpr size_t OFF_WAB    = OFF_WHB    + 135000;
constexpr size_t OFF_WHMB   = OFF_WAB    + 135000;
constexpr size_t OFF_WSB    = OFF_WHMB   + 135000;      // 300*300 bf16
constexpr size_t OFF_WTB    = OFF_WSB    + 45000;
constexpr size_t OFF_WMTB   = OFF_WTB    + 45000;       // 300*300 bf16
constexpr size_t OFF_BP     = OFF_WMTB   + 45000;       // 900 f32
constexpr size_t OFF_BH     = OFF_BP + 900;
constexpr size_t OFF_BM     = OFF_BH + 900;
constexpr size_t BUF_TOTAL  = OFF_BM + 900;

__device__ __align__(16) float g_buf[BUF_TOTAL];

__device__ __forceinline__ float fast_sigmoid(float x) {
    return __fdividef(1.f, 1.f + __expf(-x));
}
__device__ __forceinline__ float fast_tanh(float x) {
    float e = __expf(2.f * x);
    return 1.f - __fdividef(2.f, e + 1.f);
}
__device__ __forceinline__ float tanh_apx(float x) {
    float y; asm("tanh.approx.f32 %0, %1;" : "=f"(y) : "f"(x)); return y;
}
__device__ __forceinline__ float sig_apx(float x) {
    return fmaf(0.5f, tanh_apx(0.5f * x), 0.5f);
}

__device__ __forceinline__ uint32_t smem_u32(const void* p) {
    uint32_t a;
    asm("{ .reg .u64 t; cvta.to.shared.u64 t, %1; cvt.u32.u64 %0, t; }" : "=r"(a) : "l"(p));
    return a;
}
__device__ __forceinline__ void ldsm_x4(uint32_t r[4], uint32_t addr) {
    asm volatile("ldmatrix.sync.aligned.m8n8.x4.shared.b16 {%0,%1,%2,%3}, [%4];"
                 : "=r"(r[0]), "=r"(r[1]), "=r"(r[2]), "=r"(r[3]) : "r"(addr));
}
__device__ __forceinline__ void mma_bf16(float c[4], const uint32_t a[4],
                                         uint32_t b0, uint32_t b1) {
    asm volatile(
        "mma.sync.aligned.m16n8k16.row.col.f32.bf16.bf16.f32 "
        "{%0,%1,%2,%3}, {%4,%5,%6,%7}, {%8,%9}, {%0,%1,%2,%3};"
        : "+f"(c[0]), "+f"(c[1]), "+f"(c[2]), "+f"(c[3])
        : "r"(a[0]), "r"(a[1]), "r"(a[2]), "r"(a[3]), "r"(b0), "r"(b1));
}
__device__ __forceinline__ float2 bf2f2(uint32_t u) {
    __nv_bfloat162 h = *reinterpret_cast<__nv_bfloat162*>(&u);
    return __bfloat1622float2(h);
}
__device__ __forceinline__ uint32_t tanh_bf16x2(uint32_t x) {
    uint32_t d;
    asm("tanh.approx.bf16x2 %0, %1;" : "=r"(d) : "r"(x));
    return d;
}

// ======================= fused prep (1 launch) ==============================
__global__ void prep_all(const float* __restrict__ Wih_p, const float* __restrict__ bih_p,
                         const float* __restrict__ bhh_p,
                         const float* __restrict__ Wih_h, const float* __restrict__ bih_h,
                         const float* __restrict__ bhh_h,
                         const float* __restrict__ Wih_m, const float* __restrict__ bih_m,
                         const float* __restrict__ bhh_m,
                         const float* __restrict__ Wm,
                         const float* __restrict__ Ws, const float* __restrict__ Wt,
                         __nv_bfloat16* __restrict__ Wp, __nv_bfloat16* __restrict__ Wh,
                         __nv_bfloat16* __restrict__ Wa, __nv_bfloat16* __restrict__ Whm,
                         __nv_bfloat16* __restrict__ Wsb, __nv_bfloat16* __restrict__ Wtb,
                         __nv_bfloat16* __restrict__ WmT,
                         float* __restrict__ bp, float* __restrict__ bh,
                         float* __restrict__ bm)
{
    int idx = blockIdx.x * blockDim.x + threadIdx.x;
    if (idx < 270000) {
        int j = idx / 300, k2 = idx % 300;
        int src = (j < 300) ? j : j + 300;
        Wp[idx] = __float2bfloat16(Wih_p[(size_t)src * 300 + k2]);
    } else if (idx < 540000) {
        int t = idx - 270000; int j = t / 300, k2 = t % 300;
        int src = (j < 300) ? j : j + 300;
        Wh[t] = __float2bfloat16(Wih_h[(size_t)src * 300 + k2]);
    } else if (idx < 810000) {
        int t = idx - 540000; int j = t / 300, k2 = t % 300;
        int src = (j < 300) ? j : j + 300;
        Wa[t] = __float2bfloat16(Wih_m[(size_t)src * 600 + k2]);
    } else if (idx < 1080000) {
        int t = idx - 810000; int j = t / 300, k2 = t % 300;
        int src = (j < 300) ? j : j + 300;
        Whm[t] = __float2bfloat16(Wih_m[(size_t)src * 600 + 300 + k2]);
    } else if (idx < 1170000) {
        int t = idx - 1080000;
        Wsb[t] = __float2bfloat16(Ws[t]);
    } else if (idx < 1260000) {
        int t = idx - 1170000;
        Wtb[t] = __float2bfloat16(Wt[t]);
    } else if (idx < 1350000) {
        int t = idx - 1260000; int d = t / 300, j = t % 300;
        WmT[t] = __float2bfloat16(Wm[(size_t)j * 300 + d]);
    }
    if (idx < 900) {
        int src = (idx < 300) ? idx : idx + 300;
        bp[idx] = bih_p[src] + bhh_p[src];
        bh[idx] = bih_h[src] + bhh_h[src];
        bm[idx] = bih_m[src] + bhh_m[src];
    }
}

// ======================= bf16 tensor-core GEMM core =========================
constexpr int GLDK = 40;
constexpr int GBUF = 128 * GLDK;   // 5120 bf16 per buffer

template <typename AT, typename CT>
__device__ __forceinline__ void gemm_core(
    const AT* __restrict__ A, const int* __restrict__ tok,
    const __nv_bfloat16* __restrict__ B, int Brows,
    CT* __restrict__ C, int N, const float* __restrict__ bias,
    __nv_bfloat16* __restrict__ sm, int mbase, int nbase)
{
    constexpr bool AF32 = (sizeof(AT) == 4);
    const int tid = threadIdx.x;
    const int warp = tid >> 5, lane = tid & 31;
    const int wm = warp >> 2, wn = warp & 3;

    const uint32_t aB[2] = { smem_u32(sm),            smem_u32(sm + GBUF) };
    const uint32_t bB[2] = { smem_u32(sm + 2 * GBUF), smem_u32(sm + 3 * GBUF) };

    int arow_s[4], asrc[4], ac4[4];
    bool bok[4];
#pragma unroll
    for (int p = 0; p < 4; ++p) {
        const int f4 = tid + 256 * p;
        const int row = f4 >> 3;
        arow_s[p] = row;
        ac4[p]    = f4 & 7;
        const int gm = mbase + row;
        asrc[p] = tok ? tok[gm] : gm;
        bok[p]  = (nbase + row) < Brows;
    }

    float acc[4][4][4];
#pragma unroll
    for (int i = 0; i < 4; i++)
#pragma unroll
        for (int n = 0; n < 4; n++)
#pragma unroll
            for (int e = 0; e < 4; e++) acc[i][n][e] = 0.f;

    const int lrow = lane & 15;
    const int lkof = (lane >> 4) << 3;

    float4 vaf[4];
    uint2  vab[4], vbb[4];

    auto load_chunk = [&](int k0) {
#pragma unroll
        for (int p = 0; p < 4; ++p) {
            const int kk = k0 + ac4[p] * 4;
            const bool kv = (kk < 300);
            if (AF32) {
                vaf[p] = kv ? *reinterpret_cast<const float4*>((const float*)A + (size_t)asrc[p] * 300 + kk)
                            : make_float4(0.f, 0.f, 0.f, 0.f);
            } else {
                vab[p] = kv ? *reinterpret_cast<const uint2*>((const __nv_bfloat16*)A + (size_t)asrc[p] * 300 + kk)
                            : make_uint2(0u, 0u);
            }
            vbb[p] = (kv && bok[p])
                ? *reinterpret_cast<const uint2*>(B + (size_t)(nbase + arow_s[p]) * 300 + kk)
                : make_uint2(0u, 0u);
        }
    };
    auto store_chunk = [&](int buf) {
        __nv_bfloat16* Asb = sm + buf * GBUF;
        __nv_bfloat16* Bsb = sm + (2 + buf) * GBUF;
#pragma unroll
        for (int p = 0; p < 4; ++p) {
            const int off = arow_s[p] * GLDK + ac4[p] * 4;
            if (AF32) {
                __nv_bfloat162 alo = __float22bfloat162_rn(make_float2(vaf[p].x, vaf[p].y));
                __nv_bfloat162 ahi = __float22bfloat162_rn(make_float2(vaf[p].z, vaf[p].w));
                *reinterpret_cast<uint2*>(&Asb[off]) =
                    make_uint2(*reinterpret_cast<uint32_t*>(&alo), *reinterpret_cast<uint32_t*>(&ahi));
            } else {
                *reinterpret_cast<uint2*>(&Asb[off]) = vab[p];
            }
            *reinterpret_cast<uint2*>(&Bsb[off]) = vbb[p];
        }
    };

    load_chunk(0);
    store_chunk(0);
    __syncthreads();

#pragma unroll 1
    for (int c = 0; c < 10; ++c) {
        if (c < 9) load_chunk((c + 1) * 32);
        const uint32_t a0 = aB[c & 1], b0 = bB[c & 1];
#pragma unroll
        for (int j = 0; j < 2; ++j) {
            const int kcol = j * 16 + lkof;
            uint32_t af[4][4], bfr[2][4];
#pragma unroll
            for (int i = 0; i < 4; ++i)
                ldsm_x4(af[i], a0 + (uint32_t)(((wm * 64 + i * 16 + lrow) * GLDK + kcol) * 2));
#pragma unroll
            for (int nt = 0; nt < 2; ++nt)
                ldsm_x4(bfr[nt], b0 + (uint32_t)(((wn * 32 + nt * 16 + lrow) * GLDK + kcol) * 2));
#pragma unroll
            for (int i = 0; i < 4; ++i)
#pragma unroll
                for (int n = 0; n < 4; ++n) {
                    const int nt = n >> 1, s = n & 1;
                    mma_bf16(acc[i][n], af[i], bfr[nt][s], bfr[nt][s + 2]);
                }
        }
        if (c < 9) { store_chunk((c + 1) & 1); __syncthreads(); }
    }

#pragma unroll
    for (int i = 0; i < 4; ++i) {
        const int r = mbase + wm * 64 + i * 16 + (lane >> 2);
#pragma unroll
        for (int n = 0; n < 4; ++n) {
            const int col = nbase + wn * 32 + n * 8 + (lane & 3) * 2;
            if (col < N) {
                float2 bv = make_float2(0.f, 0.f);
                if (bias) bv = *reinterpret_cast<const float2*>(bias + col);
                float v0 = acc[i][n][0] + bv.x, v1 = acc[i][n][1] + bv.y;
                float v2 = acc[i][n][2] + bv.x, v3 = acc[i][n][3] + bv.y;
                if (sizeof(CT) == 4) {
                    *reinterpret_cast<float2*>((float*)C + (size_t)r * N + col) = make_float2(v0, v1);
                    *reinterpret_cast<float2*>((float*)C + (size_t)(r + 8) * N + col) = make_float2(v2, v3);
                } else {
                    __nv_bfloat162 lo = __float22bfloat162_rn(make_float2(v0, v1));
                    __nv_bfloat162 hi = __float22bfloat162_rn(make_float2(v2, v3));
                    *reinterpret_cast<uint32_t*>((__nv_bfloat16*)C + (size_t)r * N + col) =
                        *reinterpret_cast<uint32_t*>(&lo);
                    *reinterpret_cast<uint32_t*>((__nv_bfloat16*)C + (size_t)(r + 8) * N + col) =
                        *reinterpret_cast<uint32_t*>(&hi);
                }
            }
        }
    }
}

// encoders: z=0 premise, z=1 hypothesis (f32 gather A, f32 C, fused bias)
__global__ __launch_bounds__(256, 2)
void gemm_enc(const float* __restrict__ embed,
              const int* __restrict__ tokA, const int* __restrict__ tokB,
              const __nv_bfloat16* __restrict__ WA, const __nv_bfloat16* __restrict__ WB,
              const float* __restrict__ bA, const float* __restrict__ bB2,
              float* __restrict__ CA, float* __restrict__ CB)
{
    __shared__ __nv_bfloat16 sm[4 * GBUF];
    const int z = blockIdx.z;
    gemm_core<float, float>(embed, z ? tokB : tokA, z ? WB : WA, 900,
                            z ? CB : CA, 900, z ? bB2 : bA, sm,
                            blockIdx.y * 128, blockIdx.x * 128);
}

// 4 precomputes in one launch (bf16 A, bf16 C)
struct Pre4 {
    const __nv_bfloat16* A[4];
    const __nv_bfloat16* B[4];
    __nv_bfloat16*       C[4];
    const float*         bias[4];
    int                  N[4];
};
__global__ __launch_bounds__(256, 2)
void gemm_pre(Pre4 a)
{
    __shared__ __nv_bfloat16 sm[4 * GBUF];
    const int z = blockIdx.z;
    const int N = a.N[z];
    const int nbase = blockIdx.x * 128;
    if (nbase >= N) return;
    gemm_core<__nv_bfloat16, __nv_bfloat16>(a.A[z], nullptr, a.B[z], N,
                                            a.C[z], N, a.bias[z], sm,
                                            blockIdx.y * 128, nbase);
}

// ======================= lstm0 activation (bias pre-fused) ==================
__global__ void lstm_act2(const float* __restrict__ G1, const float* __restrict__ G2,
                          __nv_bfloat16* __restrict__ h1, __nv_bfloat16* __restrict__ h2)
{
    int idx = blockIdx.x * blockDim.x + threadIdx.x;
    if (idx >= 8192 * 150) return;
    const float* G = blockIdx.y ? G2 : G1;
    __nv_bfloat16* h = blockIdx.y ? h2 : h1;
    int m = idx / 150, j2 = (idx % 150) * 2;
    const float* g = G + (size_t)m * 900;
    float2 gi = *reinterpret_cast<const float2*>(g + j2);
    float2 gg = *reinterpret_cast<const float2*>(g + j2 + 300);
    float2 go = *reinterpret_cast<const float2*>(g + j2 + 600);
    float c0 = sig_apx(gi.x) * tanh_apx(gg.x);
    float c1 = sig_apx(gi.y) * tanh_apx(gg.y);
    float v0 = sig_apx(go.x) * tanh_apx(c0);
    float v1 = sig_apx(go.y) * tanh_apx(c1);
    __nv_bfloat162 o2 = __float22bfloat162_rn(make_float2(v0, v1));
    *reinterpret_cast<uint32_t*>(h + (size_t)m * 300 + j2) = *reinterpret_cast<uint32_t*>(&o2);
}

// ======================= persistent per-batch scan (512 thr) ================
constexpr int SM_WMT = 0;        // 90000 bf16 = 180000
constexpr int SM_SP  = 180000;   // 19200 bf16 = 38400
constexpr int SM_SCR = 218400;   // 1800 f32 = 7200 (A partials; C gates)
constexpr int SM_WE  = 225600;   // 300 f32
constexpr int SM_HM  = 226800;   // 300 f32
constexpr int SM_AL  = 228000;   // 64 f32
constexpr int SM_HF  = 228256;   // 300 f32
constexpr int SM_TM  = 229456;   // 300 bf16 = 600
constexpr int SM_RED = 230056;   // 8 f32
constexpr int SCAN_SMEM_BYTES = 230088;

__global__ __launch_bounds__(512)
void scan_kernel(const __nv_bfloat16* __restrict__ sproj, const __nv_bfloat16* __restrict__ tproj,
                 const __nv_bfloat16* __restrict__ htpre, const __nv_bfloat16* __restrict__ hsWa,
                 const __nv_bfloat16* __restrict__ WmTg,  const float* __restrict__ w_e,
                 const int* __restrict__ plen_a,  const int* __restrict__ hlen_a,
                 const float* __restrict__ fcw,   const float* __restrict__ fcb,
                 float* __restrict__ out)
{
    extern __shared__ char smraw[];
    __nv_bfloat16* wmt   = reinterpret_cast<__nv_bfloat16*>(smraw + SM_WMT);
    __nv_bfloat16* sp    = reinterpret_cast<__nv_bfloat16*>(smraw + SM_SP);
    float*         scr   = reinterpret_cast<float*>(smraw + SM_SCR);
    float*         we_s  = reinterpret_cast<float*>(smraw + SM_WE);
    float*         hm    = reinterpret_cast<float*>(smraw + SM_HM);
    float*         alpha = reinterpret_cast<float*>(smraw + SM_AL);
    float*         hfin  = reinterpret_cast<float*>(smraw + SM_HF);
    __nv_bfloat16* tm    = reinterpret_cast<__nv_bfloat16*>(smraw + SM_TM);
    float*         red   = reinterpret_cast<float*>(smraw + SM_RED);

    const int b    = blockIdx.x;
    const int tid  = threadIdx.x;
    const int warp = tid >> 5, lane = tid & 31;

    for (int i = tid; i < 11250; i += 512)
        reinterpret_cast<uint4*>(wmt)[i] = reinterpret_cast<const uint4*>(WmTg)[i];
    const uint4* spg = reinterpret_cast<const uint4*>(sproj + (size_t)b * 19200);
    for (int i = tid; i < 2400; i += 512)
        reinterpret_cast<uint4*>(sp)[i] = spg[i];
    for (int i = tid; i < 300; i += 512) { we_s[i] = w_e[i]; hm[i] = 0.f; }
    const int plen = plen_a[b];
    const int hlen = hlen_a[b];

    // hsWa is k-INVARIANT: load the 64 attention rows into registers ONCE.
    // tid<450 holds column pair (2*tid, 2*tid+1) of all 64 rows. ~64 regs.
    uint32_t pre[64];
    if (tid < 450) {
        const uint32_t* hwp = reinterpret_cast<const uint32_t*>(
                                  hsWa + (size_t)b * (64 * 900)) + tid;
#pragma unroll
        for (int p = 0; p < 64; ++p)
            pre[p] = hwp[(size_t)p * 450];
    }
    __syncthreads();

    for (int k = 0; k < hlen; ++k) {
        // stream htpre row k (only k-dependent gate input); hides under A/B
        uint32_t prh = 0;
        if (tid < 450)
            prh = __ldcs(reinterpret_cast<const uint32_t*>(
                      htpre + ((size_t)b * 64 + k) * 900) + tid);

        // Phase A: m_proj partials = hm @ Wm^T (6 segs x 75 col-quads)
        if (k > 0 && tid < 450) {
            const int seg = tid / 75;
            const int jq  = tid % 75;
            const int d0  = seg * 50;
            float4 acc = make_float4(0.f, 0.f, 0.f, 0.f);
#pragma unroll 2
            for (int d = d0; d < d0 + 50; ++d) {
                const float hv = hm[d];
                const uint2 w = *reinterpret_cast<const uint2*>(wmt + d * 300 + jq * 4);
                float2 w0 = bf2f2(w.x), w1 = bf2f2(w.y);
                acc.x += hv * w0.x; acc.y += hv * w0.y;
                acc.z += hv * w1.x; acc.w += hv * w1.y;
            }
            reinterpret_cast<float4*>(scr)[seg * 75 + jq] = acc;
        }
        __syncthreads();

        // reduce partials -> mp; tm = bf16(tk + mp)
        if (tid < 75) {
            float4 m = make_float4(0.f, 0.f, 0.f, 0.f);
            if (k > 0) {
#pragma unroll
                for (int s = 0; s < 6; ++s) {
                    float4 a = reinterpret_cast<float4*>(scr)[s * 75 + tid];
                    m.x += a.x; m.y += a.y; m.z += a.z; m.w += a.w;
                }
            }
            const uint32_t* tkg = reinterpret_cast<const uint32_t*>(
                tproj + ((size_t)b * 64 + k) * 300) + 2 * tid;
            float2 t0 = bf2f2(tkg[0]), t1 = bf2f2(tkg[1]);
            __nv_bfloat162 p0 = __float22bfloat162_rn(make_float2(m.x + t0.x, m.y + t0.y));
            __nv_bfloat162 p1 = __float22bfloat162_rn(make_float2(m.z + t1.x, m.w + t1.y));
            *reinterpret_cast<uint2*>(tm + 4 * tid) =
                make_uint2(*reinterpret_cast<uint32_t*>(&p0), *reinterpret_cast<uint32_t*>(&p1));
        }
        __syncthreads();

        // Phase B: e[p] = w_e . tanh(sp[p] + tm)  (packed bf16x2, MUFU tanh)
        const uint32_t* tmu = reinterpret_cast<const uint32_t*>(tm);
        for (int p = warp; p < plen; p += 16) {
            const uint32_t* srow = reinterpret_cast<const uint32_t*>(sp + p * 300);
            float acc = 0.f;
            for (int hp = lane; hp < 150; hp += 32) {
                uint32_t s2 = srow[hp], t2 = tmu[hp];
                __nv_bfloat162 x2 = __hadd2(*reinterpret_cast<__nv_bfloat162*>(&s2),
                                            *reinterpret_cast<__nv_bfloat162*>(&t2));
                uint32_t th = tanh_bf16x2(*reinterpret_cast<uint32_t*>(&x2));
                float2 tf = bf2f2(th);
                float2 w2 = *reinterpret_cast<const float2*>(we_s + 2 * hp);
                acc = fmaf(w2.x, tf.x, acc);
                acc = fmaf(w2.y, tf.y, acc);
            }
#pragma unroll
            for (int o = 16; o > 0; o >>= 1) acc += __shfl_xor_sync(0xffffffffu, acc, o);
            if (lane == 0) alpha[p] = acc;
        }
        __syncthreads();

        // masked softmax over p (warp 0); writes exact zeros for p >= plen
        if (warp == 0) {
            float e0 = (lane < plen) ? alpha[lane] : -FLT_MAX;
            float e1 = (lane + 32 < plen) ? alpha[lane + 32] : -FLT_MAX;
            float mx = fmaxf(e0, e1);
#pragma unroll
            for (int o = 16; o > 0; o >>= 1) mx = fmaxf(mx, __shfl_xor_sync(0xffffffffu, mx, o));
            float x0 = (lane < plen) ? __expf(e0 - mx) : 0.f;
            float x1 = (lane + 32 < plen) ? __expf(e1 - mx) : 0.f;
            float s = x0 + x1;
#pragma unroll
            for (int o = 16; o > 0; o >>= 1) s += __shfl_xor_sync(0xffffffffu, s, o);
            float inv = 1.f / s;
            alpha[lane]      = x0 * inv;
            alpha[lane + 32] = x1 * inv;
        }
        __syncthreads();

        // Phase C: gates = sum_p alpha[p]*pre[p] + htpre(+biasM)  — regs only
        if (tid < 450) {
            float2 acc = bf2f2(prh);
#pragma unroll
            for (int p = 0; p < 64; ++p) {
                const float a = alpha[p];
                float2 w = bf2f2(pre[p]);
                acc.x = fmaf(a, w.x, acc.x);
                acc.y = fmaf(a, w.y, acc.y);
            }
            scr[2 * tid]     = acc.x;
            scr[2 * tid + 1] = acc.y;
        }
        __syncthreads();

        // Phase D: h_m update (accurate fast-math f32 — feeds final logits)
        if (tid < 300) {
            const int h = tid;
            float gi = scr[h];
            float gg = scr[h + 300];
            float go = scr[h + 600];
            float c  = fast_sigmoid(gi) * fast_tanh(gg);
            float hv = fast_sigmoid(go) * fast_tanh(c);
            hm[h] = hv;
            if (k == hlen - 1) hfin[h] = hv;
        }
        __syncthreads();
    }

    if (warp < 3) {
        float acc = 0.f;
        for (int h = lane; h < 300; h += 32) acc += hfin[h] * fcw[warp * 300 + h];
#pragma unroll
        for (int o = 16; o > 0; o >>= 1) acc += __shfl_xor_sync(0xffffffffu, acc, o);
        if (lane == 0) red[warp] = acc + fcb[warp];
    }
    __syncthreads();
    if (tid == 0) {
        float l0 = red[0], l1 = red[1], l2 = red[2];
        float mx = fmaxf(l0, fmaxf(l1, l2));
        float e0 = expf(l0 - mx), e1 = expf(l1 - mx), e2 = expf(l2 - mx);
        float inv = 1.f / (e0 + e1 + e2);
        out[b * 3 + 0] = e0 * inv;
        out[b * 3 + 1] = e1 * inv;
        out[b * 3 + 2] = e2 * inv;
    }
}

// ---------------------------------------------------------------------------
extern "C" void kernel_launch(void* const* d_in, const int* in_sizes, int n_in,
                              void* d_out, int out_size)
{
    const int*   premise = (const int*)  d_in[0];
    const int*   plen    = (const int*)  d_in[1];
    const int*   hyp     = (const int*)  d_in[2];
    const int*   hlen    = (const int*)  d_in[3];
    const float* embed   = (const float*)d_in[4];
    const float* w_e     = (const float*)d_in[5];
    const float* W_s     = (const float*)d_in[6];
    const float* W_t     = (const float*)d_in[7];
    const float* W_m     = (const float*)d_in[8];
    const float* fc_w    = (const float*)d_in[9];
    const float* fc_b    = (const float*)d_in[10];
    const float* Wih_p   = (const float*)d_in[11];
    const float* bih_p   = (const float*)d_in[13];
    const float* bhh_p   = (const float*)d_in[14];
    const float* Wih_h   = (const float*)d_in[15];
    const float* bih_h   = (const float*)d_in[17];
    const float* bhh_h   = (const float*)d_in[18];
    const float* Wih_m   = (const float*)d_in[19];
    const float* bih_m   = (const float*)d_in[21];
    const float* bhh_m   = (const float*)d_in[22];

    float* buf = nullptr;
    cudaGetSymbolAddress((void**)&buf, g_buf);
    float*          gates1 = buf + OFF_GATES1;
    float*          gates2 = buf + OFF_GATES2;
    __nv_bfloat16*  hs     = (__nv_bfloat16*)(buf + OFF_HS);
    __nv_bfloat16*  ht     = (__nv_bfloat16*)(buf + OFF_HT);
    __nv_bfloat16*  sprojp = (__nv_bfloat16*)(buf + OFF_SPROJ);
    __nv_bfloat16*  tprojp = (__nv_bfloat16*)(buf + OFF_TPROJ);
    __nv_bfloat16*  htprep = (__nv_bfloat16*)(buf + OFF_HTPRE);
    __nv_bfloat16*  hsWap  = (__nv_bfloat16*)(buf + OFF_HSWA);
    __nv_bfloat16*  Wp     = (__nv_bfloat16*)(buf + OFF_WPB);
    __nv_bfloat16*  Wh     = (__nv_bfloat16*)(buf + OFF_WHB);
    __nv_bfloat16*  Wa     = (__nv_bfloat16*)(buf + OFF_WAB);
    __nv_bfloat16*  Whm    = (__nv_bfloat16*)(buf + OFF_WHMB);
    __nv_bfloat16*  Wsb    = (__nv_bfloat16*)(buf + OFF_WSB);
    __nv_bfloat16*  Wtb    = (__nv_bfloat16*)(buf + OFF_WTB);
    __nv_bfloat16*  WmT    = (__nv_bfloat16*)(buf + OFF_WMTB);
    float* bp = buf + OFF_BP;
    float* bh = buf + OFF_BH;
    float* bm = buf + OFF_BM;

    prep_all<<<(1350000 + 255) / 256, 256>>>(Wih_p, bih_p, bhh_p,
                                             Wih_h, bih_h, bhh_h,
                                             Wih_m, bih_m, bhh_m,
                                             W_m, W_s, W_t,
                                             Wp, Wh, Wa, Whm, Wsb, Wtb, WmT,
                                             bp, bh, bm);

    gemm_enc<<<dim3(8, 64, 2), 256>>>(embed, premise, hyp, Wp, Wh, bp, bh,
                                      gates1, gates2);
    lstm_act2<<<dim3((8192 * 150 + 255) / 256, 2), 256>>>(gates1, gates2, hs, ht);

    Pre4 pa;
    pa.A[0] = hs;  pa.B[0] = Wa;  pa.C[0] = hsWap;  pa.bias[0] = nullptr; pa.N[0] = 900;
    pa.A[1] = ht;  pa.B[1] = Whm; pa.C[1] = htprep; pa.bias[1] = bm;      pa.N[1] = 900;
    pa.A[2] = hs;  pa.B[2] = Wsb; pa.C[2] = sprojp; pa.bias[2] = nullptr; pa.N[2] = 300;
    pa.A[3] = ht;  pa.B[3] = Wtb; pa.C[3] = tprojp; pa.bias[3] = nullptr; pa.N[3] = 300;
    gemm_pre<<<dim3(8, 64, 4), 256>>>(pa);

    cudaFuncSetAttribute(scan_kernel, cudaFuncAttributeMaxDynamicSharedMemorySize,
                         SCAN_SMEM_BYTES);
    scan_kernel<<<128, 512, SCAN_SMEM_BYTES>>>(sprojp, tprojp, htprep, hsWap, WmT,
                                               w_e, plen, hlen, fc_w, fc_b,
                                               (float*)d_out);
}

// round 11
// speedup vs baseline: 4.0248x; 1.0568x over previous
#include <cuda_runtime.h>
#include <cuda_bf16.h>
#include <math.h>
#include <float.h>
#include <stdint.h>

// ---------------------------------------------------------------------------
// MatchLSTM: B=128, P=K=64, E=H=300, V=50000, C=3
//  GEMMs: bf16 mma.sync.m16n8k16 + ldmatrix, double-buffered SMEM, fused bias.
//  Scan: 512 thr/block; WmT in SMEM; hsWa in registers; tproj/htpre prefetch;
//        all-warp redundant softmax (5 barriers/step).
// ---------------------------------------------------------------------------

// offsets in f32 units
constexpr size_t OFF_GATES1 = 0;                        // 8192*900 bf16
constexpr size_t OFF_GATES2 = OFF_GATES1 + 3686400;     // 8192*900 bf16
constexpr size_t OFF_HS     = OFF_GATES2 + 3686400;     // 8192*300 bf16
constexpr size_t OFF_HT     = OFF_HS     + 1228800;
constexpr size_t OFF_SPROJ  = OFF_HT     + 1228800;     // 8192*300 bf16
constexpr size_t OFF_TPROJ  = OFF_SPROJ  + 1228800;     // 8192*300 bf16
constexpr size_t OFF_HTPRE  = OFF_TPROJ  + 1228800;     // 8192*900 bf16 (+biasM)
constexpr size_t OFF_HSWA   = OFF_HTPRE  + 3686400;     // 8192*900 bf16
constexpr size_t OFF_WPB    = OFF_HSWA   + 3686400;     // 900*300 bf16
constexpr size_t OFF_WHB    = OFF_WPB    + 135000;
constexpr size_t OFF_WAB    = OFF_WHB    + 135000;
constexpr size_t OFF_WHMB   = OFF_WAB    + 135000;
constexpr size_t OFF_WSB    = OFF_WHMB   + 135000;      // 300*300 bf16
constexpr size_t OFF_WTB    = OFF_WSB    + 45000;
constexpr size_t OFF_WMTB   = OFF_WTB    + 45000;       // 300*300 bf16
constexpr size_t OFF_BP     = OFF_WMTB   + 45000;       // 900 f32
constexpr size_t OFF_BH     = OFF_BP + 900;
constexpr size_t OFF_BM     = OFF_BH + 900;
constexpr size_t BUF_TOTAL  = OFF_BM + 900;

__device__ __align__(16) float g_buf[BUF_TOTAL];

__device__ __forceinline__ float fast_sigmoid(float x) {
    return __fdividef(1.f, 1.f + __expf(-x));
}
__device__ __forceinline__ float fast_tanh(float x) {
    float e = __expf(2.f * x);
    return 1.f - __fdividef(2.f, e + 1.f);
}
__device__ __forceinline__ float tanh_apx(float x) {
    float y; asm("tanh.approx.f32 %0, %1;" : "=f"(y) : "f"(x)); return y;
}
__device__ __forceinline__ float sig_apx(float x) {
    return fmaf(0.5f, tanh_apx(0.5f * x), 0.5f);
}

__device__ __forceinline__ uint32_t smem_u32(const void* p) {
    uint32_t a;
    asm("{ .reg .u64 t; cvta.to.shared.u64 t, %1; cvt.u32.u64 %0, t; }" : "=r"(a) : "l"(p));
    return a;
}
__device__ __forceinline__ void ldsm_x4(uint32_t r[4], uint32_t addr) {
    asm volatile("ldmatrix.sync.aligned.m8n8.x4.shared.b16 {%0,%1,%2,%3}, [%4];"
                 : "=r"(r[0]), "=r"(r[1]), "=r"(r[2]), "=r"(r[3]) : "r"(addr));
}
__device__ __forceinline__ void mma_bf16(float c[4], const uint32_t a[4],
                                         uint32_t b0, uint32_t b1) {
    asm volatile(
        "mma.sync.aligned.m16n8k16.row.col.f32.bf16.bf16.f32 "
        "{%0,%1,%2,%3}, {%4,%5,%6,%7}, {%8,%9}, {%0,%1,%2,%3};"
        : "+f"(c[0]), "+f"(c[1]), "+f"(c[2]), "+f"(c[3])
        : "r"(a[0]), "r"(a[1]), "r"(a[2]), "r"(a[3]), "r"(b0), "r"(b1));
}
__device__ __forceinline__ float2 bf2f2(uint32_t u) {
    __nv_bfloat162 h = *reinterpret_cast<__nv_bfloat162*>(&u);
    return __bfloat1622float2(h);
}
__device__ __forceinline__ uint32_t tanh_bf16x2(uint32_t x) {
    uint32_t d;
    asm("tanh.approx.bf16x2 %0, %1;" : "=r"(d) : "r"(x));
    return d;
}

// ======================= fused prep (1 launch) ==============================
__global__ void prep_all(const float* __restrict__ Wih_p, const float* __restrict__ bih_p,
                         const float* __restrict__ bhh_p,
                         const float* __restrict__ Wih_h, const float* __restrict__ bih_h,
                         const float* __restrict__ bhh_h,
                         const float* __restrict__ Wih_m, const float* __restrict__ bih_m,
                         const float* __restrict__ bhh_m,
                         const float* __restrict__ Wm,
                         const float* __restrict__ Ws, const float* __restrict__ Wt,
                         __nv_bfloat16* __restrict__ Wp, __nv_bfloat16* __restrict__ Wh,
                         __nv_bfloat16* __restrict__ Wa, __nv_bfloat16* __restrict__ Whm,
                         __nv_bfloat16* __restrict__ Wsb, __nv_bfloat16* __restrict__ Wtb,
                         __nv_bfloat16* __restrict__ WmT,
                         float* __restrict__ bp, float* __restrict__ bh,
                         float* __restrict__ bm)
{
    int idx = blockIdx.x * blockDim.x + threadIdx.x;
    if (idx < 270000) {
        int j = idx / 300, k2 = idx % 300;
        int src = (j < 300) ? j : j + 300;
        Wp[idx] = __float2bfloat16(Wih_p[(size_t)src * 300 + k2]);
    } else if (idx < 540000) {
        int t = idx - 270000; int j = t / 300, k2 = t % 300;
        int src = (j < 300) ? j : j + 300;
        Wh[t] = __float2bfloat16(Wih_h[(size_t)src * 300 + k2]);
    } else if (idx < 810000) {
        int t = idx - 540000; int j = t / 300, k2 = t % 300;
        int src = (j < 300) ? j : j + 300;
        Wa[t] = __float2bfloat16(Wih_m[(size_t)src * 600 + k2]);
    } else if (idx < 1080000) {
        int t = idx - 810000; int j = t / 300, k2 = t % 300;
        int src = (j < 300) ? j : j + 300;
        Whm[t] = __float2bfloat16(Wih_m[(size_t)src * 600 + 300 + k2]);
    } else if (idx < 1170000) {
        int t = idx - 1080000;
        Wsb[t] = __float2bfloat16(Ws[t]);
    } else if (idx < 1260000) {
        int t = idx - 1170000;
        Wtb[t] = __float2bfloat16(Wt[t]);
    } else if (idx < 1350000) {
        int t = idx - 1260000; int d = t / 300, j = t % 300;
        WmT[t] = __float2bfloat16(Wm[(size_t)j * 300 + d]);
    }
    if (idx < 900) {
        int src = (idx < 300) ? idx : idx + 300;
        bp[idx] = bih_p[src] + bhh_p[src];
        bh[idx] = bih_h[src] + bhh_h[src];
        bm[idx] = bih_m[src] + bhh_m[src];
    }
}

// ======================= bf16 tensor-core GEMM core =========================
constexpr int GLDK = 40;
constexpr int GBUF = 128 * GLDK;   // 5120 bf16 per buffer

template <typename AT, typename CT>
__device__ __forceinline__ void gemm_core(
    const AT* __restrict__ A, const int* __restrict__ tok,
    const __nv_bfloat16* __restrict__ B, int Brows,
    CT* __restrict__ C, int N, const float* __restrict__ bias,
    __nv_bfloat16* __restrict__ sm, int mbase, int nbase)
{
    constexpr bool AF32 = (sizeof(AT) == 4);
    const int tid = threadIdx.x;
    const int warp = tid >> 5, lane = tid & 31;
    const int wm = warp >> 2, wn = warp & 3;

    const uint32_t aB[2] = { smem_u32(sm),            smem_u32(sm + GBUF) };
    const uint32_t bB[2] = { smem_u32(sm + 2 * GBUF), smem_u32(sm + 3 * GBUF) };

    int arow_s[4], asrc[4], ac4[4];
    bool bok[4];
#pragma unroll
    for (int p = 0; p < 4; ++p) {
        const int f4 = tid + 256 * p;
        const int row = f4 >> 3;
        arow_s[p] = row;
        ac4[p]    = f4 & 7;
        const int gm = mbase + row;
        asrc[p] = tok ? tok[gm] : gm;
        bok[p]  = (nbase + row) < Brows;
    }

    float acc[4][4][4];
#pragma unroll
    for (int i = 0; i < 4; i++)
#pragma unroll
        for (int n = 0; n < 4; n++)
#pragma unroll
            for (int e = 0; e < 4; e++) acc[i][n][e] = 0.f;

    const int lrow = lane & 15;
    const int lkof = (lane >> 4) << 3;

    float4 vaf[4];
    uint2  vab[4], vbb[4];

    auto load_chunk = [&](int k0) {
#pragma unroll
        for (int p = 0; p < 4; ++p) {
            const int kk = k0 + ac4[p] * 4;
            const bool kv = (kk < 300);
            if (AF32) {
                vaf[p] = kv ? *reinterpret_cast<const float4*>((const float*)A + (size_t)asrc[p] * 300 + kk)
                            : make_float4(0.f, 0.f, 0.f, 0.f);
            } else {
                vab[p] = kv ? *reinterpret_cast<const uint2*>((const __nv_bfloat16*)A + (size_t)asrc[p] * 300 + kk)
                            : make_uint2(0u, 0u);
            }
            vbb[p] = (kv && bok[p])
                ? *reinterpret_cast<const uint2*>(B + (size_t)(nbase + arow_s[p]) * 300 + kk)
                : make_uint2(0u, 0u);
        }
    };
    auto store_chunk = [&](int buf) {
        __nv_bfloat16* Asb = sm + buf * GBUF;
        __nv_bfloat16* Bsb = sm + (2 + buf) * GBUF;
#pragma unroll
        for (int p = 0; p < 4; ++p) {
            const int off = arow_s[p] * GLDK + ac4[p] * 4;
            if (AF32) {
                __nv_bfloat162 alo = __float22bfloat162_rn(make_float2(vaf[p].x, vaf[p].y));
                __nv_bfloat162 ahi = __float22bfloat162_rn(make_float2(vaf[p].z, vaf[p].w));
                *reinterpret_cast<uint2*>(&Asb[off]) =
                    make_uint2(*reinterpret_cast<uint32_t*>(&alo), *reinterpret_cast<uint32_t*>(&ahi));
            } else {
                *reinterpret_cast<uint2*>(&Asb[off]) = vab[p];
            }
            *reinterpret_cast<uint2*>(&Bsb[off]) = vbb[p];
        }
    };

    load_chunk(0);
    store_chunk(0);
    __syncthreads();

#pragma unroll 1
    for (int c = 0; c < 10; ++c) {
        if (c < 9) load_chunk((c + 1) * 32);
        const uint32_t a0 = aB[c & 1], b0 = bB[c & 1];
#pragma unroll
        for (int j = 0; j < 2; ++j) {
            const int kcol = j * 16 + lkof;
            uint32_t af[4][4], bfr[2][4];
#pragma unroll
            for (int i = 0; i < 4; ++i)
                ldsm_x4(af[i], a0 + (uint32_t)(((wm * 64 + i * 16 + lrow) * GLDK + kcol) * 2));
#pragma unroll
            for (int nt = 0; nt < 2; ++nt)
                ldsm_x4(bfr[nt], b0 + (uint32_t)(((wn * 32 + nt * 16 + lrow) * GLDK + kcol) * 2));
#pragma unroll
            for (int i = 0; i < 4; ++i)
#pragma unroll
                for (int n = 0; n < 4; ++n) {
                    const int nt = n >> 1, s = n & 1;
                    mma_bf16(acc[i][n], af[i], bfr[nt][s], bfr[nt][s + 2]);
                }
        }
        if (c < 9) { store_chunk((c + 1) & 1); __syncthreads(); }
    }

#pragma unroll
    for (int i = 0; i < 4; ++i) {
        const int r = mbase + wm * 64 + i * 16 + (lane >> 2);
#pragma unroll
        for (int n = 0; n < 4; ++n) {
            const int col = nbase + wn * 32 + n * 8 + (lane & 3) * 2;
            if (col < N) {
                float2 bv = make_float2(0.f, 0.f);
                if (bias) bv = *reinterpret_cast<const float2*>(bias + col);
                float v0 = acc[i][n][0] + bv.x, v1 = acc[i][n][1] + bv.y;
                float v2 = acc[i][n][2] + bv.x, v3 = acc[i][n][3] + bv.y;
                if (sizeof(CT) == 4) {
                    *reinterpret_cast<float2*>((float*)C + (size_t)r * N + col) = make_float2(v0, v1);
                    *reinterpret_cast<float2*>((float*)C + (size_t)(r + 8) * N + col) = make_float2(v2, v3);
                } else {
                    __nv_bfloat162 lo = __float22bfloat162_rn(make_float2(v0, v1));
                    __nv_bfloat162 hi = __float22bfloat162_rn(make_float2(v2, v3));
                    *reinterpret_cast<uint32_t*>((__nv_bfloat16*)C + (size_t)r * N + col) =
                        *reinterpret_cast<uint32_t*>(&lo);
                    *reinterpret_cast<uint32_t*>((__nv_bfloat16*)C + (size_t)(r + 8) * N + col) =
                        *reinterpret_cast<uint32_t*>(&hi);
                }
            }
        }
    }
}

// encoders: z=0 premise, z=1 hypothesis (f32 gather A, bf16 C, fused bias)
__global__ __launch_bounds__(256, 2)
void gemm_enc(const float* __restrict__ embed,
              const int* __restrict__ tokA, const int* __restrict__ tokB,
              const __nv_bfloat16* __restrict__ WA, const __nv_bfloat16* __restrict__ WB,
              const float* __restrict__ bA, const float* __restrict__ bB2,
              __nv_bfloat16* __restrict__ CA, __nv_bfloat16* __restrict__ CB)
{
    __shared__ __nv_bfloat16 sm[4 * GBUF];
    const int z = blockIdx.z;
    gemm_core<float, __nv_bfloat16>(embed, z ? tokB : tokA, z ? WB : WA, 900,
                                    z ? CB : CA, 900, z ? bB2 : bA, sm,
                                    blockIdx.y * 128, blockIdx.x * 128);
}

// 4 precomputes in one launch (bf16 A, bf16 C)
struct Pre4 {
    const __nv_bfloat16* A[4];
    const __nv_bfloat16* B[4];
    __nv_bfloat16*       C[4];
    const float*         bias[4];
    int                  N[4];
};
__global__ __launch_bounds__(256, 2)
void gemm_pre(Pre4 a)
{
    __shared__ __nv_bfloat16 sm[4 * GBUF];
    const int z = blockIdx.z;
    const int N = a.N[z];
    const int nbase = blockIdx.x * 128;
    if (nbase >= N) return;
    gemm_core<__nv_bfloat16, __nv_bfloat16>(a.A[z], nullptr, a.B[z], N,
                                            a.C[z], N, a.bias[z], sm,
                                            blockIdx.y * 128, nbase);
}

// ======================= lstm0 activation (bf16 gates in) ===================
__global__ void lstm_act2(const __nv_bfloat16* __restrict__ G1,
                          const __nv_bfloat16* __restrict__ G2,
                          __nv_bfloat16* __restrict__ h1, __nv_bfloat16* __restrict__ h2)
{
    int idx = blockIdx.x * blockDim.x + threadIdx.x;
    if (idx >= 8192 * 150) return;
    const __nv_bfloat16* G = blockIdx.y ? G2 : G1;
    __nv_bfloat16* h = blockIdx.y ? h2 : h1;
    int m = idx / 150, j2 = (idx % 150) * 2;
    const uint32_t* g = reinterpret_cast<const uint32_t*>(G + (size_t)m * 900);
    float2 gi = bf2f2(g[j2 / 2]);
    float2 gg = bf2f2(g[(j2 + 300) / 2]);
    float2 go = bf2f2(g[(j2 + 600) / 2]);
    float c0 = sig_apx(gi.x) * tanh_apx(gg.x);
    float c1 = sig_apx(gi.y) * tanh_apx(gg.y);
    float v0 = sig_apx(go.x) * tanh_apx(c0);
    float v1 = sig_apx(go.y) * tanh_apx(c1);
    __nv_bfloat162 o2 = __float22bfloat162_rn(make_float2(v0, v1));
    *reinterpret_cast<uint32_t*>(h + (size_t)m * 300 + j2) = *reinterpret_cast<uint32_t*>(&o2);
}

// ======================= persistent per-batch scan (512 thr) ================
constexpr int SM_WMT = 0;        // 90000 bf16 = 180000
constexpr int SM_SP  = 180000;   // 19200 bf16 = 38400
constexpr int SM_SCR = 218400;   // 1800 f32 = 7200 (A partials; C gates)
constexpr int SM_WE  = 225600;   // 300 f32
constexpr int SM_HM  = 226800;   // 300 f32
constexpr int SM_AL  = 228000;   // 64 f32 (raw e)
constexpr int SM_HF  = 228256;   // 300 f32
constexpr int SM_TM  = 229456;   // 300 bf16 = 600
constexpr int SM_RED = 230056;   // 8 f32
constexpr int SM_ALN = 230096;   // 64 f32 (normalized alpha, 16B aligned)
constexpr int SCAN_SMEM_BYTES = 230352;

__global__ __launch_bounds__(512)
void scan_kernel(const __nv_bfloat16* __restrict__ sproj, const __nv_bfloat16* __restrict__ tproj,
                 const __nv_bfloat16* __restrict__ htpre, const __nv_bfloat16* __restrict__ hsWa,
                 const __nv_bfloat16* __restrict__ WmTg,  const float* __restrict__ w_e,
                 const int* __restrict__ plen_a,  const int* __restrict__ hlen_a,
                 const float* __restrict__ fcw,   const float* __restrict__ fcb,
                 float* __restrict__ out)
{
    extern __shared__ char smraw[];
    __nv_bfloat16* wmt   = reinterpret_cast<__nv_bfloat16*>(smraw + SM_WMT);
    __nv_bfloat16* sp    = reinterpret_cast<__nv_bfloat16*>(smraw + SM_SP);
    float*         scr   = reinterpret_cast<float*>(smraw + SM_SCR);
    float*         we_s  = reinterpret_cast<float*>(smraw + SM_WE);
    float*         hm    = reinterpret_cast<float*>(smraw + SM_HM);
    float*         alpha = reinterpret_cast<float*>(smraw + SM_AL);
    float*         hfin  = reinterpret_cast<float*>(smraw + SM_HF);
    __nv_bfloat16* tm    = reinterpret_cast<__nv_bfloat16*>(smraw + SM_TM);
    float*         red   = reinterpret_cast<float*>(smraw + SM_RED);
    float*         alpn  = reinterpret_cast<float*>(smraw + SM_ALN);

    const int b    = blockIdx.x;
    const int tid  = threadIdx.x;
    const int warp = tid >> 5, lane = tid & 31;

    for (int i = tid; i < 11250; i += 512)
        reinterpret_cast<uint4*>(wmt)[i] = reinterpret_cast<const uint4*>(WmTg)[i];
    const uint4* spg = reinterpret_cast<const uint4*>(sproj + (size_t)b * 19200);
    for (int i = tid; i < 2400; i += 512)
        reinterpret_cast<uint4*>(sp)[i] = spg[i];
    for (int i = tid; i < 300; i += 512) { we_s[i] = w_e[i]; hm[i] = 0.f; }
    const int plen = plen_a[b];
    const int hlen = hlen_a[b];

    // hsWa is k-invariant: 64 rows in registers (column pair per thread)
    uint32_t pre[64];
    if (tid < 450) {
        const uint32_t* hwp = reinterpret_cast<const uint32_t*>(
                                  hsWa + (size_t)b * (64 * 900)) + tid;
#pragma unroll
        for (int p = 0; p < 64; ++p)
            pre[p] = hwp[(size_t)p * 450];
    }
    __syncthreads();

    for (int k = 0; k < hlen; ++k) {
        // prefetch step-k streams (consumed >2K cycles later)
        uint32_t prh = 0;
        uint2 tkv = make_uint2(0u, 0u);
        if (tid < 450)
            prh = __ldcs(reinterpret_cast<const uint32_t*>(
                      htpre + ((size_t)b * 64 + k) * 900) + tid);
        if (tid < 75)
            tkv = __ldcs(reinterpret_cast<const uint2*>(
                      tproj + ((size_t)b * 64 + k) * 300) + tid);

        // Phase A: m_proj partials = hm @ Wm^T (6 segs x 75 col-quads), d-pairs
        if (k > 0 && tid < 450) {
            const int seg = tid / 75;
            const int jq  = tid % 75;
            const int d0  = seg * 50;
            float4 acc = make_float4(0.f, 0.f, 0.f, 0.f);
#pragma unroll 5
            for (int d = d0; d < d0 + 50; d += 2) {
                const float2 hv = *reinterpret_cast<const float2*>(hm + d);
                const uint2 w0 = *reinterpret_cast<const uint2*>(wmt + d * 300 + jq * 4);
                const uint2 w1 = *reinterpret_cast<const uint2*>(wmt + (d + 1) * 300 + jq * 4);
                float2 a0 = bf2f2(w0.x), a1 = bf2f2(w0.y);
                float2 b0 = bf2f2(w1.x), b1 = bf2f2(w1.y);
                acc.x = fmaf(hv.x, a0.x, fmaf(hv.y, b0.x, acc.x));
                acc.y = fmaf(hv.x, a0.y, fmaf(hv.y, b0.y, acc.y));
                acc.z = fmaf(hv.x, a1.x, fmaf(hv.y, b1.x, acc.z));
                acc.w = fmaf(hv.x, a1.y, fmaf(hv.y, b1.y, acc.w));
            }
            reinterpret_cast<float4*>(scr)[seg * 75 + jq] = acc;
        }
        __syncthreads();

        // reduce partials -> mp; tm = bf16(tk + mp); tk already in regs
        if (tid < 75) {
            float4 m = make_float4(0.f, 0.f, 0.f, 0.f);
            if (k > 0) {
#pragma unroll
                for (int s = 0; s < 6; ++s) {
                    float4 a = reinterpret_cast<float4*>(scr)[s * 75 + tid];
                    m.x += a.x; m.y += a.y; m.z += a.z; m.w += a.w;
                }
            }
            float2 t0 = bf2f2(tkv.x), t1 = bf2f2(tkv.y);
            __nv_bfloat162 p0 = __float22bfloat162_rn(make_float2(m.x + t0.x, m.y + t0.y));
            __nv_bfloat162 p1 = __float22bfloat162_rn(make_float2(m.z + t1.x, m.w + t1.y));
            *reinterpret_cast<uint2*>(tm + 4 * tid) =
                make_uint2(*reinterpret_cast<uint32_t*>(&p0), *reinterpret_cast<uint32_t*>(&p1));
        }
        __syncthreads();

        // Phase B: e[p] = w_e . tanh(sp[p] + tm)  (packed bf16x2, MUFU tanh)
        const uint32_t* tmu = reinterpret_cast<const uint32_t*>(tm);
        for (int p = warp; p < plen; p += 16) {
            const uint32_t* srow = reinterpret_cast<const uint32_t*>(sp + p * 300);
            float acc = 0.f;
            for (int hp = lane; hp < 150; hp += 32) {
                uint32_t s2 = srow[hp], t2 = tmu[hp];
                __nv_bfloat162 x2 = __hadd2(*reinterpret_cast<__nv_bfloat162*>(&s2),
                                            *reinterpret_cast<__nv_bfloat162*>(&t2));
                uint32_t th = tanh_bf16x2(*reinterpret_cast<uint32_t*>(&x2));
                float2 tf = bf2f2(th);
                float2 w2 = *reinterpret_cast<const float2*>(we_s + 2 * hp);
                acc = fmaf(w2.x, tf.x, acc);
                acc = fmaf(w2.y, tf.y, acc);
            }
#pragma unroll
            for (int o = 16; o > 0; o >>= 1) acc += __shfl_xor_sync(0xffffffffu, acc, o);
            if (lane == 0) alpha[p] = acc;
        }
        __syncthreads();

        // softmax: ALL warps compute redundantly (identical ops, benign races),
        // each warp writes all 64 alpn entries -> no block barrier before C.
        {
            float e0 = (lane < plen) ? alpha[lane] : -FLT_MAX;
            float e1 = (lane + 32 < plen) ? alpha[lane + 32] : -FLT_MAX;
            float mx = fmaxf(e0, e1);
#pragma unroll
            for (int o = 16; o > 0; o >>= 1) mx = fmaxf(mx, __shfl_xor_sync(0xffffffffu, mx, o));
            float x0 = (lane < plen) ? __expf(e0 - mx) : 0.f;
            float x1 = (lane + 32 < plen) ? __expf(e1 - mx) : 0.f;
            float s = x0 + x1;
#pragma unroll
            for (int o = 16; o > 0; o >>= 1) s += __shfl_xor_sync(0xffffffffu, s, o);
            float inv = 1.f / s;
            alpn[lane]      = x0 * inv;
            alpn[lane + 32] = x1 * inv;
            __syncwarp();
        }

        // Phase C: gates = sum_p alpn[p]*pre[p] + htpre(+biasM); dual accs,
        // alpn via float4 (own warp wrote the full array).
        if (tid < 450) {
            float2 acc0 = bf2f2(prh);
            float2 acc1 = make_float2(0.f, 0.f);
            const float4* al4 = reinterpret_cast<const float4*>(alpn);
#pragma unroll
            for (int q = 0; q < 16; ++q) {
                const float4 av = al4[q];
                float2 w;
                w = bf2f2(pre[4 * q + 0]);
                acc0.x = fmaf(av.x, w.x, acc0.x); acc0.y = fmaf(av.x, w.y, acc0.y);
                w = bf2f2(pre[4 * q + 1]);
                acc1.x = fmaf(av.y, w.x, acc1.x); acc1.y = fmaf(av.y, w.y, acc1.y);
                w = bf2f2(pre[4 * q + 2]);
                acc0.x = fmaf(av.z, w.x, acc0.x); acc0.y = fmaf(av.z, w.y, acc0.y);
                w = bf2f2(pre[4 * q + 3]);
                acc1.x = fmaf(av.w, w.x, acc1.x); acc1.y = fmaf(av.w, w.y, acc1.y);
            }
            scr[2 * tid]     = acc0.x + acc1.x;
            scr[2 * tid + 1] = acc0.y + acc1.y;
        }
        __syncthreads();

        // Phase D: h_m update (accurate fast-math f32 — feeds final logits)
        if (tid < 300) {
            const int h = tid;
            float gi = scr[h];
            float gg = scr[h + 300];
            float go = scr[h + 600];
            float c  = fast_sigmoid(gi) * fast_tanh(gg);
            float hv = fast_sigmoid(go) * fast_tanh(c);
            hm[h] = hv;
            if (k == hlen - 1) hfin[h] = hv;
        }
        __syncthreads();
    }

    if (warp < 3) {
        float acc = 0.f;
        for (int h = lane; h < 300; h += 32) acc += hfin[h] * fcw[warp * 300 + h];
#pragma unroll
        for (int o = 16; o > 0; o >>= 1) acc += __shfl_xor_sync(0xffffffffu, acc, o);
        if (lane == 0) red[warp] = acc + fcb[warp];
    }
    __syncthreads();
    if (tid == 0) {
        float l0 = red[0], l1 = red[1], l2 = red[2];
        float mx = fmaxf(l0, fmaxf(l1, l2));
        float e0 = expf(l0 - mx), e1 = expf(l1 - mx), e2 = expf(l2 - mx);
        float inv = 1.f / (e0 + e1 + e2);
        out[b * 3 + 0] = e0 * inv;
        out[b * 3 + 1] = e1 * inv;
        out[b * 3 + 2] = e2 * inv;
    }
}

// ---------------------------------------------------------------------------
extern "C" void kernel_launch(void* const* d_in, const int* in_sizes, int n_in,
                              void* d_out, int out_size)
{
    const int*   premise = (const int*)  d_in[0];
    const int*   plen    = (const int*)  d_in[1];
    const int*   hyp     = (const int*)  d_in[2];
    const int*   hlen    = (const int*)  d_in[3];
    const float* embed   = (const float*)d_in[4];
    const float* w_e     = (const float*)d_in[5];
    const float* W_s     = (const float*)d_in[6];
    const float* W_t     = (const float*)d_in[7];
    const float* W_m     = (const float*)d_in[8];
    const float* fc_w    = (const float*)d_in[9];
    const float* fc_b    = (const float*)d_in[10];
    const float* Wih_p   = (const float*)d_in[11];
    const float* bih_p   = (const float*)d_in[13];
    const float* bhh_p   = (const float*)d_in[14];
    const float* Wih_h   = (const float*)d_in[15];
    const float* bih_h   = (const float*)d_in[17];
    const float* bhh_h   = (const float*)d_in[18];
    const float* Wih_m   = (const float*)d_in[19];
    const float* bih_m   = (const float*)d_in[21];
    const float* bhh_m   = (const float*)d_in[22];

    float* buf = nullptr;
    cudaGetSymbolAddress((void**)&buf, g_buf);
    __nv_bfloat16*  gates1 = (__nv_bfloat16*)(buf + OFF_GATES1);
    __nv_bfloat16*  gates2 = (__nv_bfloat16*)(buf + OFF_GATES2);
    __nv_bfloat16*  hs     = (__nv_bfloat16*)(buf + OFF_HS);
    __nv_bfloat16*  ht     = (__nv_bfloat16*)(buf + OFF_HT);
    __nv_bfloat16*  sprojp = (__nv_bfloat16*)(buf + OFF_SPROJ);
    __nv_bfloat16*  tprojp = (__nv_bfloat16*)(buf + OFF_TPROJ);
    __nv_bfloat16*  htprep = (__nv_bfloat16*)(buf + OFF_HTPRE);
    __nv_bfloat16*  hsWap  = (__nv_bfloat16*)(buf + OFF_HSWA);
    __nv_bfloat16*  Wp     = (__nv_bfloat16*)(buf + OFF_WPB);
    __nv_bfloat16*  Wh     = (__nv_bfloat16*)(buf + OFF_WHB);
    __nv_bfloat16*  Wa     = (__nv_bfloat16*)(buf + OFF_WAB);
    __nv_bfloat16*  Whm    = (__nv_bfloat16*)(buf + OFF_WHMB);
    __nv_bfloat16*  Wsb    = (__nv_bfloat16*)(buf + OFF_WSB);
    __nv_bfloat16*  Wtb    = (__nv_bfloat16*)(buf + OFF_WTB);
    __nv_bfloat16*  WmT    = (__nv_bfloat16*)(buf + OFF_WMTB);
    float* bp = buf + OFF_BP;
    float* bh = buf + OFF_BH;
    float* bm = buf + OFF_BM;

    prep_all<<<(1350000 + 255) / 256, 256>>>(Wih_p, bih_p, bhh_p,
                                             Wih_h, bih_h, bhh_h,
                                             Wih_m, bih_m, bhh_m,
                                             W_m, W_s, W_t,
                                             Wp, Wh, Wa, Whm, Wsb, Wtb, WmT,
                                             bp, bh, bm);

    gemm_enc<<<dim3(8, 64, 2), 256>>>(embed, premise, hyp, Wp, Wh, bp, bh,
                                      gates1, gates2);
    lstm_act2<<<dim3((8192 * 150 + 255) / 256, 2), 256>>>(gates1, gates2, hs, ht);

    Pre4 pa;
    pa.A[0] = hs;  pa.B[0] = Wa;  pa.C[0] = hsWap;  pa.bias[0] = nullptr; pa.N[0] = 900;
    pa.A[1] = ht;  pa.B[1] = Whm; pa.C[1] = htprep; pa.bias[1] = bm;      pa.N[1] = 900;
    pa.A[2] = hs;  pa.B[2] = Wsb; pa.C[2] = sprojp; pa.bias[2] = nullptr; pa.N[2] = 300;
    pa.A[3] = ht;  pa.B[3] = Wtb; pa.C[3] = tprojp; pa.bias[3] = nullptr; pa.N[3] = 300;
    gemm_pre<<<dim3(8, 64, 4), 256>>>(pa);

    cudaFuncSetAttribute(scan_kernel, cudaFuncAttributeMaxDynamicSharedMemorySize,
                         SCAN_SMEM_BYTES);
    scan_kernel<<<128, 512, SCAN_SMEM_BYTES>>>(sprojp, tprojp, htprep, hsWap, WmT,
                                               w_e, plen, hlen, fc_w, fc_b,
                                               (float*)d_out);
}